// round 2
// baseline (speedup 1.0000x reference)
#include <cuda_runtime.h>
#include <math.h>

// ---------------- problem constants ----------------
#define NPAIRS_MAP 4096
#define NNODES     50000
#define NEDGES     500000
#define NSCORE     1000000
#define FEAT       300
#define HID        128
#define HEADS      3
#define OUTC       10
#define H1DIM      (HEADS*HID)   // 384

// ---------------- scratch (static device memory; no allocations) ----------------
__device__ float g_q[NPAIRS_MAP*FEAT];
__device__ float g_k[NPAIRS_MAP*FEAT];
__device__ float g_v[NPAIRS_MAP*FEAT];
__device__ float g_S[(size_t)NPAIRS_MAP*NPAIRS_MAP];
__device__ float g_attv[NPAIRS_MAP*FEAT];
__device__ float g_fused[NPAIRS_MAP*FEAT];
__device__ float g_x[NNODES*FEAT];
__device__ int   g_winner[NNODES];
__device__ float g_h1[(size_t)NNODES*H1DIM];
__device__ float g_es1[NNODES*HEADS];
__device__ float g_ed1[NNODES*HEADS];
__device__ float g_m1[NNODES*HEADS];
__device__ float g_den1[NNODES*HEADS];
__device__ float g_o1[(size_t)NNODES*H1DIM];
__device__ float g_h2[NNODES*OUTC];
__device__ float g_es2[NNODES];
__device__ float g_ed2[NNODES];
__device__ float g_m2[NNODES];
__device__ float g_den2[NNODES];
__device__ float g_o2[NNODES*OUTC];

// ---------------- helpers ----------------
__device__ __forceinline__ void atomicMaxFloat(float* addr, float value) {
    if (value >= 0.f) atomicMax((int*)addr, __float_as_int(value));
    else              atomicMin((unsigned int*)addr, __float_as_uint(value));
}

__device__ __forceinline__ void red_add4(float* addr, float a, float b, float c, float d) {
    asm volatile("red.global.add.v4.f32 [%0], {%1, %2, %3, %4};"
                 :: "l"(addr), "f"(a), "f"(b), "f"(c), "f"(d) : "memory");
}

// ---------------- generic tiled SGEMM: C = scale*(A@B or A@B^T) + bias ----------------
#define BM 64
#define BN 64
#define BK 16

template<bool TRANSB>
__global__ void sgemm_kernel(const float* __restrict__ A, const float* __restrict__ B,
                             const float* __restrict__ bias, float* __restrict__ C,
                             int M, int N, int K, float scale)
{
    __shared__ float As[BK][BM+1];
    __shared__ float Bs[BK][BN+1];
    int tid = threadIdx.x;             // 256 threads
    int tx = tid & 15, ty = tid >> 4;  // 16x16
    int row0 = blockIdx.y * BM, col0 = blockIdx.x * BN;
    float acc[4][4] = {};

    for (int k0 = 0; k0 < K; k0 += BK) {
        // A tile: 64x16
        #pragma unroll
        for (int i = 0; i < 4; i++) {
            int r = ty + 16*i, c = tx;
            float v = 0.f;
            if (row0 + r < M && k0 + c < K) v = A[(size_t)(row0+r)*K + k0 + c];
            As[c][r] = v;
        }
        // B tile: 16x64
        if (TRANSB) {
            #pragma unroll
            for (int i = 0; i < 4; i++) {
                int kk = tx, nn = ty + 16*i;
                float v = 0.f;
                if (col0 + nn < N && k0 + kk < K) v = B[(size_t)(col0+nn)*K + k0 + kk];
                Bs[kk][nn] = v;
            }
        } else {
            #pragma unroll
            for (int i = 0; i < 4; i++) {
                int kk = ty, nn = tx + 16*i;
                float v = 0.f;
                if (k0 + kk < K && col0 + nn < N) v = B[(size_t)(k0+kk)*N + col0 + nn];
                Bs[kk][nn] = v;
            }
        }
        __syncthreads();
        #pragma unroll
        for (int kk = 0; kk < BK; kk++) {
            float a[4], b[4];
            #pragma unroll
            for (int i = 0; i < 4; i++) a[i] = As[kk][ty*4+i];
            #pragma unroll
            for (int j = 0; j < 4; j++) b[j] = Bs[kk][tx*4+j];
            #pragma unroll
            for (int i = 0; i < 4; i++)
                #pragma unroll
                for (int j = 0; j < 4; j++) acc[i][j] += a[i]*b[j];
        }
        __syncthreads();
    }
    #pragma unroll
    for (int i = 0; i < 4; i++) {
        int r = row0 + ty*4 + i;
        if (r >= M) continue;
        #pragma unroll
        for (int j = 0; j < 4; j++) {
            int c = col0 + tx*4 + j;
            if (c >= N) continue;
            float v = acc[i][j] * scale;
            if (bias) v += bias[c];
            C[(size_t)r*N + c] = v;
        }
    }
}

// ---------------- softmax over 4096-wide rows ----------------
__global__ void softmax_rows(float* __restrict__ S)
{
    __shared__ float buf[NPAIRS_MAP];
    __shared__ float red[256];
    int row = blockIdx.x, tid = threadIdx.x;
    float* r = S + (size_t)row * NPAIRS_MAP;
    float mx = -INFINITY;
    for (int i = tid; i < NPAIRS_MAP; i += 256) { float v = r[i]; buf[i] = v; mx = fmaxf(mx, v); }
    red[tid] = mx; __syncthreads();
    for (int o = 128; o; o >>= 1) { if (tid < o) red[tid] = fmaxf(red[tid], red[tid+o]); __syncthreads(); }
    mx = red[0]; __syncthreads();
    float sum = 0.f;
    for (int i = tid; i < NPAIRS_MAP; i += 256) { float e = expf(buf[i] - mx); buf[i] = e; sum += e; }
    red[tid] = sum; __syncthreads();
    for (int o = 128; o; o >>= 1) { if (tid < o) red[tid] += red[tid+o]; __syncthreads(); }
    float inv = 1.f / red[0];
    for (int i = tid; i < NPAIRS_MAP; i += 256) r[i] = buf[i] * inv;
}

// ---------------- misc elementwise ----------------
__global__ void fill_f32(float* p, float v, int n)
{ int i = blockIdx.x*blockDim.x + threadIdx.x; if (i < n) p[i] = v; }

__global__ void add_inplace(float* __restrict__ a, const float* __restrict__ b, int n)
{ int i = blockIdx.x*blockDim.x + threadIdx.x; if (i < n) a[i] += b[i]; }

__global__ void bias_elu(float* __restrict__ p, const float* __restrict__ b, int n, int cols)
{
    int i = blockIdx.x*blockDim.x + threadIdx.x; if (i >= n) return;
    float v = p[i] + b[i % cols];
    p[i] = v > 0.f ? v : expm1f(v);
}

__global__ void bias_add(float* __restrict__ p, const float* __restrict__ b, int n, int cols)
{ int i = blockIdx.x*blockDim.x + threadIdx.x; if (i < n) p[i] += b[i % cols]; }

// ---------------- scatter (last occurrence wins, matching sequential .at[].set) ----------------
__global__ void scatter_winner(const int* __restrict__ com_idx, int* __restrict__ winner, int n)
{ int i = blockIdx.x*blockDim.x + threadIdx.x; if (i < n) atomicMax(&winner[com_idx[i]], i); }

__global__ void scatter_apply(const int* __restrict__ com_idx, const int* __restrict__ winner,
                              const float* __restrict__ fused, float* __restrict__ x, int n)
{
    int i = blockIdx.x*blockDim.x + threadIdx.x;
    int p = i / FEAT, c = i % FEAT;
    if (p >= n) return;
    int node = com_idx[p];
    if (winner[node] == p) x[(size_t)node*FEAT + c] = fused[(size_t)p*FEAT + c];
}

// ---------------- GAT layer 1 (H=3, C=128) ----------------
__global__ void node_e1(const float* __restrict__ h1, const float* __restrict__ a_src,
                        const float* __restrict__ a_dst, float* __restrict__ es, float* __restrict__ ed)
{
    int warp = (blockIdx.x*blockDim.x + threadIdx.x) >> 5;
    int lane = threadIdx.x & 31;
    int node = warp / HEADS, h = warp % HEADS;
    if (node >= NNODES) return;
    const float* hp = h1 + (size_t)node*H1DIM + h*HID;
    float s = 0.f, d = 0.f;
    #pragma unroll
    for (int c = lane; c < HID; c += 32) {
        float v = hp[c];
        s += v * a_src[h*HID + c];
        d += v * a_dst[h*HID + c];
    }
    #pragma unroll
    for (int o = 16; o; o >>= 1) { s += __shfl_xor_sync(~0u, s, o); d += __shfl_xor_sync(~0u, d, o); }
    if (!lane) { es[node*HEADS + h] = s; ed[node*HEADS + h] = d; }
}

__global__ void edge_max1(const int* __restrict__ src, const int* __restrict__ dst, int E,
                          const float* __restrict__ es, const float* __restrict__ ed,
                          float* __restrict__ m)
{
    int e = blockIdx.x*blockDim.x + threadIdx.x;
    if (e >= E + NNODES) return;
    int s = e < E ? src[e] : e - E;
    int d = e < E ? dst[e] : e - E;
    #pragma unroll
    for (int h = 0; h < HEADS; h++) {
        float v = es[s*HEADS+h] + ed[d*HEADS+h];
        v = v > 0.f ? v : 0.2f*v;
        atomicMaxFloat(&m[d*HEADS+h], v);
    }
}

__global__ void edge_exp1(const int* __restrict__ src, const int* __restrict__ dst, int E,
                          const float* __restrict__ es, const float* __restrict__ ed,
                          const float* __restrict__ m, float* __restrict__ den)
{
    int e = blockIdx.x*blockDim.x + threadIdx.x;
    if (e >= E + NNODES) return;
    int s = e < E ? src[e] : e - E;
    int d = e < E ? dst[e] : e - E;
    #pragma unroll
    for (int h = 0; h < HEADS; h++) {
        float v = es[s*HEADS+h] + ed[d*HEADS+h];
        v = v > 0.f ? v : 0.2f*v;
        atomicAdd(&den[d*HEADS+h], expf(v - m[d*HEADS+h]));
    }
}

__global__ void edge_agg1(const int* __restrict__ src, const int* __restrict__ dst, int E,
                          const float* __restrict__ es, const float* __restrict__ ed,
                          const float* __restrict__ m, const float* __restrict__ den,
                          const float* __restrict__ h1, float* __restrict__ out)
{
    int warp = (blockIdx.x*blockDim.x + threadIdx.x) >> 5;
    int lane = threadIdx.x & 31;
    if (warp >= E + NNODES) return;
    int s = warp < E ? src[warp] : warp - E;
    int d = warp < E ? dst[warp] : warp - E;
    float alpha[HEADS];
    #pragma unroll
    for (int h = 0; h < HEADS; h++) {
        float v = es[s*HEADS+h] + ed[d*HEADS+h];
        v = v > 0.f ? v : 0.2f*v;
        float ex = expf(v - m[d*HEADS+h]);
        alpha[h] = ex / (den[d*HEADS+h] + 1e-16f);
    }
    const float4* hp = (const float4*)(h1 + (size_t)s*H1DIM);
    float* op = out + (size_t)d*H1DIM;
    #pragma unroll
    for (int it = 0; it < 3; it++) {
        int i = lane + 32*it;             // float4 index 0..95; head = it
        float4 hv = hp[i];
        float a = alpha[it];
        red_add4(op + i*4, hv.x*a, hv.y*a, hv.z*a, hv.w*a);
    }
}

// ---------------- GAT layer 2 (H=1, C=10) ----------------
__global__ void node_e2(const float* __restrict__ h2, const float* __restrict__ a_src,
                        const float* __restrict__ a_dst, float* __restrict__ es, float* __restrict__ ed)
{
    int n = blockIdx.x*blockDim.x + threadIdx.x;
    if (n >= NNODES) return;
    float s = 0.f, d = 0.f;
    #pragma unroll
    for (int c = 0; c < OUTC; c++) {
        float v = h2[n*OUTC + c];
        s += v * a_src[c];
        d += v * a_dst[c];
    }
    es[n] = s; ed[n] = d;
}

__global__ void edge_max2(const int* __restrict__ src, const int* __restrict__ dst, int E,
                          const float* __restrict__ es, const float* __restrict__ ed, float* __restrict__ m)
{
    int e = blockIdx.x*blockDim.x + threadIdx.x;
    if (e >= E + NNODES) return;
    int s = e < E ? src[e] : e - E;
    int d = e < E ? dst[e] : e - E;
    float v = es[s] + ed[d];
    v = v > 0.f ? v : 0.2f*v;
    atomicMaxFloat(&m[d], v);
}

__global__ void edge_exp2(const int* __restrict__ src, const int* __restrict__ dst, int E,
                          const float* __restrict__ es, const float* __restrict__ ed,
                          const float* __restrict__ m, float* __restrict__ den)
{
    int e = blockIdx.x*blockDim.x + threadIdx.x;
    if (e >= E + NNODES) return;
    int s = e < E ? src[e] : e - E;
    int d = e < E ? dst[e] : e - E;
    float v = es[s] + ed[d];
    v = v > 0.f ? v : 0.2f*v;
    atomicAdd(&den[d], expf(v - m[d]));
}

__global__ void edge_agg2(const int* __restrict__ src, const int* __restrict__ dst, int E,
                          const float* __restrict__ es, const float* __restrict__ ed,
                          const float* __restrict__ m, const float* __restrict__ den,
                          const float* __restrict__ h2, float* __restrict__ out)
{
    int e = blockIdx.x*blockDim.x + threadIdx.x;
    if (e >= E + NNODES) return;
    int s = e < E ? src[e] : e - E;
    int d = e < E ? dst[e] : e - E;
    float v = es[s] + ed[d];
    v = v > 0.f ? v : 0.2f*v;
    float alpha = expf(v - m[d]) / (den[d] + 1e-16f);
    #pragma unroll
    for (int c = 0; c < OUTC; c++)
        atomicAdd(&out[d*OUTC + c], h2[s*OUTC + c] * alpha);
}

// ---------------- final pair scores ----------------
__global__ void pair_scores(const int* __restrict__ pair, const float* __restrict__ emb,
                            float* __restrict__ out, int n)
{
    int i = blockIdx.x*blockDim.x + threadIdx.x;
    if (i >= n) return;
    int a = pair[2*i], b = pair[2*i+1];
    const float* ea = emb + (size_t)a*OUTC;
    const float* eb = emb + (size_t)b*OUTC;
    float s = 0.f;
    #pragma unroll
    for (int c = 0; c < OUTC; c++) s += ea[c] * eb[c];
    out[i] = s;
}

// ---------------- host ----------------
static void launch_sgemm(const float* A, const float* B, const float* bias, float* C,
                         int M, int N, int K, float scale, bool transB)
{
    dim3 grid((N + BN - 1)/BN, (M + BM - 1)/BM);
    if (transB) sgemm_kernel<true ><<<grid, 256>>>(A, B, bias, C, M, N, K, scale);
    else        sgemm_kernel<false><<<grid, 256>>>(A, B, bias, C, M, N, K, scale);
}

extern "C" void kernel_launch(void* const* d_in, const int* in_sizes, int n_in,
                              void* d_out, int out_size)
{
    const float* fsub   = (const float*)d_in[0];
    const float* fcom   = (const float*)d_in[1];
    const float* x      = (const float*)d_in[2];
    const int*   comidx = (const int*)  d_in[3];
    const int*   edge   = (const int*)  d_in[4];
    const int*   pair   = (const int*)  d_in[5];
    const float* Wq = (const float*)d_in[6];  const float* bq = (const float*)d_in[7];
    const float* Wk = (const float*)d_in[8];  const float* bk = (const float*)d_in[9];
    const float* Wv = (const float*)d_in[10]; const float* bv = (const float*)d_in[11];
    const float* Wf = (const float*)d_in[12]; const float* bf = (const float*)d_in[13];
    const float* W1 = (const float*)d_in[14];
    const float* as1 = (const float*)d_in[15]; const float* ad1 = (const float*)d_in[16];
    const float* b1 = (const float*)d_in[17];
    const float* W2 = (const float*)d_in[18];
    const float* as2 = (const float*)d_in[19]; const float* ad2 = (const float*)d_in[20];
    const float* b2 = (const float*)d_in[21];
    float* out = (float*)d_out;

    const int E = in_sizes[4] / 2;           // 500000
    const int* src = edge;
    const int* dst = edge + E;
    const int npairs = in_sizes[5] / 2;      // 1e6

    float *q, *k, *v, *S, *attv, *fused, *xw, *h1, *es1, *ed1, *m1, *den1, *o1;
    float *h2, *es2, *ed2, *m2, *den2, *o2;
    int* winner;
    cudaGetSymbolAddress((void**)&q, g_q);       cudaGetSymbolAddress((void**)&k, g_k);
    cudaGetSymbolAddress((void**)&v, g_v);       cudaGetSymbolAddress((void**)&S, g_S);
    cudaGetSymbolAddress((void**)&attv, g_attv); cudaGetSymbolAddress((void**)&fused, g_fused);
    cudaGetSymbolAddress((void**)&xw, g_x);      cudaGetSymbolAddress((void**)&winner, g_winner);
    cudaGetSymbolAddress((void**)&h1, g_h1);
    cudaGetSymbolAddress((void**)&es1, g_es1);   cudaGetSymbolAddress((void**)&ed1, g_ed1);
    cudaGetSymbolAddress((void**)&m1, g_m1);     cudaGetSymbolAddress((void**)&den1, g_den1);
    cudaGetSymbolAddress((void**)&o1, g_o1);     cudaGetSymbolAddress((void**)&h2, g_h2);
    cudaGetSymbolAddress((void**)&es2, g_es2);   cudaGetSymbolAddress((void**)&ed2, g_ed2);
    cudaGetSymbolAddress((void**)&m2, g_m2);     cudaGetSymbolAddress((void**)&den2, g_den2);
    cudaGetSymbolAddress((void**)&o2, g_o2);

    const float inv_sqrt_feat = 0.057735026918962584f;   // 1/sqrt(300)

    // ---- cross-attention ----
    launch_sgemm(fsub, Wq, bq, q, NPAIRS_MAP, FEAT, FEAT, 1.f, false);
    launch_sgemm(fcom, Wk, bk, k, NPAIRS_MAP, FEAT, FEAT, 1.f, false);
    launch_sgemm(fcom, Wv, bv, v, NPAIRS_MAP, FEAT, FEAT, 1.f, false);
    launch_sgemm(q, k, nullptr, S, NPAIRS_MAP, NPAIRS_MAP, FEAT, inv_sqrt_feat, true);
    softmax_rows<<<NPAIRS_MAP, 256>>>(S);
    launch_sgemm(S, v, nullptr, attv, NPAIRS_MAP, FEAT, NPAIRS_MAP, 1.f, false);
    add_inplace<<<(NPAIRS_MAP*FEAT + 255)/256, 256>>>(attv, fsub, NPAIRS_MAP*FEAT);
    launch_sgemm(attv, Wf, bf, fused, NPAIRS_MAP, FEAT, FEAT, 1.f, false);

    // ---- write fused rows into x (last-occurrence-wins) ----
    cudaMemcpyAsync(xw, x, (size_t)NNODES*FEAT*sizeof(float), cudaMemcpyDeviceToDevice, 0);
    cudaMemsetAsync(winner, 0xFF, NNODES*sizeof(int), 0);   // -1
    scatter_winner<<<(NPAIRS_MAP + 255)/256, 256>>>(comidx, winner, NPAIRS_MAP);
    scatter_apply<<<(NPAIRS_MAP*FEAT + 255)/256, 256>>>(comidx, winner, fused, xw, NPAIRS_MAP);

    // ---- GAT layer 1 ----
    launch_sgemm(xw, W1, nullptr, h1, NNODES, H1DIM, FEAT, 1.f, false);
    {
        int warps = NNODES*HEADS;
        node_e1<<<(warps*32 + 255)/256, 256>>>(h1, as1, ad1, es1, ed1);
    }
    fill_f32<<<(NNODES*HEADS + 255)/256, 256>>>(m1, -INFINITY, NNODES*HEADS);
    cudaMemsetAsync(den1, 0, NNODES*HEADS*sizeof(float), 0);
    cudaMemsetAsync(o1, 0, (size_t)NNODES*H1DIM*sizeof(float), 0);
    {
        int tot = E + NNODES;
        edge_max1<<<(tot + 255)/256, 256>>>(src, dst, E, es1, ed1, m1);
        edge_exp1<<<(tot + 255)/256, 256>>>(src, dst, E, es1, ed1, m1, den1);
        edge_agg1<<<((size_t)tot*32 + 255)/256, 256>>>(src, dst, E, es1, ed1, m1, den1, h1, o1);
    }
    bias_elu<<<((size_t)NNODES*H1DIM + 255)/256, 256>>>(o1, b1, NNODES*H1DIM, H1DIM);

    // ---- GAT layer 2 ----
    launch_sgemm(o1, W2, nullptr, h2, NNODES, OUTC, H1DIM, 1.f, false);
    node_e2<<<(NNODES + 255)/256, 256>>>(h2, as2, ad2, es2, ed2);
    fill_f32<<<(NNODES + 255)/256, 256>>>(m2, -INFINITY, NNODES);
    cudaMemsetAsync(den2, 0, NNODES*sizeof(float), 0);
    cudaMemsetAsync(o2, 0, NNODES*OUTC*sizeof(float), 0);
    {
        int tot = E + NNODES;
        edge_max2<<<(tot + 255)/256, 256>>>(src, dst, E, es2, ed2, m2);
        edge_exp2<<<(tot + 255)/256, 256>>>(src, dst, E, es2, ed2, m2, den2);
        edge_agg2<<<(tot + 255)/256, 256>>>(src, dst, E, es2, ed2, m2, den2, h2, o2);
    }
    bias_add<<<(NNODES*OUTC + 255)/256, 256>>>(o2, b2, NNODES*OUTC, OUTC);

    // ---- pair scores ----
    pair_scores<<<(npairs + 255)/256, 256>>>(pair, o2, out, npairs);
}

// round 3
// speedup vs baseline: 1.8400x; 1.8400x over previous
#include <cuda_runtime.h>
#include <math.h>
#include <stdint.h>

// ---------------- problem constants ----------------
#define NPAIRS_MAP 4096
#define NNODES     50000
#define FEAT       300
#define HID        128
#define HEADS      3
#define OUTC       10
#define H1DIM      (HEADS*HID)   // 384

// ---------------- scratch (static device memory; no allocations) ----------------
__device__ float g_q[NPAIRS_MAP*FEAT];
__device__ float g_k[NPAIRS_MAP*FEAT];
__device__ float g_v[NPAIRS_MAP*FEAT];
__device__ float g_S[(size_t)NPAIRS_MAP*NPAIRS_MAP];
__device__ float g_attv[NPAIRS_MAP*FEAT];
__device__ float g_fused[NPAIRS_MAP*FEAT];
__device__ float g_x[NNODES*FEAT];
__device__ int   g_winner[NNODES];
__device__ float g_h1[(size_t)NNODES*H1DIM];
__device__ float g_es1[NNODES*HEADS];
__device__ float g_ed1[NNODES*HEADS];
__device__ float g_m1[NNODES*HEADS];
__device__ float g_den1[NNODES*HEADS];
__device__ float g_o1[(size_t)NNODES*H1DIM];
__device__ float g_h2[NNODES*OUTC];
__device__ float g_es2[NNODES];
__device__ float g_ed2[NNODES];
__device__ float g_m2[NNODES];
__device__ float g_den2[NNODES];
__device__ float g_o2[NNODES*OUTC];

// ---------------- helpers ----------------
__device__ __forceinline__ void atomicMaxFloat(float* addr, float value) {
    if (value >= 0.f) atomicMax((int*)addr, __float_as_int(value));
    else              atomicMin((unsigned int*)addr, __float_as_uint(value));
}

__device__ __forceinline__ void red_add4(float* addr, float a, float b, float c, float d) {
    asm volatile("red.global.add.v4.f32 [%0], {%1, %2, %3, %4};"
                 :: "l"(addr), "f"(a), "f"(b), "f"(c), "f"(d) : "memory");
}

__device__ __forceinline__ uint32_t f2tf32(float f) {
    uint32_t u; asm("cvt.rna.tf32.f32 %0, %1;" : "=r"(u) : "f"(f)); return u;
}

__device__ __forceinline__ void mma_tf32(float* c, const uint32_t* a, const uint32_t* b) {
    asm volatile("mma.sync.aligned.m16n8k8.row.col.f32.tf32.tf32.f32 "
        "{%0,%1,%2,%3}, {%4,%5,%6,%7}, {%8,%9}, {%0,%1,%2,%3};"
        : "+f"(c[0]), "+f"(c[1]), "+f"(c[2]), "+f"(c[3])
        : "r"(a[0]), "r"(a[1]), "r"(a[2]), "r"(a[3]), "r"(b[0]), "r"(b[1]));
}

// ---------------- TF32 tensor-core GEMM ----------------
// C[M,N] = scale * (A[M,K] @ B) + bias + resid ;  B is [K,N] or (TRANSB) [N,K]
template<int BM, int A_IT>
__device__ __forceinline__ void gemm_loadA(const float* __restrict__ A, int M, int K,
                                           int row0, int k0, int tid, float (&areg)[A_IT][8])
{
    #pragma unroll
    for (int i = 0; i < A_IT; i++) {
        int idx = tid + i*256;
        #pragma unroll
        for (int j = 0; j < 8; j++) areg[i][j] = 0.f;
        if (idx < BM*2) {
            int r = idx >> 1, seg = idx & 1;
            int grow = row0 + r, gk = k0 + seg*8;
            if (grow < M) {
                const float* ap = A + (size_t)grow*K + gk;
                if (gk + 8 <= K) {
                    float4 v0 = *(const float4*)ap;
                    float4 v1 = *(const float4*)(ap+4);
                    areg[i][0]=v0.x; areg[i][1]=v0.y; areg[i][2]=v0.z; areg[i][3]=v0.w;
                    areg[i][4]=v1.x; areg[i][5]=v1.y; areg[i][6]=v1.z; areg[i][7]=v1.w;
                } else {
                    #pragma unroll
                    for (int j = 0; j < 8; j++) if (gk + j < K) areg[i][j] = ap[j];
                }
            }
        }
    }
}

template<bool TRANSB>
__device__ __forceinline__ void gemm_loadB(const float* __restrict__ B, int N, int K,
                                           int col0, int k0, int tid, float (&breg)[4])
{
    breg[0]=breg[1]=breg[2]=breg[3]=0.f;
    if (TRANSB) {
        int n = tid & 63, seg = tid >> 6;
        int gn = col0 + n, gk = k0 + seg*4;
        if (gn < N) {
            const float* bp = B + (size_t)gn*K + gk;
            if (gk + 4 <= K) {
                float4 v = *(const float4*)bp;
                breg[0]=v.x; breg[1]=v.y; breg[2]=v.z; breg[3]=v.w;
            } else {
                #pragma unroll
                for (int j = 0; j < 4; j++) if (gk + j < K) breg[j] = bp[j];
            }
        }
    } else {
        int kk = tid >> 4, f = tid & 15;
        int gk = k0 + kk, gc = col0 + f*4;
        if (gk < K) {
            const float* bp = B + (size_t)gk*N + gc;
            if (gc + 4 <= N) {
                float4 v = *(const float4*)bp;
                breg[0]=v.x; breg[1]=v.y; breg[2]=v.z; breg[3]=v.w;
            } else {
                #pragma unroll
                for (int j = 0; j < 4; j++) if (gc + j < N) breg[j] = bp[j];
            }
        }
    }
}

template<int BM, int ASTR, int A_IT>
__device__ __forceinline__ void gemm_stsA(uint32_t* __restrict__ sA, int tid,
                                          const float (&areg)[A_IT][8])
{
    #pragma unroll
    for (int i = 0; i < A_IT; i++) {
        int idx = tid + i*256;
        if (idx < BM*2) {
            int r = idx >> 1, seg = idx & 1;
            #pragma unroll
            for (int j = 0; j < 8; j++)
                sA[(seg*8 + j)*ASTR + r] = f2tf32(areg[i][j]);
        }
    }
}

template<bool TRANSB>
__device__ __forceinline__ void gemm_stsB(uint32_t* __restrict__ sB, int tid,
                                          const float (&breg)[4])
{
    if (TRANSB) {
        int n = tid & 63, seg = tid >> 6;
        #pragma unroll
        for (int j = 0; j < 4; j++)
            sB[(seg*4 + j)*72 + n] = f2tf32(breg[j]);
    } else {
        int kk = tid >> 4, f = tid & 15;
        uint4 v;
        v.x = f2tf32(breg[0]); v.y = f2tf32(breg[1]);
        v.z = f2tf32(breg[2]); v.w = f2tf32(breg[3]);
        *(uint4*)&sB[kk*72 + f*4] = v;
    }
}

template<int BM, int WARPS_M, int WARPS_N, bool TRANSB>
__global__ void __launch_bounds__(256)
tf32_gemm(const float* __restrict__ A, const float* __restrict__ B,
          const float* __restrict__ bias, const float* __restrict__ resid,
          float* __restrict__ C, int M, int N, int K, float scale)
{
    constexpr int BK = 16;
    constexpr int ASTR = BM + 8;      // stride % 32 == 8 -> conflict-free fragment LDS
    constexpr int BSTR = 72;          // 64 + 8
    constexpr int WM = BM / WARPS_M, WN = 64 / WARPS_N;
    constexpr int MT = WM / 16, NT = WN / 8;
    constexpr int A_IT = (BM*2 + 255) / 256;

    __shared__ uint32_t sA[2*BK*ASTR];
    __shared__ uint32_t sB[2*BK*BSTR];

    int tid = threadIdx.x, lane = tid & 31, warp = tid >> 5;
    int wm = warp % WARPS_M, wn = warp / WARPS_M;
    int row0 = blockIdx.y * BM, col0 = blockIdx.x * 64;
    int lr = lane >> 2, lc = lane & 3;

    float acc[MT][NT][4];
    #pragma unroll
    for (int i = 0; i < MT; i++)
        #pragma unroll
        for (int j = 0; j < NT; j++)
            #pragma unroll
            for (int e = 0; e < 4; e++) acc[i][j][e] = 0.f;

    int ntiles = (K + BK - 1) / BK;
    float areg[A_IT][8];
    float breg[4];

    // prologue: tile 0
    gemm_loadA<BM, A_IT>(A, M, K, row0, 0, tid, areg);
    gemm_loadB<TRANSB>(B, N, K, col0, 0, tid, breg);
    gemm_stsA<BM, ASTR, A_IT>(sA, tid, areg);
    gemm_stsB<TRANSB>(sB, tid, breg);
    __syncthreads();

    int buf = 0;
    for (int t = 0; t < ntiles; t++) {
        bool more = (t + 1 < ntiles);
        if (more) {
            gemm_loadA<BM, A_IT>(A, M, K, row0, (t+1)*BK, tid, areg);
            gemm_loadB<TRANSB>(B, N, K, col0, (t+1)*BK, tid, breg);
        }
        const uint32_t* pA = sA + buf*BK*ASTR;
        const uint32_t* pB = sB + buf*BK*BSTR;
        #pragma unroll
        for (int ks = 0; ks < 2; ks++) {
            int kk = ks*8;
            uint32_t af[MT][4];
            #pragma unroll
            for (int i = 0; i < MT; i++) {
                int m0 = wm*WM + i*16;
                af[i][0] = pA[(kk+lc  )*ASTR + m0 + lr];
                af[i][1] = pA[(kk+lc  )*ASTR + m0 + lr + 8];
                af[i][2] = pA[(kk+lc+4)*ASTR + m0 + lr];
                af[i][3] = pA[(kk+lc+4)*ASTR + m0 + lr + 8];
            }
            uint32_t bf2[NT][2];
            #pragma unroll
            for (int j = 0; j < NT; j++) {
                int n0 = wn*WN + j*8;
                bf2[j][0] = pB[(kk+lc  )*BSTR + n0 + lr];
                bf2[j][1] = pB[(kk+lc+4)*BSTR + n0 + lr];
            }
            #pragma unroll
            for (int i = 0; i < MT; i++)
                #pragma unroll
                for (int j = 0; j < NT; j++)
                    mma_tf32(acc[i][j], af[i], bf2[j]);
        }
        if (more) {
            gemm_stsA<BM, ASTR, A_IT>(sA + (buf^1)*BK*ASTR, tid, areg);
            gemm_stsB<TRANSB>(sB + (buf^1)*BK*BSTR, tid, breg);
        }
        __syncthreads();
        buf ^= 1;
    }

    // epilogue
    #pragma unroll
    for (int i = 0; i < MT; i++) {
        int r0 = row0 + wm*WM + i*16 + lr;
        #pragma unroll
        for (int j = 0; j < NT; j++) {
            int c0 = col0 + wn*WN + j*8 + 2*lc;
            #pragma unroll
            for (int e = 0; e < 4; e++) {
                int r = r0 + (e >> 1)*8;
                int c = c0 + (e & 1);
                if (r < M && c < N) {
                    float v = acc[i][j][e] * scale;
                    if (bias)  v += bias[c];
                    if (resid) v += resid[(size_t)r*N + c];
                    C[(size_t)r*N + c] = v;
                }
            }
        }
    }
}

static void launch_tf32(const float* A, const float* B, const float* bias, const float* resid,
                        float* C, int M, int N, int K, float scale, bool transB, bool bigM)
{
    if (bigM) {
        dim3 grid((N + 63)/64, (M + 127)/128);
        if (transB) tf32_gemm<128,4,2,true ><<<grid,256>>>(A,B,bias,resid,C,M,N,K,scale);
        else        tf32_gemm<128,4,2,false><<<grid,256>>>(A,B,bias,resid,C,M,N,K,scale);
    } else {
        dim3 grid((N + 63)/64, (M + 63)/64);
        if (transB) tf32_gemm<64,2,4,true ><<<grid,256>>>(A,B,bias,resid,C,M,N,K,scale);
        else        tf32_gemm<64,2,4,false><<<grid,256>>>(A,B,bias,resid,C,M,N,K,scale);
    }
}

// ---------------- dedicated o1 @ W2 (K=384, N=10) ----------------
__global__ void gemm_w2(const float* __restrict__ o1, const float* __restrict__ W2,
                        float* __restrict__ h2)
{
    __shared__ float wT[OUTC][H1DIM];
    int tid = threadIdx.x;
    for (int i = tid; i < OUTC*H1DIM; i += blockDim.x) {
        int k = i / OUTC, c = i % OUTC;
        wT[c][k] = W2[i];
    }
    __syncthreads();
    int lane = tid & 31;
    int gw = blockIdx.x * (blockDim.x >> 5) + (tid >> 5);
    int nwarps = gridDim.x * (blockDim.x >> 5);
    for (int row = gw; row < NNODES; row += nwarps) {
        const float* rp = o1 + (size_t)row * H1DIM;
        float x[12];
        #pragma unroll
        for (int t = 0; t < 12; t++) x[t] = rp[lane + 32*t];
        float out[OUTC];
        #pragma unroll
        for (int c = 0; c < OUTC; c++) {
            float s = 0.f;
            #pragma unroll
            for (int t = 0; t < 12; t++) s += x[t] * wT[c][lane + 32*t];
            out[c] = s;
        }
        #pragma unroll
        for (int c = 0; c < OUTC; c++)
            #pragma unroll
            for (int o = 16; o; o >>= 1) out[c] += __shfl_xor_sync(~0u, out[c], o);
        if (lane == 0) {
            #pragma unroll
            for (int c = 0; c < OUTC; c++) h2[(size_t)row*OUTC + c] = out[c];
        }
    }
}

// ---------------- softmax over 4096-wide rows ----------------
__global__ void softmax_rows(float* __restrict__ S)
{
    __shared__ float buf[NPAIRS_MAP];
    __shared__ float red[256];
    int row = blockIdx.x, tid = threadIdx.x;
    float* r = S + (size_t)row * NPAIRS_MAP;
    float mx = -INFINITY;
    for (int i = tid; i < NPAIRS_MAP; i += 256) { float v = r[i]; buf[i] = v; mx = fmaxf(mx, v); }
    red[tid] = mx; __syncthreads();
    for (int o = 128; o; o >>= 1) { if (tid < o) red[tid] = fmaxf(red[tid], red[tid+o]); __syncthreads(); }
    mx = red[0]; __syncthreads();
    float sum = 0.f;
    for (int i = tid; i < NPAIRS_MAP; i += 256) { float e = expf(buf[i] - mx); buf[i] = e; sum += e; }
    red[tid] = sum; __syncthreads();
    for (int o = 128; o; o >>= 1) { if (tid < o) red[tid] += red[tid+o]; __syncthreads(); }
    float inv = 1.f / red[0];
    for (int i = tid; i < NPAIRS_MAP; i += 256) r[i] = buf[i] * inv;
}

// ---------------- misc elementwise ----------------
__global__ void fill_f32(float* p, float v, int n)
{ int i = blockIdx.x*blockDim.x + threadIdx.x; if (i < n) p[i] = v; }

__global__ void bias_elu(float* __restrict__ p, const float* __restrict__ b, int n, int cols)
{
    int i = blockIdx.x*blockDim.x + threadIdx.x; if (i >= n) return;
    float v = p[i] + b[i % cols];
    p[i] = v > 0.f ? v : expm1f(v);
}

__global__ void bias_add(float* __restrict__ p, const float* __restrict__ b, int n, int cols)
{ int i = blockIdx.x*blockDim.x + threadIdx.x; if (i < n) p[i] += b[i % cols]; }

// ---------------- scatter (last occurrence wins) ----------------
__global__ void scatter_winner(const int* __restrict__ com_idx, int* __restrict__ winner, int n)
{ int i = blockIdx.x*blockDim.x + threadIdx.x; if (i < n) atomicMax(&winner[com_idx[i]], i); }

__global__ void scatter_apply(const int* __restrict__ com_idx, const int* __restrict__ winner,
                              const float* __restrict__ fused, float* __restrict__ x, int n)
{
    int i = blockIdx.x*blockDim.x + threadIdx.x;
    int p = i / FEAT, c = i % FEAT;
    if (p >= n) return;
    int node = com_idx[p];
    if (winner[node] == p) x[(size_t)node*FEAT + c] = fused[(size_t)p*FEAT + c];
}

// ---------------- GAT layer 1 (H=3, C=128) ----------------
__global__ void node_e1(const float* __restrict__ h1, const float* __restrict__ a_src,
                        const float* __restrict__ a_dst, float* __restrict__ es, float* __restrict__ ed)
{
    int warp = (blockIdx.x*blockDim.x + threadIdx.x) >> 5;
    int lane = threadIdx.x & 31;
    int node = warp / HEADS, h = warp % HEADS;
    if (node >= NNODES) return;
    const float* hp = h1 + (size_t)node*H1DIM + h*HID;
    float s = 0.f, d = 0.f;
    #pragma unroll
    for (int c = lane; c < HID; c += 32) {
        float v = hp[c];
        s += v * a_src[h*HID + c];
        d += v * a_dst[h*HID + c];
    }
    #pragma unroll
    for (int o = 16; o; o >>= 1) { s += __shfl_xor_sync(~0u, s, o); d += __shfl_xor_sync(~0u, d, o); }
    if (!lane) { es[node*HEADS + h] = s; ed[node*HEADS + h] = d; }
}

__global__ void edge_max1(const int* __restrict__ src, const int* __restrict__ dst, int E,
                          const float* __restrict__ es, const float* __restrict__ ed,
                          float* __restrict__ m)
{
    int e = blockIdx.x*blockDim.x + threadIdx.x;
    if (e >= E + NNODES) return;
    int s = e < E ? src[e] : e - E;
    int d = e < E ? dst[e] : e - E;
    #pragma unroll
    for (int h = 0; h < HEADS; h++) {
        float v = es[s*HEADS+h] + ed[d*HEADS+h];
        v = v > 0.f ? v : 0.2f*v;
        atomicMaxFloat(&m[d*HEADS+h], v);
    }
}

__global__ void edge_exp1(const int* __restrict__ src, const int* __restrict__ dst, int E,
                          const float* __restrict__ es, const float* __restrict__ ed,
                          const float* __restrict__ m, float* __restrict__ den)
{
    int e = blockIdx.x*blockDim.x + threadIdx.x;
    if (e >= E + NNODES) return;
    int s = e < E ? src[e] : e - E;
    int d = e < E ? dst[e] : e - E;
    #pragma unroll
    for (int h = 0; h < HEADS; h++) {
        float v = es[s*HEADS+h] + ed[d*HEADS+h];
        v = v > 0.f ? v : 0.2f*v;
        atomicAdd(&den[d*HEADS+h], expf(v - m[d*HEADS+h]));
    }
}

__global__ void edge_agg1(const int* __restrict__ src, const int* __restrict__ dst, int E,
                          const float* __restrict__ es, const float* __restrict__ ed,
                          const float* __restrict__ m, const float* __restrict__ den,
                          const float* __restrict__ h1, float* __restrict__ out)
{
    int warp = (blockIdx.x*blockDim.x + threadIdx.x) >> 5;
    int lane = threadIdx.x & 31;
    if (warp >= E + NNODES) return;
    int s = warp < E ? src[warp] : warp - E;
    int d = warp < E ? dst[warp] : warp - E;
    float alpha[HEADS];
    #pragma unroll
    for (int h = 0; h < HEADS; h++) {
        float v = es[s*HEADS+h] + ed[d*HEADS+h];
        v = v > 0.f ? v : 0.2f*v;
        float ex = expf(v - m[d*HEADS+h]);
        alpha[h] = ex / (den[d*HEADS+h] + 1e-16f);
    }
    const float4* hp = (const float4*)(h1 + (size_t)s*H1DIM);
    float* op = out + (size_t)d*H1DIM;
    #pragma unroll
    for (int it = 0; it < 3; it++) {
        int i = lane + 32*it;
        float4 hv = hp[i];
        float a = alpha[it];
        red_add4(op + i*4, hv.x*a, hv.y*a, hv.z*a, hv.w*a);
    }
}

// ---------------- GAT layer 2 (H=1, C=10) ----------------
__global__ void node_e2(const float* __restrict__ h2, const float* __restrict__ a_src,
                        const float* __restrict__ a_dst, float* __restrict__ es, float* __restrict__ ed)
{
    int n = blockIdx.x*blockDim.x + threadIdx.x;
    if (n >= NNODES) return;
    float s = 0.f, d = 0.f;
    #pragma unroll
    for (int c = 0; c < OUTC; c++) {
        float v = h2[n*OUTC + c];
        s += v * a_src[c];
        d += v * a_dst[c];
    }
    es[n] = s; ed[n] = d;
}

__global__ void edge_max2(const int* __restrict__ src, const int* __restrict__ dst, int E,
                          const float* __restrict__ es, const float* __restrict__ ed, float* __restrict__ m)
{
    int e = blockIdx.x*blockDim.x + threadIdx.x;
    if (e >= E + NNODES) return;
    int s = e < E ? src[e] : e - E;
    int d = e < E ? dst[e] : e - E;
    float v = es[s] + ed[d];
    v = v > 0.f ? v : 0.2f*v;
    atomicMaxFloat(&m[d], v);
}

__global__ void edge_exp2(const int* __restrict__ src, const int* __restrict__ dst, int E,
                          const float* __restrict__ es, const float* __restrict__ ed,
                          const float* __restrict__ m, float* __restrict__ den)
{
    int e = blockIdx.x*blockDim.x + threadIdx.x;
    if (e >= E + NNODES) return;
    int s = e < E ? src[e] : e - E;
    int d = e < E ? dst[e] : e - E;
    float v = es[s] + ed[d];
    v = v > 0.f ? v : 0.2f*v;
    atomicAdd(&den[d], expf(v - m[d]));
}

__global__ void edge_agg2(const int* __restrict__ src, const int* __restrict__ dst, int E,
                          const float* __restrict__ es, const float* __restrict__ ed,
                          const float* __restrict__ m, const float* __restrict__ den,
                          const float* __restrict__ h2, float* __restrict__ out)
{
    int e = blockIdx.x*blockDim.x + threadIdx.x;
    if (e >= E + NNODES) return;
    int s = e < E ? src[e] : e - E;
    int d = e < E ? dst[e] : e - E;
    float v = es[s] + ed[d];
    v = v > 0.f ? v : 0.2f*v;
    float alpha = expf(v - m[d]) / (den[d] + 1e-16f);
    #pragma unroll
    for (int c = 0; c < OUTC; c++)
        atomicAdd(&out[d*OUTC + c], h2[s*OUTC + c] * alpha);
}

// ---------------- final pair scores ----------------
__global__ void pair_scores(const int* __restrict__ pair, const float* __restrict__ emb,
                            float* __restrict__ out, int n)
{
    int i = blockIdx.x*blockDim.x + threadIdx.x;
    if (i >= n) return;
    int a = pair[2*i], b = pair[2*i+1];
    const float* ea = emb + (size_t)a*OUTC;
    const float* eb = emb + (size_t)b*OUTC;
    float s = 0.f;
    #pragma unroll
    for (int c = 0; c < OUTC; c++) s += ea[c] * eb[c];
    out[i] = s;
}

// ---------------- host ----------------
extern "C" void kernel_launch(void* const* d_in, const int* in_sizes, int n_in,
                              void* d_out, int out_size)
{
    const float* fsub   = (const float*)d_in[0];
    const float* fcom   = (const float*)d_in[1];
    const float* x      = (const float*)d_in[2];
    const int*   comidx = (const int*)  d_in[3];
    const int*   edge   = (const int*)  d_in[4];
    const int*   pair   = (const int*)  d_in[5];
    const float* Wq = (const float*)d_in[6];  const float* bq = (const float*)d_in[7];
    const float* Wk = (const float*)d_in[8];  const float* bk = (const float*)d_in[9];
    const float* Wv = (const float*)d_in[10]; const float* bv = (const float*)d_in[11];
    const float* Wf = (const float*)d_in[12]; const float* bf = (const float*)d_in[13];
    const float* W1 = (const float*)d_in[14];
    const float* as1 = (const float*)d_in[15]; const float* ad1 = (const float*)d_in[16];
    const float* b1 = (const float*)d_in[17];
    const float* W2 = (const float*)d_in[18];
    const float* as2 = (const float*)d_in[19]; const float* ad2 = (const float*)d_in[20];
    const float* b2 = (const float*)d_in[21];
    float* out = (float*)d_out;

    const int E = in_sizes[4] / 2;
    const int* src = edge;
    const int* dst = edge + E;
    const int npairs = in_sizes[5] / 2;

    float *q, *k, *v, *S, *attv, *fused, *xw, *h1, *es1, *ed1, *m1, *den1, *o1;
    float *h2, *es2, *ed2, *m2, *den2, *o2;
    int* winner;
    cudaGetSymbolAddress((void**)&q, g_q);       cudaGetSymbolAddress((void**)&k, g_k);
    cudaGetSymbolAddress((void**)&v, g_v);       cudaGetSymbolAddress((void**)&S, g_S);
    cudaGetSymbolAddress((void**)&attv, g_attv); cudaGetSymbolAddress((void**)&fused, g_fused);
    cudaGetSymbolAddress((void**)&xw, g_x);      cudaGetSymbolAddress((void**)&winner, g_winner);
    cudaGetSymbolAddress((void**)&h1, g_h1);
    cudaGetSymbolAddress((void**)&es1, g_es1);   cudaGetSymbolAddress((void**)&ed1, g_ed1);
    cudaGetSymbolAddress((void**)&m1, g_m1);     cudaGetSymbolAddress((void**)&den1, g_den1);
    cudaGetSymbolAddress((void**)&o1, g_o1);     cudaGetSymbolAddress((void**)&h2, g_h2);
    cudaGetSymbolAddress((void**)&es2, g_es2);   cudaGetSymbolAddress((void**)&ed2, g_ed2);
    cudaGetSymbolAddress((void**)&m2, g_m2);     cudaGetSymbolAddress((void**)&den2, g_den2);
    cudaGetSymbolAddress((void**)&o2, g_o2);

    const float inv_sqrt_feat = 0.057735026918962584f;   // 1/sqrt(300)

    // ---- cross-attention (tensor cores, tf32) ----
    launch_tf32(fsub, Wq, bq, nullptr, q, NPAIRS_MAP, FEAT, FEAT, 1.f, false, false);
    launch_tf32(fcom, Wk, bk, nullptr, k, NPAIRS_MAP, FEAT, FEAT, 1.f, false, false);
    launch_tf32(fcom, Wv, bv, nullptr, v, NPAIRS_MAP, FEAT, FEAT, 1.f, false, false);
    launch_tf32(q, k, nullptr, nullptr, S, NPAIRS_MAP, NPAIRS_MAP, FEAT, inv_sqrt_feat, true, true);
    softmax_rows<<<NPAIRS_MAP, 256>>>(S);
    launch_tf32(S, v, nullptr, fsub, attv, NPAIRS_MAP, FEAT, NPAIRS_MAP, 1.f, false, false);
    launch_tf32(attv, Wf, bf, nullptr, fused, NPAIRS_MAP, FEAT, FEAT, 1.f, false, false);

    // ---- write fused rows into x (last-occurrence-wins) ----
    cudaMemcpyAsync(xw, x, (size_t)NNODES*FEAT*sizeof(float), cudaMemcpyDeviceToDevice, 0);
    cudaMemsetAsync(winner, 0xFF, NNODES*sizeof(int), 0);
    scatter_winner<<<(NPAIRS_MAP + 255)/256, 256>>>(comidx, winner, NPAIRS_MAP);
    scatter_apply<<<(NPAIRS_MAP*FEAT + 255)/256, 256>>>(comidx, winner, fused, xw, NPAIRS_MAP);

    // ---- GAT layer 1 ----
    launch_tf32(xw, W1, nullptr, nullptr, h1, NNODES, H1DIM, FEAT, 1.f, false, true);
    {
        int warps = NNODES*HEADS;
        node_e1<<<(warps*32 + 255)/256, 256>>>(h1, as1, ad1, es1, ed1);
    }
    fill_f32<<<(NNODES*HEADS + 255)/256, 256>>>(m1, -INFINITY, NNODES*HEADS);
    cudaMemsetAsync(den1, 0, NNODES*HEADS*sizeof(float), 0);
    cudaMemsetAsync(o1, 0, (size_t)NNODES*H1DIM*sizeof(float), 0);
    {
        int tot = E + NNODES;
        edge_max1<<<(tot + 255)/256, 256>>>(src, dst, E, es1, ed1, m1);
        edge_exp1<<<(tot + 255)/256, 256>>>(src, dst, E, es1, ed1, m1, den1);
        edge_agg1<<<((size_t)tot*32 + 255)/256, 256>>>(src, dst, E, es1, ed1, m1, den1, h1, o1);
    }
    bias_elu<<<((size_t)NNODES*H1DIM + 255)/256, 256>>>(o1, b1, NNODES*H1DIM, H1DIM);

    // ---- GAT layer 2 ----
    gemm_w2<<<1024, 256>>>(o1, W2, h2);
    node_e2<<<(NNODES + 255)/256, 256>>>(h2, as2, ad2, es2, ed2);
    fill_f32<<<(NNODES + 255)/256, 256>>>(m2, -INFINITY, NNODES);
    cudaMemsetAsync(den2, 0, NNODES*sizeof(float), 0);
    cudaMemsetAsync(o2, 0, NNODES*OUTC*sizeof(float), 0);
    {
        int tot = E + NNODES;
        edge_max2<<<(tot + 255)/256, 256>>>(src, dst, E, es2, ed2, m2);
        edge_exp2<<<(tot + 255)/256, 256>>>(src, dst, E, es2, ed2, m2, den2);
        edge_agg2<<<(tot + 255)/256, 256>>>(src, dst, E, es2, ed2, m2, den2, h2, o2);
    }
    bias_add<<<(NNODES*OUTC + 255)/256, 256>>>(o2, b2, NNODES*OUTC, OUTC);

    // ---- pair scores ----
    pair_scores<<<(npairs + 255)/256, 256>>>(pair, o2, out, npairs);
}

// round 4
// speedup vs baseline: 2.1564x; 1.1720x over previous
#include <cuda_runtime.h>
#include <math.h>
#include <stdint.h>

// ---------------- problem constants ----------------
#define NPAIRS_MAP 4096
#define NNODES     50000
#define MAXEDGES   524288
#define FEAT       300
#define HID        128
#define HEADS      3
#define OUTC       10
#define H1DIM      (HEADS*HID)   // 384

// ---------------- scratch ----------------
__device__ float g_q[NPAIRS_MAP*FEAT];
__device__ float g_k[NPAIRS_MAP*FEAT];
__device__ float g_v[NPAIRS_MAP*FEAT];
__device__ float g_S[(size_t)NPAIRS_MAP*NPAIRS_MAP];
__device__ float g_attv[NPAIRS_MAP*FEAT];
__device__ float g_fused[NPAIRS_MAP*FEAT];
__device__ float g_x[NNODES*FEAT];
__device__ int   g_winner[NNODES];
__device__ float g_h1[(size_t)NNODES*H1DIM];
__device__ float g_es1[NNODES*HEADS];
__device__ float g_ed1[NNODES*HEADS];
__device__ float g_h2[NNODES*OUTC];
__device__ float g_es2[NNODES];
__device__ float g_ed2[NNODES];
__device__ float g_o2[NNODES*OUTC];
__device__ int   g_deg[NNODES];
__device__ int   g_off[NNODES+1];
__device__ int   g_cur[NNODES];
__device__ int   g_csr[MAXEDGES];

// ---------------- helpers ----------------
__device__ __forceinline__ uint32_t f2tf32(float f) {
    uint32_t u; asm("cvt.rna.tf32.f32 %0, %1;" : "=r"(u) : "f"(f)); return u;
}

__device__ __forceinline__ void mma_tf32(float* c, const uint32_t* a, const uint32_t* b) {
    asm volatile("mma.sync.aligned.m16n8k8.row.col.f32.tf32.tf32.f32 "
        "{%0,%1,%2,%3}, {%4,%5,%6,%7}, {%8,%9}, {%0,%1,%2,%3};"
        : "+f"(c[0]), "+f"(c[1]), "+f"(c[2]), "+f"(c[3])
        : "r"(a[0]), "r"(a[1]), "r"(a[2]), "r"(a[3]), "r"(b[0]), "r"(b[1]));
}

__device__ __forceinline__ float leaky(float v) { return v > 0.f ? v : 0.2f*v; }

// ---------------- TF32 tensor-core GEMM (unchanged from R3) ----------------
template<int BM, int A_IT>
__device__ __forceinline__ void gemm_loadA(const float* __restrict__ A, int M, int K,
                                           int row0, int k0, int tid, float (&areg)[A_IT][8])
{
    #pragma unroll
    for (int i = 0; i < A_IT; i++) {
        int idx = tid + i*256;
        #pragma unroll
        for (int j = 0; j < 8; j++) areg[i][j] = 0.f;
        if (idx < BM*2) {
            int r = idx >> 1, seg = idx & 1;
            int grow = row0 + r, gk = k0 + seg*8;
            if (grow < M) {
                const float* ap = A + (size_t)grow*K + gk;
                if (gk + 8 <= K) {
                    float4 v0 = *(const float4*)ap;
                    float4 v1 = *(const float4*)(ap+4);
                    areg[i][0]=v0.x; areg[i][1]=v0.y; areg[i][2]=v0.z; areg[i][3]=v0.w;
                    areg[i][4]=v1.x; areg[i][5]=v1.y; areg[i][6]=v1.z; areg[i][7]=v1.w;
                } else {
                    #pragma unroll
                    for (int j = 0; j < 8; j++) if (gk + j < K) areg[i][j] = ap[j];
                }
            }
        }
    }
}

template<bool TRANSB>
__device__ __forceinline__ void gemm_loadB(const float* __restrict__ B, int N, int K,
                                           int col0, int k0, int tid, float (&breg)[4])
{
    breg[0]=breg[1]=breg[2]=breg[3]=0.f;
    if (TRANSB) {
        int n = tid & 63, seg = tid >> 6;
        int gn = col0 + n, gk = k0 + seg*4;
        if (gn < N) {
            const float* bp = B + (size_t)gn*K + gk;
            if (gk + 4 <= K) {
                float4 v = *(const float4*)bp;
                breg[0]=v.x; breg[1]=v.y; breg[2]=v.z; breg[3]=v.w;
            } else {
                #pragma unroll
                for (int j = 0; j < 4; j++) if (gk + j < K) breg[j] = bp[j];
            }
        }
    } else {
        int kk = tid >> 4, f = tid & 15;
        int gk = k0 + kk, gc = col0 + f*4;
        if (gk < K) {
            const float* bp = B + (size_t)gk*N + gc;
            if (gc + 4 <= N) {
                float4 v = *(const float4*)bp;
                breg[0]=v.x; breg[1]=v.y; breg[2]=v.z; breg[3]=v.w;
            } else {
                #pragma unroll
                for (int j = 0; j < 4; j++) if (gc + j < N) breg[j] = bp[j];
            }
        }
    }
}

template<int BM, int ASTR, int A_IT>
__device__ __forceinline__ void gemm_stsA(uint32_t* __restrict__ sA, int tid,
                                          const float (&areg)[A_IT][8])
{
    #pragma unroll
    for (int i = 0; i < A_IT; i++) {
        int idx = tid + i*256;
        if (idx < BM*2) {
            int r = idx >> 1, seg = idx & 1;
            #pragma unroll
            for (int j = 0; j < 8; j++)
                sA[(seg*8 + j)*ASTR + r] = f2tf32(areg[i][j]);
        }
    }
}

template<bool TRANSB>
__device__ __forceinline__ void gemm_stsB(uint32_t* __restrict__ sB, int tid,
                                          const float (&breg)[4])
{
    if (TRANSB) {
        int n = tid & 63, seg = tid >> 6;
        #pragma unroll
        for (int j = 0; j < 4; j++)
            sB[(seg*4 + j)*72 + n] = f2tf32(breg[j]);
    } else {
        int kk = tid >> 4, f = tid & 15;
        uint4 v;
        v.x = f2tf32(breg[0]); v.y = f2tf32(breg[1]);
        v.z = f2tf32(breg[2]); v.w = f2tf32(breg[3]);
        *(uint4*)&sB[kk*72 + f*4] = v;
    }
}

template<int BM, int WARPS_M, int WARPS_N, bool TRANSB>
__global__ void __launch_bounds__(256)
tf32_gemm(const float* __restrict__ A, const float* __restrict__ B,
          const float* __restrict__ bias, const float* __restrict__ resid,
          float* __restrict__ C, int M, int N, int K, float scale)
{
    constexpr int BK = 16;
    constexpr int ASTR = BM + 8;
    constexpr int BSTR = 72;
    constexpr int WM = BM / WARPS_M, WN = 64 / WARPS_N;
    constexpr int MT = WM / 16, NT = WN / 8;
    constexpr int A_IT = (BM*2 + 255) / 256;

    __shared__ uint32_t sA[2*BK*ASTR];
    __shared__ uint32_t sB[2*BK*BSTR];

    int tid = threadIdx.x, lane = tid & 31, warp = tid >> 5;
    int wm = warp % WARPS_M, wn = warp / WARPS_M;
    int row0 = blockIdx.y * BM, col0 = blockIdx.x * 64;
    int lr = lane >> 2, lc = lane & 3;

    float acc[MT][NT][4];
    #pragma unroll
    for (int i = 0; i < MT; i++)
        #pragma unroll
        for (int j = 0; j < NT; j++)
            #pragma unroll
            for (int e = 0; e < 4; e++) acc[i][j][e] = 0.f;

    int ntiles = (K + BK - 1) / BK;
    float areg[A_IT][8];
    float breg[4];

    gemm_loadA<BM, A_IT>(A, M, K, row0, 0, tid, areg);
    gemm_loadB<TRANSB>(B, N, K, col0, 0, tid, breg);
    gemm_stsA<BM, ASTR, A_IT>(sA, tid, areg);
    gemm_stsB<TRANSB>(sB, tid, breg);
    __syncthreads();

    int buf = 0;
    for (int t = 0; t < ntiles; t++) {
        bool more = (t + 1 < ntiles);
        if (more) {
            gemm_loadA<BM, A_IT>(A, M, K, row0, (t+1)*BK, tid, areg);
            gemm_loadB<TRANSB>(B, N, K, col0, (t+1)*BK, tid, breg);
        }
        const uint32_t* pA = sA + buf*BK*ASTR;
        const uint32_t* pB = sB + buf*BK*BSTR;
        #pragma unroll
        for (int ks = 0; ks < 2; ks++) {
            int kk = ks*8;
            uint32_t af[MT][4];
            #pragma unroll
            for (int i = 0; i < MT; i++) {
                int m0 = wm*WM + i*16;
                af[i][0] = pA[(kk+lc  )*ASTR + m0 + lr];
                af[i][1] = pA[(kk+lc  )*ASTR + m0 + lr + 8];
                af[i][2] = pA[(kk+lc+4)*ASTR + m0 + lr];
                af[i][3] = pA[(kk+lc+4)*ASTR + m0 + lr + 8];
            }
            uint32_t bf2[NT][2];
            #pragma unroll
            for (int j = 0; j < NT; j++) {
                int n0 = wn*WN + j*8;
                bf2[j][0] = pB[(kk+lc  )*BSTR + n0 + lr];
                bf2[j][1] = pB[(kk+lc+4)*BSTR + n0 + lr];
            }
            #pragma unroll
            for (int i = 0; i < MT; i++)
                #pragma unroll
                for (int j = 0; j < NT; j++)
                    mma_tf32(acc[i][j], af[i], bf2[j]);
        }
        if (more) {
            gemm_stsA<BM, ASTR, A_IT>(sA + (buf^1)*BK*ASTR, tid, areg);
            gemm_stsB<TRANSB>(sB + (buf^1)*BK*BSTR, tid, breg);
        }
        __syncthreads();
        buf ^= 1;
    }

    #pragma unroll
    for (int i = 0; i < MT; i++) {
        int r0 = row0 + wm*WM + i*16 + lr;
        #pragma unroll
        for (int j = 0; j < NT; j++) {
            int c0 = col0 + wn*WN + j*8 + 2*lc;
            #pragma unroll
            for (int e = 0; e < 4; e++) {
                int r = r0 + (e >> 1)*8;
                int c = c0 + (e & 1);
                if (r < M && c < N) {
                    float v = acc[i][j][e] * scale;
                    if (bias)  v += bias[c];
                    if (resid) v += resid[(size_t)r*N + c];
                    C[(size_t)r*N + c] = v;
                }
            }
        }
    }
}

static void launch_tf32(const float* A, const float* B, const float* bias, const float* resid,
                        float* C, int M, int N, int K, float scale, bool transB, bool bigM)
{
    if (bigM) {
        dim3 grid((N + 63)/64, (M + 127)/128);
        if (transB) tf32_gemm<128,4,2,true ><<<grid,256>>>(A,B,bias,resid,C,M,N,K,scale);
        else        tf32_gemm<128,4,2,false><<<grid,256>>>(A,B,bias,resid,C,M,N,K,scale);
    } else {
        dim3 grid((N + 63)/64, (M + 63)/64);
        if (transB) tf32_gemm<64,2,4,true ><<<grid,256>>>(A,B,bias,resid,C,M,N,K,scale);
        else        tf32_gemm<64,2,4,false><<<grid,256>>>(A,B,bias,resid,C,M,N,K,scale);
    }
}

// ---------------- softmax over 4096-wide rows ----------------
__global__ void softmax_rows(float* __restrict__ S)
{
    __shared__ float buf[NPAIRS_MAP];
    __shared__ float red[256];
    int row = blockIdx.x, tid = threadIdx.x;
    float* r = S + (size_t)row * NPAIRS_MAP;
    float mx = -INFINITY;
    for (int i = tid; i < NPAIRS_MAP; i += 256) { float v = r[i]; buf[i] = v; mx = fmaxf(mx, v); }
    red[tid] = mx; __syncthreads();
    for (int o = 128; o; o >>= 1) { if (tid < o) red[tid] = fmaxf(red[tid], red[tid+o]); __syncthreads(); }
    mx = red[0]; __syncthreads();
    float sum = 0.f;
    for (int i = tid; i < NPAIRS_MAP; i += 256) { float e = expf(buf[i] - mx); buf[i] = e; sum += e; }
    red[tid] = sum; __syncthreads();
    for (int o = 128; o; o >>= 1) { if (tid < o) red[tid] += red[tid+o]; __syncthreads(); }
    float inv = 1.f / red[0];
    for (int i = tid; i < NPAIRS_MAP; i += 256) r[i] = buf[i] * inv;
}

// ---------------- scatter (last occurrence wins) ----------------
__global__ void scatter_winner(const int* __restrict__ com_idx, int* __restrict__ winner, int n)
{ int i = blockIdx.x*blockDim.x + threadIdx.x; if (i < n) atomicMax(&winner[com_idx[i]], i); }

__global__ void scatter_apply(const int* __restrict__ com_idx, const int* __restrict__ winner,
                              const float* __restrict__ fused, float* __restrict__ x, int n)
{
    int i = blockIdx.x*blockDim.x + threadIdx.x;
    int p = i / FEAT, c = i % FEAT;
    if (p >= n) return;
    int node = com_idx[p];
    if (winner[node] == p) x[(size_t)node*FEAT + c] = fused[(size_t)p*FEAT + c];
}

// ---------------- CSR build by dst ----------------
__global__ void hist_dst(const int* __restrict__ dst, int* __restrict__ deg, int E)
{ int e = blockIdx.x*blockDim.x + threadIdx.x; if (e < E) atomicAdd(&deg[dst[e]], 1); }

__global__ void scan_deg(const int* __restrict__ deg, int* __restrict__ off,
                         int* __restrict__ cur, int n)
{
    __shared__ int warp_sums[32];
    __shared__ int s_carry;
    int tid = threadIdx.x;             // 1024
    int lane = tid & 31, w = tid >> 5;
    if (tid == 0) s_carry = 0;
    __syncthreads();
    for (int base = 0; base < n; base += 1024) {
        int i = base + tid;
        int v = (i < n) ? deg[i] : 0;
        int x = v;
        #pragma unroll
        for (int o = 1; o < 32; o <<= 1) { int y = __shfl_up_sync(~0u, x, o); if (lane >= o) x += y; }
        if (lane == 31) warp_sums[w] = x;
        __syncthreads();
        if (w == 0) {
            int t = warp_sums[lane];
            #pragma unroll
            for (int o = 1; o < 32; o <<= 1) { int y = __shfl_up_sync(~0u, t, o); if (lane >= o) t += y; }
            warp_sums[lane] = t;
        }
        __syncthreads();
        int warp_off = (w == 0) ? 0 : warp_sums[w-1];
        int incl = x + warp_off;
        int carry = s_carry;
        if (i < n) { off[i] = carry + incl - v; cur[i] = carry + incl - v; }
        __syncthreads();
        if (tid == 1023) s_carry = carry + incl;
        __syncthreads();
    }
    if (threadIdx.x == 0) off[n] = s_carry;
}

__global__ void scatter_csr(const int* __restrict__ src, const int* __restrict__ dst,
                            int* __restrict__ cur, int* __restrict__ csr, int E)
{
    int e = blockIdx.x*blockDim.x + threadIdx.x;
    if (e >= E) return;
    int pos = atomicAdd(&cur[dst[e]], 1);
    csr[pos] = src[e];
}

// ---------------- node scores for layer 1 ----------------
__global__ void node_e1(const float* __restrict__ h1, const float* __restrict__ a_src,
                        const float* __restrict__ a_dst, float* __restrict__ es, float* __restrict__ ed)
{
    int warp = (blockIdx.x*blockDim.x + threadIdx.x) >> 5;
    int lane = threadIdx.x & 31;
    int node = warp / HEADS, h = warp % HEADS;
    if (node >= NNODES) return;
    const float* hp = h1 + (size_t)node*H1DIM + h*HID;
    float s = 0.f, d = 0.f;
    #pragma unroll
    for (int c = lane; c < HID; c += 32) {
        float v = hp[c];
        s += v * a_src[h*HID + c];
        d += v * a_dst[h*HID + c];
    }
    #pragma unroll
    for (int o = 16; o; o >>= 1) { s += __shfl_xor_sync(~0u, s, o); d += __shfl_xor_sync(~0u, d, o); }
    if (!lane) { es[node*HEADS + h] = s; ed[node*HEADS + h] = d; }
}

// ---------------- mega-fused GAT1 aggregate + ELU + W2 GEMV + node_e2 ----------------
__global__ void __launch_bounds__(256)
gat1_fused(const int* __restrict__ off, const int* __restrict__ csr,
           const float* __restrict__ es, const float* __restrict__ ed,
           const float* __restrict__ h1, const float* __restrict__ b1,
           const float* __restrict__ W2, const float* __restrict__ as2,
           const float* __restrict__ ad2,
           float* __restrict__ h2, float* __restrict__ es2, float* __restrict__ ed2)
{
    __shared__ float wT[OUTC][H1DIM];     // W2 transposed: [10][384]
    __shared__ float sb1[H1DIM];
    int tid = threadIdx.x;
    for (int i = tid; i < OUTC*H1DIM; i += 256) {
        int k = i / OUTC, c = i % OUTC;
        wT[c][k] = W2[i];
    }
    for (int i = tid; i < H1DIM; i += 256) sb1[i] = b1[i];
    __syncthreads();

    int lane = tid & 31;
    int d = blockIdx.x*8 + (tid >> 5);
    if (d >= NNODES) return;

    int s0 = off[d], s1 = off[d+1];
    float edv[HEADS], eself[HEADS], m[HEADS];
    #pragma unroll
    for (int h = 0; h < HEADS; h++) {
        edv[h] = ed[d*HEADS + h];
        eself[h] = leaky(es[d*HEADS + h] + edv[h]);
        m[h] = eself[h];
    }
    // phase A: per-dst max (lane-parallel over edges)
    for (int i = s0 + lane; i < s1; i += 32) {
        int s = csr[i];
        #pragma unroll
        for (int h = 0; h < HEADS; h++)
            m[h] = fmaxf(m[h], leaky(es[s*HEADS + h] + edv[h]));
    }
    #pragma unroll
    for (int h = 0; h < HEADS; h++)
        #pragma unroll
        for (int o = 16; o; o >>= 1) m[h] = fmaxf(m[h], __shfl_xor_sync(~0u, m[h], o));

    // phase B: weighted accumulation (self-loop first)
    float den[HEADS];
    float acc[12];
    {
        const float* hp = h1 + (size_t)d*H1DIM;
        #pragma unroll
        for (int h = 0; h < HEADS; h++) den[h] = expf(eself[h] - m[h]);
        #pragma unroll
        for (int t = 0; t < 12; t++) acc[t] = hp[lane + 32*t] * den[t >> 2];
    }
    for (int i = s0; i < s1; i++) {
        int s = csr[i];                    // uniform across warp -> broadcast
        float w[HEADS];
        #pragma unroll
        for (int h = 0; h < HEADS; h++) {
            w[h] = expf(leaky(es[s*HEADS + h] + edv[h]) - m[h]);
            den[h] += w[h];
        }
        const float* sp = h1 + (size_t)s*H1DIM;
        #pragma unroll
        for (int t = 0; t < 12; t++) acc[t] += w[t >> 2] * sp[lane + 32*t];
    }
    float inv[HEADS];
    #pragma unroll
    for (int h = 0; h < HEADS; h++) inv[h] = 1.f / (den[h] + 1e-16f);

    // bias + ELU
    float v[12];
    #pragma unroll
    for (int t = 0; t < 12; t++) {
        float x = acc[t]*inv[t >> 2] + sb1[lane + 32*t];
        v[t] = x > 0.f ? x : expm1f(x);
    }
    // W2 GEMV: h2[d][j] = sum_c v[c]*W2[c][j]
    float hh[OUTC];
    #pragma unroll
    for (int j = 0; j < OUTC; j++) {
        float s = 0.f;
        #pragma unroll
        for (int t = 0; t < 12; t++) s += v[t] * wT[j][lane + 32*t];
        #pragma unroll
        for (int o = 16; o; o >>= 1) s += __shfl_xor_sync(~0u, s, o);
        hh[j] = s;
    }
    if (lane == 0) {
        float s2 = 0.f, d2 = 0.f;
        #pragma unroll
        for (int j = 0; j < OUTC; j++) {
            h2[(size_t)d*OUTC + j] = hh[j];
            s2 += hh[j] * as2[j];
            d2 += hh[j] * ad2[j];
        }
        es2[d] = s2; ed2[d] = d2;
    }
}

// ---------------- fused GAT2 aggregate + bias ----------------
__global__ void __launch_bounds__(256)
gat2_fused(const int* __restrict__ off, const int* __restrict__ csr,
           const float* __restrict__ es, const float* __restrict__ ed,
           const float* __restrict__ h2, const float* __restrict__ b2,
           float* __restrict__ o2)
{
    int lane = threadIdx.x & 31;
    int d = blockIdx.x*8 + (threadIdx.x >> 5);
    if (d >= NNODES) return;
    int s0 = off[d], s1 = off[d+1];
    float edv = ed[d];
    float eself = leaky(es[d] + edv);
    float m = eself;
    for (int i = s0 + lane; i < s1; i += 32)
        m = fmaxf(m, leaky(es[csr[i]] + edv));
    #pragma unroll
    for (int o = 16; o; o >>= 1) m = fmaxf(m, __shfl_xor_sync(~0u, m, o));

    float den = 0.f;
    float acc[OUTC];
    #pragma unroll
    for (int c = 0; c < OUTC; c++) acc[c] = 0.f;
    for (int i = s0 + lane; i < s1; i += 32) {
        int s = csr[i];
        float w = expf(leaky(es[s] + edv) - m);
        den += w;
        const float* hp = h2 + (size_t)s*OUTC;
        #pragma unroll
        for (int c = 0; c < OUTC; c++) acc[c] += w * hp[c];
    }
    if (lane == 0) {
        float w = expf(eself - m);
        den += w;
        const float* hp = h2 + (size_t)d*OUTC;
        #pragma unroll
        for (int c = 0; c < OUTC; c++) acc[c] += w * hp[c];
    }
    #pragma unroll
    for (int o = 16; o; o >>= 1) {
        den += __shfl_xor_sync(~0u, den, o);
        #pragma unroll
        for (int c = 0; c < OUTC; c++) acc[c] += __shfl_xor_sync(~0u, acc[c], o);
    }
    if (lane == 0) {
        float inv = 1.f / (den + 1e-16f);
        #pragma unroll
        for (int c = 0; c < OUTC; c++) o2[(size_t)d*OUTC + c] = acc[c]*inv + b2[c];
    }
}

// ---------------- final pair scores ----------------
__global__ void pair_scores(const int* __restrict__ pair, const float* __restrict__ emb,
                            float* __restrict__ out, int n)
{
    int i = blockIdx.x*blockDim.x + threadIdx.x;
    if (i >= n) return;
    int a = pair[2*i], b = pair[2*i+1];
    const float* ea = emb + (size_t)a*OUTC;
    const float* eb = emb + (size_t)b*OUTC;
    float s = 0.f;
    #pragma unroll
    for (int c = 0; c < OUTC; c++) s += ea[c] * eb[c];
    out[i] = s;
}

// ---------------- host ----------------
extern "C" void kernel_launch(void* const* d_in, const int* in_sizes, int n_in,
                              void* d_out, int out_size)
{
    const float* fsub   = (const float*)d_in[0];
    const float* fcom   = (const float*)d_in[1];
    const float* x      = (const float*)d_in[2];
    const int*   comidx = (const int*)  d_in[3];
    const int*   edge   = (const int*)  d_in[4];
    const int*   pair   = (const int*)  d_in[5];
    const float* Wq = (const float*)d_in[6];  const float* bq = (const float*)d_in[7];
    const float* Wk = (const float*)d_in[8];  const float* bk = (const float*)d_in[9];
    const float* Wv = (const float*)d_in[10]; const float* bv = (const float*)d_in[11];
    const float* Wf = (const float*)d_in[12]; const float* bf = (const float*)d_in[13];
    const float* W1 = (const float*)d_in[14];
    const float* as1 = (const float*)d_in[15]; const float* ad1 = (const float*)d_in[16];
    const float* b1 = (const float*)d_in[17];
    const float* W2 = (const float*)d_in[18];
    const float* as2 = (const float*)d_in[19]; const float* ad2 = (const float*)d_in[20];
    const float* b2 = (const float*)d_in[21];
    float* out = (float*)d_out;

    const int E = in_sizes[4] / 2;
    const int* src = edge;
    const int* dst = edge + E;
    const int npairs = in_sizes[5] / 2;

    float *q, *k, *v, *S, *attv, *fused, *xw, *h1, *es1, *ed1;
    float *h2, *es2, *ed2, *o2;
    int *winner, *deg, *off, *cur, *csr;
    cudaGetSymbolAddress((void**)&q, g_q);       cudaGetSymbolAddress((void**)&k, g_k);
    cudaGetSymbolAddress((void**)&v, g_v);       cudaGetSymbolAddress((void**)&S, g_S);
    cudaGetSymbolAddress((void**)&attv, g_attv); cudaGetSymbolAddress((void**)&fused, g_fused);
    cudaGetSymbolAddress((void**)&xw, g_x);      cudaGetSymbolAddress((void**)&winner, g_winner);
    cudaGetSymbolAddress((void**)&h1, g_h1);
    cudaGetSymbolAddress((void**)&es1, g_es1);   cudaGetSymbolAddress((void**)&ed1, g_ed1);
    cudaGetSymbolAddress((void**)&h2, g_h2);
    cudaGetSymbolAddress((void**)&es2, g_es2);   cudaGetSymbolAddress((void**)&ed2, g_ed2);
    cudaGetSymbolAddress((void**)&o2, g_o2);
    cudaGetSymbolAddress((void**)&deg, g_deg);   cudaGetSymbolAddress((void**)&off, g_off);
    cudaGetSymbolAddress((void**)&cur, g_cur);   cudaGetSymbolAddress((void**)&csr, g_csr);

    const float inv_sqrt_feat = 0.057735026918962584f;   // 1/sqrt(300)

    // ---- CSR build (independent of everything else) ----
    cudaMemsetAsync(deg, 0, NNODES*sizeof(int), 0);
    hist_dst<<<(E + 255)/256, 256>>>(dst, deg, E);
    scan_deg<<<1, 1024>>>(deg, off, cur, NNODES);
    scatter_csr<<<(E + 255)/256, 256>>>(src, dst, cur, csr, E);

    // ---- cross-attention (tensor cores, tf32) ----
    launch_tf32(fsub, Wq, bq, nullptr, q, NPAIRS_MAP, FEAT, FEAT, 1.f, false, false);
    launch_tf32(fcom, Wk, bk, nullptr, k, NPAIRS_MAP, FEAT, FEAT, 1.f, false, false);
    launch_tf32(fcom, Wv, bv, nullptr, v, NPAIRS_MAP, FEAT, FEAT, 1.f, false, false);
    launch_tf32(q, k, nullptr, nullptr, S, NPAIRS_MAP, NPAIRS_MAP, FEAT, inv_sqrt_feat, true, true);
    softmax_rows<<<NPAIRS_MAP, 256>>>(S);
    launch_tf32(S, v, nullptr, fsub, attv, NPAIRS_MAP, FEAT, NPAIRS_MAP, 1.f, false, false);
    launch_tf32(attv, Wf, bf, nullptr, fused, NPAIRS_MAP, FEAT, FEAT, 1.f, false, false);

    // ---- write fused rows into x (last-occurrence-wins) ----
    cudaMemcpyAsync(xw, x, (size_t)NNODES*FEAT*sizeof(float), cudaMemcpyDeviceToDevice, 0);
    cudaMemsetAsync(winner, 0xFF, NNODES*sizeof(int), 0);
    scatter_winner<<<(NPAIRS_MAP + 255)/256, 256>>>(comidx, winner, NPAIRS_MAP);
    scatter_apply<<<(NPAIRS_MAP*FEAT + 255)/256, 256>>>(comidx, winner, fused, xw, NPAIRS_MAP);

    // ---- GAT layer 1: GEMM + node scores + mega-fused aggregation ----
    launch_tf32(xw, W1, nullptr, nullptr, h1, NNODES, H1DIM, FEAT, 1.f, false, true);
    node_e1<<<(NNODES*HEADS*32 + 255)/256, 256>>>(h1, as1, ad1, es1, ed1);
    gat1_fused<<<(NNODES + 7)/8, 256>>>(off, csr, es1, ed1, h1, b1, W2, as2, ad2,
                                        h2, es2, ed2);

    // ---- GAT layer 2: fused aggregation + bias ----
    gat2_fused<<<(NNODES + 7)/8, 256>>>(off, csr, es2, ed2, h2, b2, o2);

    // ---- pair scores ----
    pair_scores<<<(npairs + 255)/256, 256>>>(pair, o2, out, npairs);
}

// round 5
// speedup vs baseline: 2.5470x; 1.1811x over previous
#include <cuda_runtime.h>
#include <math.h>
#include <stdint.h>

// ---------------- problem constants ----------------
#define NPAIRS_MAP 4096
#define NNODES     50000
#define MAXEDGES   524288
#define FEAT       300
#define HID        128
#define HEADS      3
#define OUTC       10
#define H1DIM      (HEADS*HID)   // 384

// ---------------- scratch ----------------
__device__ float g_q[NPAIRS_MAP*FEAT];
__device__ float g_k[NPAIRS_MAP*FEAT];
__device__ float g_v[NPAIRS_MAP*FEAT];
__device__ float g_S[(size_t)NPAIRS_MAP*NPAIRS_MAP];
__device__ float g_attv[NPAIRS_MAP*FEAT];
__device__ float g_fused[NPAIRS_MAP*FEAT];
__device__ float g_x[NNODES*FEAT];
__device__ int   g_winner[NNODES];
__device__ float g_h1[(size_t)NNODES*H1DIM];
__device__ float g_es1[NNODES*HEADS];
__device__ float g_ed1[NNODES*HEADS];
__device__ float g_h2[NNODES*OUTC];
__device__ float g_es2[NNODES];
__device__ float g_ed2[NNODES];
__device__ float g_o2[NNODES*OUTC];
__device__ int   g_deg[NNODES];
__device__ int   g_off[NNODES+1];
__device__ int   g_cur[NNODES];
__device__ int   g_csr[MAXEDGES];

// ---------------- helpers ----------------
__device__ __forceinline__ uint32_t f2tf32(float f) {
    uint32_t u; asm("cvt.rna.tf32.f32 %0, %1;" : "=r"(u) : "f"(f)); return u;
}

__device__ __forceinline__ void mma_tf32(float* c, const uint32_t* a, const uint32_t* b) {
    asm volatile("mma.sync.aligned.m16n8k8.row.col.f32.tf32.tf32.f32 "
        "{%0,%1,%2,%3}, {%4,%5,%6,%7}, {%8,%9}, {%0,%1,%2,%3};"
        : "+f"(c[0]), "+f"(c[1]), "+f"(c[2]), "+f"(c[3])
        : "r"(a[0]), "r"(a[1]), "r"(a[2]), "r"(a[3]), "r"(b[0]), "r"(b[1]));
}

__device__ __forceinline__ float leaky(float v) { return v > 0.f ? v : 0.2f*v; }

// ---------------- generic loaders (8 k-floats per row-slot) ----------------
template<int ROWS, int IT>
__device__ __forceinline__ void ld8(const float* __restrict__ P, int nrows, int ld,
                                    int row0, int k0, int kmax, int tid, float (&reg)[IT][8])
{
    #pragma unroll
    for (int i = 0; i < IT; i++) {
        int idx = tid + i*256;
        #pragma unroll
        for (int j = 0; j < 8; j++) reg[i][j] = 0.f;
        if (idx < ROWS*2) {
            int r = idx >> 1, seg = idx & 1;
            int gr = row0 + r, gk = k0 + seg*8;
            if (gr < nrows && gk < kmax) {
                const float* p = P + (size_t)gr*ld + gk;
                if (gk + 8 <= kmax) {
                    float4 v0 = *(const float4*)p;
                    float4 v1 = *(const float4*)(p+4);
                    reg[i][0]=v0.x; reg[i][1]=v0.y; reg[i][2]=v0.z; reg[i][3]=v0.w;
                    reg[i][4]=v1.x; reg[i][5]=v1.y; reg[i][6]=v1.z; reg[i][7]=v1.w;
                } else {
                    #pragma unroll
                    for (int j = 0; j < 8; j++) if (gk + j < kmax) reg[i][j] = p[j];
                }
            }
        }
    }
}

template<int ROWS, int STR, int IT>
__device__ __forceinline__ void sts8(uint32_t* __restrict__ s, int tid, const float (&reg)[IT][8])
{
    #pragma unroll
    for (int i = 0; i < IT; i++) {
        int idx = tid + i*256;
        if (idx < ROWS*2) {
            int r = idx >> 1, seg = idx & 1;
            #pragma unroll
            for (int j = 0; j < 8; j++)
                s[(seg*8 + j)*STR + r] = f2tf32(reg[i][j]);
        }
    }
}

// non-transposed B: rows = k (BK=16), cols = BN
template<int BN>
__device__ __forceinline__ void ldB_n(const float* __restrict__ B, int N, int k0, int kmax,
                                      int col0, int tid, float (&reg)[8])
{
    #pragma unroll
    for (int j = 0; j < 8; j++) reg[j] = 0.f;
    int kk = tid >> 4, f0 = tid & 15;
    int gk = k0 + kk;
    if (gk < kmax) {
        #pragma unroll
        for (int it = 0; it < BN/64; it++) {
            int gc = col0 + (f0 + it*16)*4;
            if (gc < N) {
                const float* bp = B + (size_t)gk*N + gc;
                if (gc + 4 <= N) {
                    float4 v = *(const float4*)bp;
                    reg[it*4+0]=v.x; reg[it*4+1]=v.y; reg[it*4+2]=v.z; reg[it*4+3]=v.w;
                } else {
                    #pragma unroll
                    for (int j = 0; j < 4; j++) if (gc + j < N) reg[it*4+j] = bp[j];
                }
            }
        }
    }
}

template<int BN, int STR>
__device__ __forceinline__ void stsB_n(uint32_t* __restrict__ s, int tid, const float (&reg)[8])
{
    int kk = tid >> 4, f0 = tid & 15;
    #pragma unroll
    for (int it = 0; it < BN/64; it++) {
        uint4 v;
        v.x = f2tf32(reg[it*4+0]); v.y = f2tf32(reg[it*4+1]);
        v.z = f2tf32(reg[it*4+2]); v.w = f2tf32(reg[it*4+3]);
        *(uint4*)&s[kk*STR + (f0 + it*16)*4] = v;
    }
}

// ---------------- TF32 tensor-core GEMM ----------------
template<int BM, int BN, int WARPS_M, int WARPS_N, bool TRANSB, bool SPLITK>
__global__ void __launch_bounds__(256)
tf32_gemm(const float* __restrict__ A, const float* __restrict__ B,
          const float* __restrict__ bias, const float* __restrict__ resid,
          float* __restrict__ C, int M, int N, int K, float scale, int kchunk)
{
    constexpr int BK = 16;
    constexpr int ASTR = BM + 8, BSTR = BN + 8;
    constexpr int WM = BM / WARPS_M, WN = BN / WARPS_N;
    constexpr int MT = WM / 16, NT = WN / 8;
    constexpr int A_IT = (BM*2 + 255)/256;
    constexpr int B_IT = (BN*2 + 255)/256;

    __shared__ uint32_t sA[2*BK*ASTR];
    __shared__ uint32_t sB[2*BK*BSTR];

    int tid = threadIdx.x, lane = tid & 31, warp = tid >> 5;
    int wm = warp % WARPS_M, wn = warp / WARPS_M;
    int row0 = blockIdx.y * BM, col0 = blockIdx.x * BN;
    int lr = lane >> 2, lc = lane & 3;

    int kb = SPLITK ? blockIdx.z * kchunk : 0;
    int ke = SPLITK ? min(K, kb + kchunk) : K;
    int ntiles = (ke - kb + BK - 1) / BK;
    if (ntiles <= 0) return;

    float acc[MT][NT][4];
    #pragma unroll
    for (int i = 0; i < MT; i++)
        #pragma unroll
        for (int j = 0; j < NT; j++)
            #pragma unroll
            for (int e = 0; e < 4; e++) acc[i][j][e] = 0.f;

    float areg[A_IT][8];
    float bregT[B_IT][8];
    float bregN[8];

    ld8<BM, A_IT>(A, M, K, row0, kb, ke, tid, areg);
    if (TRANSB) ld8<BN, B_IT>(B, N, K, col0, kb, ke, tid, bregT);
    else        ldB_n<BN>(B, N, kb, ke, col0, tid, bregN);
    sts8<BM, ASTR, A_IT>(sA, tid, areg);
    if (TRANSB) sts8<BN, BSTR, B_IT>(sB, tid, bregT);
    else        stsB_n<BN, BSTR>(sB, tid, bregN);
    __syncthreads();

    int buf = 0;
    for (int t = 0; t < ntiles; t++) {
        bool more = (t + 1 < ntiles);
        if (more) {
            int k0 = kb + (t+1)*BK;
            ld8<BM, A_IT>(A, M, K, row0, k0, ke, tid, areg);
            if (TRANSB) ld8<BN, B_IT>(B, N, K, col0, k0, ke, tid, bregT);
            else        ldB_n<BN>(B, N, k0, ke, col0, tid, bregN);
        }
        const uint32_t* pA = sA + buf*BK*ASTR;
        const uint32_t* pB = sB + buf*BK*BSTR;
        #pragma unroll
        for (int ks = 0; ks < 2; ks++) {
            int kk = ks*8;
            uint32_t af[MT][4];
            #pragma unroll
            for (int i = 0; i < MT; i++) {
                int m0 = wm*WM + i*16;
                af[i][0] = pA[(kk+lc  )*ASTR + m0 + lr];
                af[i][1] = pA[(kk+lc  )*ASTR + m0 + lr + 8];
                af[i][2] = pA[(kk+lc+4)*ASTR + m0 + lr];
                af[i][3] = pA[(kk+lc+4)*ASTR + m0 + lr + 8];
            }
            uint32_t bf2[NT][2];
            #pragma unroll
            for (int j = 0; j < NT; j++) {
                int n0 = wn*WN + j*8;
                bf2[j][0] = pB[(kk+lc  )*BSTR + n0 + lr];
                bf2[j][1] = pB[(kk+lc+4)*BSTR + n0 + lr];
            }
            #pragma unroll
            for (int i = 0; i < MT; i++)
                #pragma unroll
                for (int j = 0; j < NT; j++)
                    mma_tf32(acc[i][j], af[i], bf2[j]);
        }
        if (more) {
            sts8<BM, ASTR, A_IT>(sA + (buf^1)*BK*ASTR, tid, areg);
            if (TRANSB) sts8<BN, BSTR, B_IT>(sB + (buf^1)*BK*BSTR, tid, bregT);
            else        stsB_n<BN, BSTR>(sB + (buf^1)*BK*BSTR, tid, bregN);
        }
        __syncthreads();
        buf ^= 1;
    }

    #pragma unroll
    for (int i = 0; i < MT; i++) {
        int r0 = row0 + wm*WM + i*16 + lr;
        #pragma unroll
        for (int j = 0; j < NT; j++) {
            int c0 = col0 + wn*WN + j*8 + 2*lc;
            #pragma unroll
            for (int e = 0; e < 4; e++) {
                int r = r0 + (e >> 1)*8;
                int c = c0 + (e & 1);
                if (r < M && c < N) {
                    float v = acc[i][j][e] * scale;
                    if (SPLITK) {
                        atomicAdd(&C[(size_t)r*N + c], v);
                    } else {
                        if (bias)  v += bias[c];
                        if (resid) v += resid[(size_t)r*N + c];
                        C[(size_t)r*N + c] = v;
                    }
                }
            }
        }
    }
}

static void launch_small(const float* A, const float* B, const float* bias, const float* resid,
                         float* C, int M, int N, int K, float scale, bool transB)
{
    dim3 grid((N + 63)/64, (M + 63)/64);
    if (transB) tf32_gemm<64,64,2,4,true ,false><<<grid,256>>>(A,B,bias,resid,C,M,N,K,scale,0);
    else        tf32_gemm<64,64,2,4,false,false><<<grid,256>>>(A,B,bias,resid,C,M,N,K,scale,0);
}

static void launch_big(const float* A, const float* B, const float* bias, const float* resid,
                       float* C, int M, int N, int K, float scale, bool transB)
{
    dim3 grid((N + 127)/128, (M + 127)/128);
    if (transB) tf32_gemm<128,128,2,4,true ,false><<<grid,256>>>(A,B,bias,resid,C,M,N,K,scale,0);
    else        tf32_gemm<128,128,2,4,false,false><<<grid,256>>>(A,B,bias,resid,C,M,N,K,scale,0);
}

static void launch_splitk(const float* A, const float* B, float* C, int M, int N, int K, int splits)
{
    int chunk = ((K/splits + 15)/16)*16;
    dim3 grid((N + 63)/64, (M + 63)/64, splits);
    tf32_gemm<64,64,2,4,false,true><<<grid,256>>>(A,B,nullptr,nullptr,C,M,N,K,1.f,chunk);
}

// ---------------- softmax over 4096-wide rows ----------------
__global__ void softmax_rows(float* __restrict__ S)
{
    __shared__ float buf[NPAIRS_MAP];
    __shared__ float red[256];
    int row = blockIdx.x, tid = threadIdx.x;
    float* r = S + (size_t)row * NPAIRS_MAP;
    float mx = -INFINITY;
    for (int i = tid; i < NPAIRS_MAP; i += 256) { float v = r[i]; buf[i] = v; mx = fmaxf(mx, v); }
    red[tid] = mx; __syncthreads();
    for (int o = 128; o; o >>= 1) { if (tid < o) red[tid] = fmaxf(red[tid], red[tid+o]); __syncthreads(); }
    mx = red[0]; __syncthreads();
    float sum = 0.f;
    for (int i = tid; i < NPAIRS_MAP; i += 256) { float e = expf(buf[i] - mx); buf[i] = e; sum += e; }
    red[tid] = sum; __syncthreads();
    for (int o = 128; o; o >>= 1) { if (tid < o) red[tid] += red[tid+o]; __syncthreads(); }
    float inv = 1.f / red[0];
    for (int i = tid; i < NPAIRS_MAP; i += 256) r[i] = buf[i] * inv;
}

// ---------------- scatter (last occurrence wins) ----------------
__global__ void scatter_winner(const int* __restrict__ com_idx, int* __restrict__ winner, int n)
{ int i = blockIdx.x*blockDim.x + threadIdx.x; if (i < n) atomicMax(&winner[com_idx[i]], i); }

__global__ void scatter_apply(const int* __restrict__ com_idx, const int* __restrict__ winner,
                              const float* __restrict__ fused, float* __restrict__ x, int n)
{
    int i = blockIdx.x*blockDim.x + threadIdx.x;
    int p = i / FEAT, c = i % FEAT;
    if (p >= n) return;
    int node = com_idx[p];
    if (winner[node] == p) x[(size_t)node*FEAT + c] = fused[(size_t)p*FEAT + c];
}

// ---------------- CSR build by dst ----------------
__global__ void hist_dst(const int* __restrict__ dst, int* __restrict__ deg, int E)
{ int e = blockIdx.x*blockDim.x + threadIdx.x; if (e < E) atomicAdd(&deg[dst[e]], 1); }

__global__ void scan_deg(const int* __restrict__ deg, int* __restrict__ off,
                         int* __restrict__ cur, int n)
{
    __shared__ int warp_sums[32];
    __shared__ int s_carry;
    int tid = threadIdx.x;
    int lane = tid & 31, w = tid >> 5;
    if (tid == 0) s_carry = 0;
    __syncthreads();
    for (int base = 0; base < n; base += 1024) {
        int i = base + tid;
        int v = (i < n) ? deg[i] : 0;
        int x = v;
        #pragma unroll
        for (int o = 1; o < 32; o <<= 1) { int y = __shfl_up_sync(~0u, x, o); if (lane >= o) x += y; }
        if (lane == 31) warp_sums[w] = x;
        __syncthreads();
        if (w == 0) {
            int t = warp_sums[lane];
            #pragma unroll
            for (int o = 1; o < 32; o <<= 1) { int y = __shfl_up_sync(~0u, t, o); if (lane >= o) t += y; }
            warp_sums[lane] = t;
        }
        __syncthreads();
        int warp_off = (w == 0) ? 0 : warp_sums[w-1];
        int incl = x + warp_off;
        int carry = s_carry;
        if (i < n) { off[i] = carry + incl - v; cur[i] = carry + incl - v; }
        __syncthreads();
        if (tid == 1023) s_carry = carry + incl;
        __syncthreads();
    }
    if (threadIdx.x == 0) off[n] = s_carry;
}

__global__ void scatter_csr(const int* __restrict__ src, const int* __restrict__ dst,
                            int* __restrict__ cur, int* __restrict__ csr, int E)
{
    int e = blockIdx.x*blockDim.x + threadIdx.x;
    if (e >= E) return;
    int pos = atomicAdd(&cur[dst[e]], 1);
    csr[pos] = src[e];
}

// ---------------- node scores for layer 1 ----------------
__global__ void node_e1(const float* __restrict__ h1, const float* __restrict__ a_src,
                        const float* __restrict__ a_dst, float* __restrict__ es, float* __restrict__ ed)
{
    int warp = (blockIdx.x*blockDim.x + threadIdx.x) >> 5;
    int lane = threadIdx.x & 31;
    int node = warp / HEADS, h = warp % HEADS;
    if (node >= NNODES) return;
    const float* hp = h1 + (size_t)node*H1DIM + h*HID;
    float s = 0.f, d = 0.f;
    #pragma unroll
    for (int c = lane; c < HID; c += 32) {
        float v = hp[c];
        s += v * a_src[h*HID + c];
        d += v * a_dst[h*HID + c];
    }
    #pragma unroll
    for (int o = 16; o; o >>= 1) { s += __shfl_xor_sync(~0u, s, o); d += __shfl_xor_sync(~0u, d, o); }
    if (!lane) { es[node*HEADS + h] = s; ed[node*HEADS + h] = d; }
}

// ---------------- mega-fused GAT1 aggregate + ELU + W2 GEMV + node_e2 ----------------
__global__ void __launch_bounds__(256)
gat1_fused(const int* __restrict__ off, const int* __restrict__ csr,
           const float* __restrict__ es, const float* __restrict__ ed,
           const float* __restrict__ h1, const float* __restrict__ b1,
           const float* __restrict__ W2, const float* __restrict__ as2,
           const float* __restrict__ ad2,
           float* __restrict__ h2, float* __restrict__ es2, float* __restrict__ ed2)
{
    __shared__ float wT[OUTC][H1DIM];     // W2 transposed: [10][384]
    __shared__ float sb1[H1DIM];
    int tid = threadIdx.x;
    for (int i = tid; i < OUTC*H1DIM; i += 256) {
        int k = i / OUTC, c = i % OUTC;
        wT[c][k] = W2[i];
    }
    for (int i = tid; i < H1DIM; i += 256) sb1[i] = b1[i];
    __syncthreads();

    int lane = tid & 31;
    int d = blockIdx.x*8 + (tid >> 5);
    if (d >= NNODES) return;

    int s0 = off[d], s1 = off[d+1];
    float edv[HEADS], eself[HEADS], m[HEADS];
    #pragma unroll
    for (int h = 0; h < HEADS; h++) {
        edv[h] = ed[d*HEADS + h];
        eself[h] = leaky(es[d*HEADS + h] + edv[h]);
        m[h] = eself[h];
    }
    for (int i = s0 + lane; i < s1; i += 32) {
        int s = csr[i];
        #pragma unroll
        for (int h = 0; h < HEADS; h++)
            m[h] = fmaxf(m[h], leaky(es[s*HEADS + h] + edv[h]));
    }
    #pragma unroll
    for (int h = 0; h < HEADS; h++)
        #pragma unroll
        for (int o = 16; o; o >>= 1) m[h] = fmaxf(m[h], __shfl_xor_sync(~0u, m[h], o));

    // phase B: weighted accumulation (self-loop first); head = float4 segment
    float den[HEADS];
    float4 acc[3];
    {
        const float4* hp = (const float4*)(h1 + (size_t)d*H1DIM);
        #pragma unroll
        for (int h = 0; h < HEADS; h++) den[h] = expf(eself[h] - m[h]);
        #pragma unroll
        for (int u = 0; u < 3; u++) {
            float4 hv = hp[lane + 32*u];
            float w = den[u];
            acc[u].x = hv.x*w; acc[u].y = hv.y*w; acc[u].z = hv.z*w; acc[u].w = hv.w*w;
        }
    }
    for (int i = s0; i < s1; i++) {
        int s = csr[i];                    // uniform across warp -> broadcast
        float w[HEADS];
        #pragma unroll
        for (int h = 0; h < HEADS; h++) {
            w[h] = expf(leaky(es[s*HEADS + h] + edv[h]) - m[h]);
            den[h] += w[h];
        }
        const float4* sp = (const float4*)(h1 + (size_t)s*H1DIM);
        #pragma unroll
        for (int u = 0; u < 3; u++) {
            float4 sv = sp[lane + 32*u];
            float ww = w[u];
            acc[u].x += ww*sv.x; acc[u].y += ww*sv.y; acc[u].z += ww*sv.z; acc[u].w += ww*sv.w;
        }
    }
    float inv[HEADS];
    #pragma unroll
    for (int h = 0; h < HEADS; h++) inv[h] = 1.f / (den[h] + 1e-16f);

    // bias + ELU
    const float4* b4 = (const float4*)sb1;
    float4 v[3];
    #pragma unroll
    for (int u = 0; u < 3; u++) {
        float4 bb = b4[lane + 32*u];
        float iv = inv[u];
        float xx;
        xx = acc[u].x*iv + bb.x; v[u].x = xx > 0.f ? xx : expm1f(xx);
        xx = acc[u].y*iv + bb.y; v[u].y = xx > 0.f ? xx : expm1f(xx);
        xx = acc[u].z*iv + bb.z; v[u].z = xx > 0.f ? xx : expm1f(xx);
        xx = acc[u].w*iv + bb.w; v[u].w = xx > 0.f ? xx : expm1f(xx);
    }
    // W2 GEMV
    float hh[OUTC];
    #pragma unroll
    for (int j = 0; j < OUTC; j++) {
        const float4* w4 = (const float4*)wT[j];
        float s = 0.f;
        #pragma unroll
        for (int u = 0; u < 3; u++) {
            float4 wv = w4[lane + 32*u];
            s += v[u].x*wv.x + v[u].y*wv.y + v[u].z*wv.z + v[u].w*wv.w;
        }
        #pragma unroll
        for (int o = 16; o; o >>= 1) s += __shfl_xor_sync(~0u, s, o);
        hh[j] = s;
    }
    if (lane == 0) {
        float s2 = 0.f, d2 = 0.f;
        #pragma unroll
        for (int j = 0; j < OUTC; j++) {
            h2[(size_t)d*OUTC + j] = hh[j];
            s2 += hh[j] * as2[j];
            d2 += hh[j] * ad2[j];
        }
        es2[d] = s2; ed2[d] = d2;
    }
}

// ---------------- fused GAT2 aggregate + bias ----------------
__global__ void __launch_bounds__(256)
gat2_fused(const int* __restrict__ off, const int* __restrict__ csr,
           const float* __restrict__ es, const float* __restrict__ ed,
           const float* __restrict__ h2, const float* __restrict__ b2,
           float* __restrict__ o2)
{
    int lane = threadIdx.x & 31;
    int d = blockIdx.x*8 + (threadIdx.x >> 5);
    if (d >= NNODES) return;
    int s0 = off[d], s1 = off[d+1];
    float edv = ed[d];
    float eself = leaky(es[d] + edv);
    float m = eself;
    for (int i = s0 + lane; i < s1; i += 32)
        m = fmaxf(m, leaky(es[csr[i]] + edv));
    #pragma unroll
    for (int o = 16; o; o >>= 1) m = fmaxf(m, __shfl_xor_sync(~0u, m, o));

    float den = 0.f;
    float acc[OUTC];
    #pragma unroll
    for (int c = 0; c < OUTC; c++) acc[c] = 0.f;
    for (int i = s0 + lane; i < s1; i += 32) {
        int s = csr[i];
        float w = expf(leaky(es[s] + edv) - m);
        den += w;
        const float* hp = h2 + (size_t)s*OUTC;
        #pragma unroll
        for (int c = 0; c < OUTC; c++) acc[c] += w * hp[c];
    }
    if (lane == 0) {
        float w = expf(eself - m);
        den += w;
        const float* hp = h2 + (size_t)d*OUTC;
        #pragma unroll
        for (int c = 0; c < OUTC; c++) acc[c] += w * hp[c];
    }
    #pragma unroll
    for (int o = 16; o; o >>= 1) {
        den += __shfl_xor_sync(~0u, den, o);
        #pragma unroll
        for (int c = 0; c < OUTC; c++) acc[c] += __shfl_xor_sync(~0u, acc[c], o);
    }
    if (lane == 0) {
        float inv = 1.f / (den + 1e-16f);
        #pragma unroll
        for (int c = 0; c < OUTC; c++) o2[(size_t)d*OUTC + c] = acc[c]*inv + b2[c];
    }
}

// ---------------- final pair scores ----------------
__global__ void pair_scores(const int* __restrict__ pair, const float* __restrict__ emb,
                            float* __restrict__ out, int n)
{
    int i = blockIdx.x*blockDim.x + threadIdx.x;
    if (i >= n) return;
    int a = pair[2*i], b = pair[2*i+1];
    const float2* ea = (const float2*)(emb + (size_t)a*OUTC);
    const float2* eb = (const float2*)(emb + (size_t)b*OUTC);
    float s = 0.f;
    #pragma unroll
    for (int c = 0; c < 5; c++) {
        float2 x = ea[c], y = eb[c];
        s += x.x*y.x + x.y*y.y;
    }
    out[i] = s;
}

// ---------------- host ----------------
extern "C" void kernel_launch(void* const* d_in, const int* in_sizes, int n_in,
                              void* d_out, int out_size)
{
    const float* fsub   = (const float*)d_in[0];
    const float* fcom   = (const float*)d_in[1];
    const float* x      = (const float*)d_in[2];
    const int*   comidx = (const int*)  d_in[3];
    const int*   edge   = (const int*)  d_in[4];
    const int*   pair   = (const int*)  d_in[5];
    const float* Wq = (const float*)d_in[6];  const float* bq = (const float*)d_in[7];
    const float* Wk = (const float*)d_in[8];  const float* bk = (const float*)d_in[9];
    const float* Wv = (const float*)d_in[10]; const float* bv = (const float*)d_in[11];
    const float* Wf = (const float*)d_in[12]; const float* bf = (const float*)d_in[13];
    const float* W1 = (const float*)d_in[14];
    const float* as1 = (const float*)d_in[15]; const float* ad1 = (const float*)d_in[16];
    const float* b1 = (const float*)d_in[17];
    const float* W2 = (const float*)d_in[18];
    const float* as2 = (const float*)d_in[19]; const float* ad2 = (const float*)d_in[20];
    const float* b2 = (const float*)d_in[21];
    float* out = (float*)d_out;

    const int E = in_sizes[4] / 2;
    const int* src = edge;
    const int* dst = edge + E;
    const int npairs = in_sizes[5] / 2;

    float *q, *k, *v, *S, *attv, *fused, *xw, *h1, *es1, *ed1;
    float *h2, *es2, *ed2, *o2;
    int *winner, *deg, *off, *cur, *csr;
    cudaGetSymbolAddress((void**)&q, g_q);       cudaGetSymbolAddress((void**)&k, g_k);
    cudaGetSymbolAddress((void**)&v, g_v);       cudaGetSymbolAddress((void**)&S, g_S);
    cudaGetSymbolAddress((void**)&attv, g_attv); cudaGetSymbolAddress((void**)&fused, g_fused);
    cudaGetSymbolAddress((void**)&xw, g_x);      cudaGetSymbolAddress((void**)&winner, g_winner);
    cudaGetSymbolAddress((void**)&h1, g_h1);
    cudaGetSymbolAddress((void**)&es1, g_es1);   cudaGetSymbolAddress((void**)&ed1, g_ed1);
    cudaGetSymbolAddress((void**)&h2, g_h2);
    cudaGetSymbolAddress((void**)&es2, g_es2);   cudaGetSymbolAddress((void**)&ed2, g_ed2);
    cudaGetSymbolAddress((void**)&o2, g_o2);
    cudaGetSymbolAddress((void**)&deg, g_deg);   cudaGetSymbolAddress((void**)&off, g_off);
    cudaGetSymbolAddress((void**)&cur, g_cur);   cudaGetSymbolAddress((void**)&csr, g_csr);

    const float inv_sqrt_feat = 0.057735026918962584f;   // 1/sqrt(300)

    // ---- CSR build ----
    cudaMemsetAsync(deg, 0, NNODES*sizeof(int), 0);
    hist_dst<<<(E + 255)/256, 256>>>(dst, deg, E);
    scan_deg<<<1, 1024>>>(deg, off, cur, NNODES);
    scatter_csr<<<(E + 255)/256, 256>>>(src, dst, cur, csr, E);

    // ---- cross-attention ----
    launch_small(fsub, Wq, bq, nullptr, q, NPAIRS_MAP, FEAT, FEAT, 1.f, false);
    launch_small(fcom, Wk, bk, nullptr, k, NPAIRS_MAP, FEAT, FEAT, 1.f, false);
    launch_small(fcom, Wv, bv, nullptr, v, NPAIRS_MAP, FEAT, FEAT, 1.f, false);
    launch_big(q, k, nullptr, nullptr, S, NPAIRS_MAP, NPAIRS_MAP, FEAT, inv_sqrt_feat, true);
    softmax_rows<<<NPAIRS_MAP, 256>>>(S);
    // attv = fsub + S@v  (split-K with atomic accumulate into the residual)
    cudaMemcpyAsync(attv, fsub, (size_t)NPAIRS_MAP*FEAT*sizeof(float), cudaMemcpyDeviceToDevice, 0);
    launch_splitk(S, v, attv, NPAIRS_MAP, FEAT, NPAIRS_MAP, 8);
    launch_small(attv, Wf, bf, nullptr, fused, NPAIRS_MAP, FEAT, FEAT, 1.f, false);

    // ---- write fused rows into x (last-occurrence-wins) ----
    cudaMemcpyAsync(xw, x, (size_t)NNODES*FEAT*sizeof(float), cudaMemcpyDeviceToDevice, 0);
    cudaMemsetAsync(winner, 0xFF, NNODES*sizeof(int), 0);
    scatter_winner<<<(NPAIRS_MAP + 255)/256, 256>>>(comidx, winner, NPAIRS_MAP);
    scatter_apply<<<(NPAIRS_MAP*FEAT + 255)/256, 256>>>(comidx, winner, fused, xw, NPAIRS_MAP);

    // ---- GAT layer 1 ----
    launch_big(xw, W1, nullptr, nullptr, h1, NNODES, H1DIM, FEAT, 1.f, false);
    node_e1<<<(NNODES*HEADS*32 + 255)/256, 256>>>(h1, as1, ad1, es1, ed1);
    gat1_fused<<<(NNODES + 7)/8, 256>>>(off, csr, es1, ed1, h1, b1, W2, as2, ad2,
                                        h2, es2, ed2);

    // ---- GAT layer 2 ----
    gat2_fused<<<(NNODES + 7)/8, 256>>>(off, csr, es2, ed2, h2, b2, o2);

    // ---- pair scores ----
    pair_scores<<<(npairs + 255)/256, 256>>>(pair, o2, out, npairs);
}

// round 6
// speedup vs baseline: 2.6170x; 1.0275x over previous
#include <cuda_runtime.h>
#include <math.h>
#include <stdint.h>

// ---------------- problem constants ----------------
#define NPAIRS_MAP 4096
#define NNODES     50000
#define MAXEDGES   524288
#define FEAT       300
#define HID        128
#define HEADS      3
#define OUTC       10
#define H1DIM      (HEADS*HID)   // 384

// ---------------- scratch ----------------
__device__ float g_q[NPAIRS_MAP*FEAT];
__device__ float g_k[NPAIRS_MAP*FEAT];
__device__ float g_v[NPAIRS_MAP*FEAT];
__device__ float g_S[(size_t)NPAIRS_MAP*NPAIRS_MAP];
__device__ float g_attv[NPAIRS_MAP*FEAT];
__device__ float g_fused[NPAIRS_MAP*FEAT];
__device__ float g_x[NNODES*FEAT];
__device__ int   g_winner[NNODES];
__device__ float g_h1[(size_t)NNODES*H1DIM];
__device__ float g_es1[NNODES*HEADS];
__device__ float g_ed1[NNODES*HEADS];
__device__ float g_h2[NNODES*OUTC];
__device__ float g_es2[NNODES];
__device__ float g_ed2[NNODES];
__device__ float g_o2[NNODES*OUTC];
__device__ int   g_deg[NNODES];
__device__ int   g_off[NNODES+1];
__device__ int   g_cur[NNODES];
__device__ int   g_csr[MAXEDGES];

// ---------------- helpers ----------------
__device__ __forceinline__ uint32_t f2tf32(float f) {
    uint32_t u; asm("cvt.rna.tf32.f32 %0, %1;" : "=r"(u) : "f"(f)); return u;
}

__device__ __forceinline__ void mma_tf32(float* c, const uint32_t* a, const uint32_t* b) {
    asm volatile("mma.sync.aligned.m16n8k8.row.col.f32.tf32.tf32.f32 "
        "{%0,%1,%2,%3}, {%4,%5,%6,%7}, {%8,%9}, {%0,%1,%2,%3};"
        : "+f"(c[0]), "+f"(c[1]), "+f"(c[2]), "+f"(c[3])
        : "r"(a[0]), "r"(a[1]), "r"(a[2]), "r"(a[3]), "r"(b[0]), "r"(b[1]));
}

__device__ __forceinline__ float leaky(float v) { return v > 0.f ? v : 0.2f*v; }

// ---------------- generic loaders ----------------
template<int ROWS, int IT>
__device__ __forceinline__ void ld8(const float* __restrict__ P, int nrows, int ld,
                                    int row0, int k0, int kmax, int tid, float (&reg)[IT][8])
{
    #pragma unroll
    for (int i = 0; i < IT; i++) {
        int idx = tid + i*256;
        #pragma unroll
        for (int j = 0; j < 8; j++) reg[i][j] = 0.f;
        if (idx < ROWS*2) {
            int r = idx >> 1, seg = idx & 1;
            int gr = row0 + r, gk = k0 + seg*8;
            if (gr < nrows && gk < kmax) {
                const float* p = P + (size_t)gr*ld + gk;
                if (gk + 8 <= kmax) {
                    float4 v0 = *(const float4*)p;
                    float4 v1 = *(const float4*)(p+4);
                    reg[i][0]=v0.x; reg[i][1]=v0.y; reg[i][2]=v0.z; reg[i][3]=v0.w;
                    reg[i][4]=v1.x; reg[i][5]=v1.y; reg[i][6]=v1.z; reg[i][7]=v1.w;
                } else {
                    #pragma unroll
                    for (int j = 0; j < 8; j++) if (gk + j < kmax) reg[i][j] = p[j];
                }
            }
        }
    }
}

template<int ROWS, int STR, int IT>
__device__ __forceinline__ void sts8(uint32_t* __restrict__ s, int tid, const float (&reg)[IT][8])
{
    #pragma unroll
    for (int i = 0; i < IT; i++) {
        int idx = tid + i*256;
        if (idx < ROWS*2) {
            int r = idx >> 1, seg = idx & 1;
            #pragma unroll
            for (int j = 0; j < 8; j++)
                s[(seg*8 + j)*STR + r] = f2tf32(reg[i][j]);
        }
    }
}

template<int BN>
__device__ __forceinline__ void ldB_n(const float* __restrict__ B, int N, int k0, int kmax,
                                      int col0, int tid, float (&reg)[8])
{
    #pragma unroll
    for (int j = 0; j < 8; j++) reg[j] = 0.f;
    int kk = tid >> 4, f0 = tid & 15;
    int gk = k0 + kk;
    if (gk < kmax) {
        #pragma unroll
        for (int it = 0; it < BN/64; it++) {
            int gc = col0 + (f0 + it*16)*4;
            if (gc < N) {
                const float* bp = B + (size_t)gk*N + gc;
                if (gc + 4 <= N) {
                    float4 v = *(const float4*)bp;
                    reg[it*4+0]=v.x; reg[it*4+1]=v.y; reg[it*4+2]=v.z; reg[it*4+3]=v.w;
                } else {
                    #pragma unroll
                    for (int j = 0; j < 4; j++) if (gc + j < N) reg[it*4+j] = bp[j];
                }
            }
        }
    }
}

template<int BN, int STR>
__device__ __forceinline__ void stsB_n(uint32_t* __restrict__ s, int tid, const float (&reg)[8])
{
    int kk = tid >> 4, f0 = tid & 15;
    #pragma unroll
    for (int it = 0; it < BN/64; it++) {
        uint4 v;
        v.x = f2tf32(reg[it*4+0]); v.y = f2tf32(reg[it*4+1]);
        v.z = f2tf32(reg[it*4+2]); v.w = f2tf32(reg[it*4+3]);
        *(uint4*)&s[kk*STR + (f0 + it*16)*4] = v;
    }
}

// ---------------- TF32 GEMM body (shared by all kernels) ----------------
template<int BM, int BN, int WARPS_M, int WARPS_N, bool TRANSB, bool SPLITK>
__device__ __forceinline__ void gemm_body(
          const float* __restrict__ A, const float* __restrict__ B,
          const float* __restrict__ bias, const float* __restrict__ resid,
          float* __restrict__ C, int M, int N, int K, float scale, int kchunk)
{
    constexpr int BK = 16;
    constexpr int ASTR = BM + 8, BSTR = BN + 8;
    constexpr int WM = BM / WARPS_M, WN = BN / WARPS_N;
    constexpr int MT = WM / 16, NT = WN / 8;
    constexpr int A_IT = (BM*2 + 255)/256;
    constexpr int B_IT = (BN*2 + 255)/256;

    __shared__ uint32_t sA[2*BK*ASTR];
    __shared__ uint32_t sB[2*BK*BSTR];

    int tid = threadIdx.x, lane = tid & 31, warp = tid >> 5;
    int wm = warp % WARPS_M, wn = warp / WARPS_M;
    int row0 = blockIdx.y * BM, col0 = blockIdx.x * BN;
    int lr = lane >> 2, lc = lane & 3;

    int kb = SPLITK ? blockIdx.z * kchunk : 0;
    int ke = SPLITK ? min(K, kb + kchunk) : K;
    int ntiles = (ke - kb + BK - 1) / BK;
    if (ntiles <= 0) return;

    float acc[MT][NT][4];
    #pragma unroll
    for (int i = 0; i < MT; i++)
        #pragma unroll
        for (int j = 0; j < NT; j++)
            #pragma unroll
            for (int e = 0; e < 4; e++) acc[i][j][e] = 0.f;

    float areg[A_IT][8];
    float bregT[B_IT][8];
    float bregN[8];

    ld8<BM, A_IT>(A, M, K, row0, kb, ke, tid, areg);
    if (TRANSB) ld8<BN, B_IT>(B, N, K, col0, kb, ke, tid, bregT);
    else        ldB_n<BN>(B, N, kb, ke, col0, tid, bregN);
    sts8<BM, ASTR, A_IT>(sA, tid, areg);
    if (TRANSB) sts8<BN, BSTR, B_IT>(sB, tid, bregT);
    else        stsB_n<BN, BSTR>(sB, tid, bregN);
    __syncthreads();

    int buf = 0;
    for (int t = 0; t < ntiles; t++) {
        bool more = (t + 1 < ntiles);
        if (more) {
            int k0 = kb + (t+1)*BK;
            ld8<BM, A_IT>(A, M, K, row0, k0, ke, tid, areg);
            if (TRANSB) ld8<BN, B_IT>(B, N, K, col0, k0, ke, tid, bregT);
            else        ldB_n<BN>(B, N, k0, ke, col0, tid, bregN);
        }
        const uint32_t* pA = sA + buf*BK*ASTR;
        const uint32_t* pB = sB + buf*BK*BSTR;
        #pragma unroll
        for (int ks = 0; ks < 2; ks++) {
            int kk = ks*8;
            uint32_t af[MT][4];
            #pragma unroll
            for (int i = 0; i < MT; i++) {
                int m0 = wm*WM + i*16;
                af[i][0] = pA[(kk+lc  )*ASTR + m0 + lr];
                af[i][1] = pA[(kk+lc  )*ASTR + m0 + lr + 8];
                af[i][2] = pA[(kk+lc+4)*ASTR + m0 + lr];
                af[i][3] = pA[(kk+lc+4)*ASTR + m0 + lr + 8];
            }
            uint32_t bf2[NT][2];
            #pragma unroll
            for (int j = 0; j < NT; j++) {
                int n0 = wn*WN + j*8;
                bf2[j][0] = pB[(kk+lc  )*BSTR + n0 + lr];
                bf2[j][1] = pB[(kk+lc+4)*BSTR + n0 + lr];
            }
            #pragma unroll
            for (int i = 0; i < MT; i++)
                #pragma unroll
                for (int j = 0; j < NT; j++)
                    mma_tf32(acc[i][j], af[i], bf2[j]);
        }
        if (more) {
            sts8<BM, ASTR, A_IT>(sA + (buf^1)*BK*ASTR, tid, areg);
            if (TRANSB) sts8<BN, BSTR, B_IT>(sB + (buf^1)*BK*BSTR, tid, bregT);
            else        stsB_n<BN, BSTR>(sB + (buf^1)*BK*BSTR, tid, bregN);
        }
        __syncthreads();
        buf ^= 1;
    }

    #pragma unroll
    for (int i = 0; i < MT; i++) {
        int r0 = row0 + wm*WM + i*16 + lr;
        #pragma unroll
        for (int j = 0; j < NT; j++) {
            int c0 = col0 + wn*WN + j*8 + 2*lc;
            #pragma unroll
            for (int e = 0; e < 4; e++) {
                int r = r0 + (e >> 1)*8;
                int c = c0 + (e & 1);
                if (r < M && c < N) {
                    float v = acc[i][j][e] * scale;
                    if (SPLITK) {
                        atomicAdd(&C[(size_t)r*N + c], v);
                    } else {
                        if (bias)  v += bias[c];
                        if (resid) v += resid[(size_t)r*N + c];
                        C[(size_t)r*N + c] = v;
                    }
                }
            }
        }
    }
}

template<int BM, int BN, int WARPS_M, int WARPS_N, bool TRANSB, bool SPLITK>
__global__ void __launch_bounds__(256)
tf32_gemm(const float* __restrict__ A, const float* __restrict__ B,
          const float* __restrict__ bias, const float* __restrict__ resid,
          float* __restrict__ C, int M, int N, int K, float scale, int kchunk)
{
    gemm_body<BM,BN,WARPS_M,WARPS_N,TRANSB,SPLITK>(A,B,bias,resid,C,M,N,K,scale,kchunk);
}

// batched QKV: z selects (A,B,bias,C)
__global__ void __launch_bounds__(256)
tf32_gemm_qkv(const float* __restrict__ fsub, const float* __restrict__ fcom,
              const float* __restrict__ Wq, const float* __restrict__ bq,
              const float* __restrict__ Wk, const float* __restrict__ bk,
              const float* __restrict__ Wv, const float* __restrict__ bv,
              float* __restrict__ q, float* __restrict__ k, float* __restrict__ v)
{
    const float* A; const float* B; const float* bias; float* C;
    if (blockIdx.z == 0)      { A = fsub; B = Wq; bias = bq; C = q; }
    else if (blockIdx.z == 1) { A = fcom; B = Wk; bias = bk; C = k; }
    else                      { A = fcom; B = Wv; bias = bv; C = v; }
    gemm_body<64,64,2,4,false,false>(A, B, bias, nullptr, C,
                                     NPAIRS_MAP, FEAT, FEAT, 1.f, 0);
}

static void launch_small(const float* A, const float* B, const float* bias, const float* resid,
                         float* C, int M, int N, int K, float scale, bool transB)
{
    dim3 grid((N + 63)/64, (M + 63)/64);
    if (transB) tf32_gemm<64,64,2,4,true ,false><<<grid,256>>>(A,B,bias,resid,C,M,N,K,scale,0);
    else        tf32_gemm<64,64,2,4,false,false><<<grid,256>>>(A,B,bias,resid,C,M,N,K,scale,0);
}

static void launch_big(const float* A, const float* B, const float* bias, const float* resid,
                       float* C, int M, int N, int K, float scale, bool transB)
{
    dim3 grid((N + 127)/128, (M + 127)/128);
    if (transB) tf32_gemm<128,128,2,4,true ,false><<<grid,256>>>(A,B,bias,resid,C,M,N,K,scale,0);
    else        tf32_gemm<128,128,2,4,false,false><<<grid,256>>>(A,B,bias,resid,C,M,N,K,scale,0);
}

static void launch_splitk(const float* A, const float* B, float* C, int M, int N, int K, int splits)
{
    int chunk = ((K/splits + 15)/16)*16;
    dim3 grid((N + 63)/64, (M + 63)/64, splits);
    tf32_gemm<64,64,2,4,false,true><<<grid,256>>>(A,B,nullptr,nullptr,C,M,N,K,1.f,chunk);
}

// ---------------- softmax over 4096-wide rows ----------------
__global__ void softmax_rows(float* __restrict__ S)
{
    __shared__ float buf[NPAIRS_MAP];
    __shared__ float red[256];
    int row = blockIdx.x, tid = threadIdx.x;
    float* r = S + (size_t)row * NPAIRS_MAP;
    float mx = -INFINITY;
    for (int i = tid; i < NPAIRS_MAP; i += 256) { float v = r[i]; buf[i] = v; mx = fmaxf(mx, v); }
    red[tid] = mx; __syncthreads();
    for (int o = 128; o; o >>= 1) { if (tid < o) red[tid] = fmaxf(red[tid], red[tid+o]); __syncthreads(); }
    mx = red[0]; __syncthreads();
    float sum = 0.f;
    for (int i = tid; i < NPAIRS_MAP; i += 256) { float e = expf(buf[i] - mx); buf[i] = e; sum += e; }
    red[tid] = sum; __syncthreads();
    for (int o = 128; o; o >>= 1) { if (tid < o) red[tid] += red[tid+o]; __syncthreads(); }
    float inv = 1.f / red[0];
    for (int i = tid; i < NPAIRS_MAP; i += 256) r[i] = buf[i] * inv;
}

// ---------------- scatter (last occurrence wins) ----------------
__global__ void scatter_winner(const int* __restrict__ com_idx, int* __restrict__ winner, int n)
{ int i = blockIdx.x*blockDim.x + threadIdx.x; if (i < n) atomicMax(&winner[com_idx[i]], i); }

__global__ void scatter_apply(const int* __restrict__ com_idx, const int* __restrict__ winner,
                              const float* __restrict__ fused, float* __restrict__ x, int n)
{
    int i = blockIdx.x*blockDim.x + threadIdx.x;
    int p = i / FEAT, c = i % FEAT;
    if (p >= n) return;
    int node = com_idx[p];
    if (winner[node] == p) x[(size_t)node*FEAT + c] = fused[(size_t)p*FEAT + c];
}

// ---------------- CSR build by dst ----------------
__global__ void hist_dst(const int* __restrict__ dst, int* __restrict__ deg, int E)
{ int e = blockIdx.x*blockDim.x + threadIdx.x; if (e < E) atomicAdd(&deg[dst[e]], 1); }

__global__ void scan_deg(const int* __restrict__ deg, int* __restrict__ off,
                         int* __restrict__ cur, int n)
{
    __shared__ int warp_sums[32];
    __shared__ int s_carry;
    int tid = threadIdx.x;
    int lane = tid & 31, w = tid >> 5;
    if (tid == 0) s_carry = 0;
    __syncthreads();
    for (int base = 0; base < n; base += 1024) {
        int i = base + tid;
        int v = (i < n) ? deg[i] : 0;
        int x = v;
        #pragma unroll
        for (int o = 1; o < 32; o <<= 1) { int y = __shfl_up_sync(~0u, x, o); if (lane >= o) x += y; }
        if (lane == 31) warp_sums[w] = x;
        __syncthreads();
        if (w == 0) {
            int t = warp_sums[lane];
            #pragma unroll
            for (int o = 1; o < 32; o <<= 1) { int y = __shfl_up_sync(~0u, t, o); if (lane >= o) t += y; }
            warp_sums[lane] = t;
        }
        __syncthreads();
        int warp_off = (w == 0) ? 0 : warp_sums[w-1];
        int incl = x + warp_off;
        int carry = s_carry;
        if (i < n) { off[i] = carry + incl - v; cur[i] = carry + incl - v; }
        __syncthreads();
        if (tid == 1023) s_carry = carry + incl;
        __syncthreads();
    }
    if (threadIdx.x == 0) off[n] = s_carry;
}

__global__ void scatter_csr(const int* __restrict__ src, const int* __restrict__ dst,
                            int* __restrict__ cur, int* __restrict__ csr, int E)
{
    int e = blockIdx.x*blockDim.x + threadIdx.x;
    if (e >= E) return;
    int pos = atomicAdd(&cur[dst[e]], 1);
    csr[pos] = src[e];
}

// ---------------- node scores for layer 1 ----------------
__global__ void node_e1(const float* __restrict__ h1, const float* __restrict__ a_src,
                        const float* __restrict__ a_dst, float* __restrict__ es, float* __restrict__ ed)
{
    int warp = (blockIdx.x*blockDim.x + threadIdx.x) >> 5;
    int lane = threadIdx.x & 31;
    int node = warp / HEADS, h = warp % HEADS;
    if (node >= NNODES) return;
    const float* hp = h1 + (size_t)node*H1DIM + h*HID;
    float s = 0.f, d = 0.f;
    #pragma unroll
    for (int c = lane; c < HID; c += 32) {
        float v = hp[c];
        s += v * a_src[h*HID + c];
        d += v * a_dst[h*HID + c];
    }
    #pragma unroll
    for (int o = 16; o; o >>= 1) { s += __shfl_xor_sync(~0u, s, o); d += __shfl_xor_sync(~0u, d, o); }
    if (!lane) { es[node*HEADS + h] = s; ed[node*HEADS + h] = d; }
}

// ---------------- mega-fused GAT1 aggregate + ELU + W2 GEMV + node_e2 ----------------
__global__ void __launch_bounds__(256)
gat1_fused(const int* __restrict__ off, const int* __restrict__ csr,
           const float* __restrict__ es, const float* __restrict__ ed,
           const float* __restrict__ h1, const float* __restrict__ b1,
           const float* __restrict__ W2, const float* __restrict__ as2,
           const float* __restrict__ ad2,
           float* __restrict__ h2, float* __restrict__ es2, float* __restrict__ ed2)
{
    __shared__ float wT[OUTC][H1DIM];
    __shared__ float sb1[H1DIM];
    int tid = threadIdx.x;
    for (int i = tid; i < OUTC*H1DIM; i += 256) {
        int k = i / OUTC, c = i % OUTC;
        wT[c][k] = W2[i];
    }
    for (int i = tid; i < H1DIM; i += 256) sb1[i] = b1[i];
    __syncthreads();

    int lane = tid & 31;
    int d = blockIdx.x*8 + (tid >> 5);
    if (d >= NNODES) return;

    int s0 = off[d], s1 = off[d+1];
    float edv[HEADS], eself[HEADS], m[HEADS];
    #pragma unroll
    for (int h = 0; h < HEADS; h++) {
        edv[h] = ed[d*HEADS + h];
        eself[h] = leaky(es[d*HEADS + h] + edv[h]);
        m[h] = eself[h];
    }
    // phase A: max, lane-parallel
    for (int i = s0 + lane; i < s1; i += 32) {
        int s = csr[i];
        #pragma unroll
        for (int h = 0; h < HEADS; h++)
            m[h] = fmaxf(m[h], leaky(es[s*HEADS + h] + edv[h]));
    }
    #pragma unroll
    for (int h = 0; h < HEADS; h++)
        #pragma unroll
        for (int o = 16; o; o >>= 1) m[h] = fmaxf(m[h], __shfl_xor_sync(~0u, m[h], o));

    // phase B: lane-parallel weights (chunks of 32) + shfl-broadcast accumulation
    float denp[HEADS];                 // per-lane partial denominators
    #pragma unroll
    for (int h = 0; h < HEADS; h++) denp[h] = 0.f;
    float4 acc[3];
    {   // self-loop contribution
        const float4* hp = (const float4*)(h1 + (size_t)d*H1DIM);
        float wself[HEADS];
        #pragma unroll
        for (int h = 0; h < HEADS; h++) wself[h] = expf(eself[h] - m[h]);
        #pragma unroll
        for (int u = 0; u < 3; u++) {
            float4 hv = hp[lane + 32*u];
            float w = wself[u];
            acc[u].x = hv.x*w; acc[u].y = hv.y*w; acc[u].z = hv.z*w; acc[u].w = hv.w*w;
        }
        if (lane == 0)
            #pragma unroll
            for (int h = 0; h < HEADS; h++) denp[h] += wself[h];
    }
    for (int base = s0; base < s1; base += 32) {
        int i = base + lane;
        int sidx = 0;
        float w[HEADS];
        #pragma unroll
        for (int h = 0; h < HEADS; h++) w[h] = 0.f;
        if (i < s1) {
            sidx = csr[i];
            #pragma unroll
            for (int h = 0; h < HEADS; h++) {
                w[h] = expf(leaky(es[sidx*HEADS + h] + edv[h]) - m[h]);
                denp[h] += w[h];
            }
        }
        int cnt = min(32, s1 - base);
        #pragma unroll 4
        for (int j = 0; j < cnt; j++) {
            int s  = __shfl_sync(~0u, sidx, j);
            float w0 = __shfl_sync(~0u, w[0], j);
            float w1 = __shfl_sync(~0u, w[1], j);
            float w2 = __shfl_sync(~0u, w[2], j);
            const float4* sp = (const float4*)(h1 + (size_t)s*H1DIM);
            float4 v0 = sp[lane], v1 = sp[lane+32], v2 = sp[lane+64];
            acc[0].x += w0*v0.x; acc[0].y += w0*v0.y; acc[0].z += w0*v0.z; acc[0].w += w0*v0.w;
            acc[1].x += w1*v1.x; acc[1].y += w1*v1.y; acc[1].z += w1*v1.z; acc[1].w += w1*v1.w;
            acc[2].x += w2*v2.x; acc[2].y += w2*v2.y; acc[2].z += w2*v2.z; acc[2].w += w2*v2.w;
        }
    }
    // reduce denominators across lanes
    #pragma unroll
    for (int h = 0; h < HEADS; h++)
        #pragma unroll
        for (int o = 16; o; o >>= 1) denp[h] += __shfl_xor_sync(~0u, denp[h], o);
    float inv[HEADS];
    #pragma unroll
    for (int h = 0; h < HEADS; h++) inv[h] = 1.f / (denp[h] + 1e-16f);

    // bias + ELU
    const float4* b4 = (const float4*)sb1;
    float4 v[3];
    #pragma unroll
    for (int u = 0; u < 3; u++) {
        float4 bb = b4[lane + 32*u];
        float iv = inv[u];
        float xx;
        xx = acc[u].x*iv + bb.x; v[u].x = xx > 0.f ? xx : expm1f(xx);
        xx = acc[u].y*iv + bb.y; v[u].y = xx > 0.f ? xx : expm1f(xx);
        xx = acc[u].z*iv + bb.z; v[u].z = xx > 0.f ? xx : expm1f(xx);
        xx = acc[u].w*iv + bb.w; v[u].w = xx > 0.f ? xx : expm1f(xx);
    }
    // W2 GEMV
    float hh[OUTC];
    #pragma unroll
    for (int j = 0; j < OUTC; j++) {
        const float4* w4 = (const float4*)wT[j];
        float s = 0.f;
        #pragma unroll
        for (int u = 0; u < 3; u++) {
            float4 wv = w4[lane + 32*u];
            s += v[u].x*wv.x + v[u].y*wv.y + v[u].z*wv.z + v[u].w*wv.w;
        }
        #pragma unroll
        for (int o = 16; o; o >>= 1) s += __shfl_xor_sync(~0u, s, o);
        hh[j] = s;
    }
    if (lane == 0) {
        float s2 = 0.f, d2 = 0.f;
        #pragma unroll
        for (int j = 0; j < OUTC; j++) {
            h2[(size_t)d*OUTC + j] = hh[j];
            s2 += hh[j] * as2[j];
            d2 += hh[j] * ad2[j];
        }
        es2[d] = s2; ed2[d] = d2;
    }
}

// ---------------- fused GAT2 aggregate + bias ----------------
__global__ void __launch_bounds__(256)
gat2_fused(const int* __restrict__ off, const int* __restrict__ csr,
           const float* __restrict__ es, const float* __restrict__ ed,
           const float* __restrict__ h2, const float* __restrict__ b2,
           float* __restrict__ o2)
{
    int lane = threadIdx.x & 31;
    int d = blockIdx.x*8 + (threadIdx.x >> 5);
    if (d >= NNODES) return;
    int s0 = off[d], s1 = off[d+1];
    float edv = ed[d];
    float eself = leaky(es[d] + edv);
    float m = eself;
    for (int i = s0 + lane; i < s1; i += 32)
        m = fmaxf(m, leaky(es[csr[i]] + edv));
    #pragma unroll
    for (int o = 16; o; o >>= 1) m = fmaxf(m, __shfl_xor_sync(~0u, m, o));

    float den = 0.f;
    float acc[OUTC];
    #pragma unroll
    for (int c = 0; c < OUTC; c++) acc[c] = 0.f;
    for (int i = s0 + lane; i < s1; i += 32) {
        int s = csr[i];
        float w = expf(leaky(es[s] + edv) - m);
        den += w;
        const float* hp = h2 + (size_t)s*OUTC;
        #pragma unroll
        for (int c = 0; c < OUTC; c++) acc[c] += w * hp[c];
    }
    if (lane == 0) {
        float w = expf(eself - m);
        den += w;
        const float* hp = h2 + (size_t)d*OUTC;
        #pragma unroll
        for (int c = 0; c < OUTC; c++) acc[c] += w * hp[c];
    }
    #pragma unroll
    for (int o = 16; o; o >>= 1) {
        den += __shfl_xor_sync(~0u, den, o);
        #pragma unroll
        for (int c = 0; c < OUTC; c++) acc[c] += __shfl_xor_sync(~0u, acc[c], o);
    }
    if (lane == 0) {
        float inv = 1.f / (den + 1e-16f);
        #pragma unroll
        for (int c = 0; c < OUTC; c++) o2[(size_t)d*OUTC + c] = acc[c]*inv + b2[c];
    }
}

// ---------------- final pair scores ----------------
__global__ void pair_scores(const int* __restrict__ pair, const float* __restrict__ emb,
                            float* __restrict__ out, int n)
{
    int i = blockIdx.x*blockDim.x + threadIdx.x;
    if (i >= n) return;
    int a = pair[2*i], b = pair[2*i+1];
    const float2* ea = (const float2*)(emb + (size_t)a*OUTC);
    const float2* eb = (const float2*)(emb + (size_t)b*OUTC);
    float s = 0.f;
    #pragma unroll
    for (int c = 0; c < 5; c++) {
        float2 x = ea[c], y = eb[c];
        s += x.x*y.x + x.y*y.y;
    }
    out[i] = s;
}

// ---------------- host ----------------
extern "C" void kernel_launch(void* const* d_in, const int* in_sizes, int n_in,
                              void* d_out, int out_size)
{
    const float* fsub   = (const float*)d_in[0];
    const float* fcom   = (const float*)d_in[1];
    const float* x      = (const float*)d_in[2];
    const int*   comidx = (const int*)  d_in[3];
    const int*   edge   = (const int*)  d_in[4];
    const int*   pair   = (const int*)  d_in[5];
    const float* Wq = (const float*)d_in[6];  const float* bq = (const float*)d_in[7];
    const float* Wk = (const float*)d_in[8];  const float* bk = (const float*)d_in[9];
    const float* Wv = (const float*)d_in[10]; const float* bv = (const float*)d_in[11];
    const float* Wf = (const float*)d_in[12]; const float* bf = (const float*)d_in[13];
    const float* W1 = (const float*)d_in[14];
    const float* as1 = (const float*)d_in[15]; const float* ad1 = (const float*)d_in[16];
    const float* b1 = (const float*)d_in[17];
    const float* W2 = (const float*)d_in[18];
    const float* as2 = (const float*)d_in[19]; const float* ad2 = (const float*)d_in[20];
    const float* b2 = (const float*)d_in[21];
    float* out = (float*)d_out;

    const int E = in_sizes[4] / 2;
    const int* src = edge;
    const int* dst = edge + E;
    const int npairs = in_sizes[5] / 2;

    float *q, *k, *v, *S, *attv, *fused, *xw, *h1, *es1, *ed1;
    float *h2, *es2, *ed2, *o2;
    int *winner, *deg, *off, *cur, *csr;
    cudaGetSymbolAddress((void**)&q, g_q);       cudaGetSymbolAddress((void**)&k, g_k);
    cudaGetSymbolAddress((void**)&v, g_v);       cudaGetSymbolAddress((void**)&S, g_S);
    cudaGetSymbolAddress((void**)&attv, g_attv); cudaGetSymbolAddress((void**)&fused, g_fused);
    cudaGetSymbolAddress((void**)&xw, g_x);      cudaGetSymbolAddress((void**)&winner, g_winner);
    cudaGetSymbolAddress((void**)&h1, g_h1);
    cudaGetSymbolAddress((void**)&es1, g_es1);   cudaGetSymbolAddress((void**)&ed1, g_ed1);
    cudaGetSymbolAddress((void**)&h2, g_h2);
    cudaGetSymbolAddress((void**)&es2, g_es2);   cudaGetSymbolAddress((void**)&ed2, g_ed2);
    cudaGetSymbolAddress((void**)&o2, g_o2);
    cudaGetSymbolAddress((void**)&deg, g_deg);   cudaGetSymbolAddress((void**)&off, g_off);
    cudaGetSymbolAddress((void**)&cur, g_cur);   cudaGetSymbolAddress((void**)&csr, g_csr);

    const float inv_sqrt_feat = 0.057735026918962584f;   // 1/sqrt(300)

    // ---- CSR build ----
    cudaMemsetAsync(deg, 0, NNODES*sizeof(int), 0);
    hist_dst<<<(E + 255)/256, 256>>>(dst, deg, E);
    scan_deg<<<1, 1024>>>(deg, off, cur, NNODES);
    scatter_csr<<<(E + 255)/256, 256>>>(src, dst, cur, csr, E);

    // ---- cross-attention ----
    {   // batched Q, K, V in one launch
        dim3 grid((FEAT + 63)/64, (NPAIRS_MAP + 63)/64, 3);
        tf32_gemm_qkv<<<grid, 256>>>(fsub, fcom, Wq, bq, Wk, bk, Wv, bv, q, k, v);
    }
    launch_big(q, k, nullptr, nullptr, S, NPAIRS_MAP, NPAIRS_MAP, FEAT, inv_sqrt_feat, true);
    softmax_rows<<<NPAIRS_MAP, 256>>>(S);
    cudaMemcpyAsync(attv, fsub, (size_t)NPAIRS_MAP*FEAT*sizeof(float), cudaMemcpyDeviceToDevice, 0);
    launch_splitk(S, v, attv, NPAIRS_MAP, FEAT, NPAIRS_MAP, 8);
    launch_small(attv, Wf, bf, nullptr, fused, NPAIRS_MAP, FEAT, FEAT, 1.f, false);

    // ---- write fused rows into x (last-occurrence-wins) ----
    cudaMemcpyAsync(xw, x, (size_t)NNODES*FEAT*sizeof(float), cudaMemcpyDeviceToDevice, 0);
    cudaMemsetAsync(winner, 0xFF, NNODES*sizeof(int), 0);
    scatter_winner<<<(NPAIRS_MAP + 255)/256, 256>>>(comidx, winner, NPAIRS_MAP);
    scatter_apply<<<(NPAIRS_MAP*FEAT + 255)/256, 256>>>(comidx, winner, fused, xw, NPAIRS_MAP);

    // ---- GAT layer 1 ----
    launch_big(xw, W1, nullptr, nullptr, h1, NNODES, H1DIM, FEAT, 1.f, false);
    node_e1<<<(NNODES*HEADS*32 + 255)/256, 256>>>(h1, as1, ad1, es1, ed1);
    gat1_fused<<<(NNODES + 7)/8, 256>>>(off, csr, es1, ed1, h1, b1, W2, as2, ad2,
                                        h2, es2, ed2);

    // ---- GAT layer 2 ----
    gat2_fused<<<(NNODES + 7)/8, 256>>>(off, csr, es2, ed2, h2, b2, o2);

    // ---- pair scores ----
    pair_scores<<<(npairs + 255)/256, 256>>>(pair, o2, out, npairs);
}

// round 7
// speedup vs baseline: 2.8060x; 1.0722x over previous
#include <cuda_runtime.h>
#include <math.h>
#include <stdint.h>

// ---------------- problem constants ----------------
#define NPAIRS_MAP 4096
#define NNODES     50000
#define MAXEDGES   524288
#define FEAT       300
#define HID        128
#define HEADS      3
#define OUTC       10
#define H1DIM      (HEADS*HID)   // 384

// ---------------- scratch ----------------
__device__ float g_q[NPAIRS_MAP*FEAT];
__device__ float g_k[NPAIRS_MAP*FEAT];
__device__ float g_v[NPAIRS_MAP*FEAT];
__device__ float g_S[(size_t)NPAIRS_MAP*NPAIRS_MAP];
__device__ float g_attv[NPAIRS_MAP*FEAT];
__device__ float g_fused[NPAIRS_MAP*FEAT];
__device__ unsigned long long g_rowptr[NNODES];
__device__ int   g_winner[NNODES];
__device__ float g_h1[(size_t)NNODES*H1DIM];
__device__ float g_es1[NNODES*HEADS];
__device__ float g_ed1[NNODES*HEADS];
__device__ float g_h2[NNODES*OUTC];
__device__ float g_es2[NNODES];
__device__ float g_ed2[NNODES];
__device__ float g_o2[NNODES*OUTC];
__device__ int   g_deg[NNODES];
__device__ int   g_off[NNODES+1];
__device__ int   g_cur[NNODES];
__device__ int   g_csr[MAXEDGES];

// ---------------- helpers ----------------
__device__ __forceinline__ uint32_t f2tf32(float f) {
    uint32_t u; asm("cvt.rna.tf32.f32 %0, %1;" : "=r"(u) : "f"(f)); return u;
}

__device__ __forceinline__ void mma_tf32(float* c, const uint32_t* a, const uint32_t* b) {
    asm volatile("mma.sync.aligned.m16n8k8.row.col.f32.tf32.tf32.f32 "
        "{%0,%1,%2,%3}, {%4,%5,%6,%7}, {%8,%9}, {%0,%1,%2,%3};"
        : "+f"(c[0]), "+f"(c[1]), "+f"(c[2]), "+f"(c[3])
        : "r"(a[0]), "r"(a[1]), "r"(a[2]), "r"(a[3]), "r"(b[0]), "r"(b[1]));
}

__device__ __forceinline__ float leaky(float v) { return v > 0.f ? v : 0.2f*v; }

// ---------------- generic loaders ----------------
template<int ROWS, int IT, bool IND>
__device__ __forceinline__ void ld8(const float* __restrict__ A,
                                    const unsigned long long* __restrict__ rowp,
                                    int nrows, int ld,
                                    int row0, int k0, int kmax, int tid, float (&reg)[IT][8])
{
    #pragma unroll
    for (int i = 0; i < IT; i++) {
        int idx = tid + i*256;
        #pragma unroll
        for (int j = 0; j < 8; j++) reg[i][j] = 0.f;
        if (idx < ROWS*2) {
            int r = idx >> 1, seg = idx & 1;
            int gr = row0 + r, gk = k0 + seg*8;
            if (gr < nrows && gk < kmax) {
                const float* base = IND ? (const float*)rowp[gr] : A + (size_t)gr*ld;
                const float* p = base + gk;
                if (gk + 8 <= kmax) {
                    float4 v0 = *(const float4*)p;
                    float4 v1 = *(const float4*)(p+4);
                    reg[i][0]=v0.x; reg[i][1]=v0.y; reg[i][2]=v0.z; reg[i][3]=v0.w;
                    reg[i][4]=v1.x; reg[i][5]=v1.y; reg[i][6]=v1.z; reg[i][7]=v1.w;
                } else {
                    #pragma unroll
                    for (int j = 0; j < 8; j++) if (gk + j < kmax) reg[i][j] = p[j];
                }
            }
        }
    }
}

template<int ROWS, int STR, int IT>
__device__ __forceinline__ void sts8(uint32_t* __restrict__ s, int tid, const float (&reg)[IT][8])
{
    #pragma unroll
    for (int i = 0; i < IT; i++) {
        int idx = tid + i*256;
        if (idx < ROWS*2) {
            int r = idx >> 1, seg = idx & 1;
            #pragma unroll
            for (int j = 0; j < 8; j++)
                s[(seg*8 + j)*STR + r] = f2tf32(reg[i][j]);
        }
    }
}

template<int BN>
__device__ __forceinline__ void ldB_n(const float* __restrict__ B, int N, int k0, int kmax,
                                      int col0, int tid, float (&reg)[8])
{
    #pragma unroll
    for (int j = 0; j < 8; j++) reg[j] = 0.f;
    int kk = tid >> 4, f0 = tid & 15;
    int gk = k0 + kk;
    if (gk < kmax) {
        #pragma unroll
        for (int it = 0; it < BN/64; it++) {
            int gc = col0 + (f0 + it*16)*4;
            if (gc < N) {
                const float* bp = B + (size_t)gk*N + gc;
                if (gc + 4 <= N) {
                    float4 v = *(const float4*)bp;
                    reg[it*4+0]=v.x; reg[it*4+1]=v.y; reg[it*4+2]=v.z; reg[it*4+3]=v.w;
                } else {
                    #pragma unroll
                    for (int j = 0; j < 4; j++) if (gc + j < N) reg[it*4+j] = bp[j];
                }
            }
        }
    }
}

template<int BN, int STR>
__device__ __forceinline__ void stsB_n(uint32_t* __restrict__ s, int tid, const float (&reg)[8])
{
    int kk = tid >> 4, f0 = tid & 15;
    #pragma unroll
    for (int it = 0; it < BN/64; it++) {
        uint4 v;
        v.x = f2tf32(reg[it*4+0]); v.y = f2tf32(reg[it*4+1]);
        v.z = f2tf32(reg[it*4+2]); v.w = f2tf32(reg[it*4+3]);
        *(uint4*)&s[kk*STR + (f0 + it*16)*4] = v;
    }
}

// ---------------- TF32 GEMM body ----------------
template<int BM, int BN, int WARPS_M, int WARPS_N, bool TRANSB, bool SPLITK>
__device__ __forceinline__ void gemm_body(
          const float* __restrict__ A, const float* __restrict__ B,
          const float* __restrict__ bias, const float* __restrict__ resid,
          float* __restrict__ C, int M, int N, int K, float scale, int kchunk)
{
    constexpr int BK = 16;
    constexpr int ASTR = BM + 8, BSTR = BN + 8;
    constexpr int WM = BM / WARPS_M, WN = BN / WARPS_N;
    constexpr int MT = WM / 16, NT = WN / 8;
    constexpr int A_IT = (BM*2 + 255)/256;
    constexpr int B_IT = (BN*2 + 255)/256;

    __shared__ uint32_t sA[2*BK*ASTR];
    __shared__ uint32_t sB[2*BK*BSTR];

    int tid = threadIdx.x, lane = tid & 31, warp = tid >> 5;
    int wm = warp % WARPS_M, wn = warp / WARPS_M;
    int row0 = blockIdx.y * BM, col0 = blockIdx.x * BN;
    int lr = lane >> 2, lc = lane & 3;

    int kb = SPLITK ? blockIdx.z * kchunk : 0;
    int ke = SPLITK ? min(K, kb + kchunk) : K;
    int ntiles = (ke - kb + BK - 1) / BK;
    if (ntiles <= 0) return;

    float acc[MT][NT][4];
    #pragma unroll
    for (int i = 0; i < MT; i++)
        #pragma unroll
        for (int j = 0; j < NT; j++)
            #pragma unroll
            for (int e = 0; e < 4; e++) acc[i][j][e] = 0.f;

    float areg[A_IT][8];
    float bregT[B_IT][8];
    float bregN[8];

    ld8<BM, A_IT, false>(A, nullptr, M, K, row0, kb, ke, tid, areg);
    if (TRANSB) ld8<BN, B_IT, false>(B, nullptr, N, K, col0, kb, ke, tid, bregT);
    else        ldB_n<BN>(B, N, kb, ke, col0, tid, bregN);
    sts8<BM, ASTR, A_IT>(sA, tid, areg);
    if (TRANSB) sts8<BN, BSTR, B_IT>(sB, tid, bregT);
    else        stsB_n<BN, BSTR>(sB, tid, bregN);
    __syncthreads();

    int buf = 0;
    for (int t = 0; t < ntiles; t++) {
        bool more = (t + 1 < ntiles);
        if (more) {
            int k0 = kb + (t+1)*BK;
            ld8<BM, A_IT, false>(A, nullptr, M, K, row0, k0, ke, tid, areg);
            if (TRANSB) ld8<BN, B_IT, false>(B, nullptr, N, K, col0, k0, ke, tid, bregT);
            else        ldB_n<BN>(B, N, k0, ke, col0, tid, bregN);
        }
        const uint32_t* pA = sA + buf*BK*ASTR;
        const uint32_t* pB = sB + buf*BK*BSTR;
        #pragma unroll
        for (int ks = 0; ks < 2; ks++) {
            int kk = ks*8;
            uint32_t af[MT][4];
            #pragma unroll
            for (int i = 0; i < MT; i++) {
                int m0 = wm*WM + i*16;
                af[i][0] = pA[(kk+lc  )*ASTR + m0 + lr];
                af[i][1] = pA[(kk+lc  )*ASTR + m0 + lr + 8];
                af[i][2] = pA[(kk+lc+4)*ASTR + m0 + lr];
                af[i][3] = pA[(kk+lc+4)*ASTR + m0 + lr + 8];
            }
            uint32_t bf2[NT][2];
            #pragma unroll
            for (int j = 0; j < NT; j++) {
                int n0 = wn*WN + j*8;
                bf2[j][0] = pB[(kk+lc  )*BSTR + n0 + lr];
                bf2[j][1] = pB[(kk+lc+4)*BSTR + n0 + lr];
            }
            #pragma unroll
            for (int i = 0; i < MT; i++)
                #pragma unroll
                for (int j = 0; j < NT; j++)
                    mma_tf32(acc[i][j], af[i], bf2[j]);
        }
        if (more) {
            sts8<BM, ASTR, A_IT>(sA + (buf^1)*BK*ASTR, tid, areg);
            if (TRANSB) sts8<BN, BSTR, B_IT>(sB + (buf^1)*BK*BSTR, tid, bregT);
            else        stsB_n<BN, BSTR>(sB + (buf^1)*BK*BSTR, tid, bregN);
        }
        __syncthreads();
        buf ^= 1;
    }

    #pragma unroll
    for (int i = 0; i < MT; i++) {
        int r0 = row0 + wm*WM + i*16 + lr;
        #pragma unroll
        for (int j = 0; j < NT; j++) {
            int c0 = col0 + wn*WN + j*8 + 2*lc;
            #pragma unroll
            for (int e = 0; e < 4; e++) {
                int r = r0 + (e >> 1)*8;
                int c = c0 + (e & 1);
                if (r < M && c < N) {
                    float v = acc[i][j][e] * scale;
                    if (SPLITK) {
                        atomicAdd(&C[(size_t)r*N + c], v);
                    } else {
                        if (bias)  v += bias[c];
                        if (resid) v += resid[(size_t)r*N + c];
                        C[(size_t)r*N + c] = v;
                    }
                }
            }
        }
    }
}

template<int BM, int BN, int WARPS_M, int WARPS_N, bool TRANSB, bool SPLITK>
__global__ void __launch_bounds__(256)
tf32_gemm(const float* __restrict__ A, const float* __restrict__ B,
          const float* __restrict__ bias, const float* __restrict__ resid,
          float* __restrict__ C, int M, int N, int K, float scale, int kchunk)
{
    gemm_body<BM,BN,WARPS_M,WARPS_N,TRANSB,SPLITK>(A,B,bias,resid,C,M,N,K,scale,kchunk);
}

// batched QKV
__global__ void __launch_bounds__(256)
tf32_gemm_qkv(const float* __restrict__ fsub, const float* __restrict__ fcom,
              const float* __restrict__ Wq, const float* __restrict__ bq,
              const float* __restrict__ Wk, const float* __restrict__ bk,
              const float* __restrict__ Wv, const float* __restrict__ bv,
              float* __restrict__ q, float* __restrict__ k, float* __restrict__ v)
{
    const float* A; const float* B; const float* bias; float* C;
    if (blockIdx.z == 0)      { A = fsub; B = Wq; bias = bq; C = q; }
    else if (blockIdx.z == 1) { A = fcom; B = Wk; bias = bk; C = k; }
    else                      { A = fcom; B = Wv; bias = bv; C = v; }
    gemm_body<64,64,2,4,false,false>(A, B, bias, nullptr, C,
                                     NPAIRS_MAP, FEAT, FEAT, 1.f, 0);
}

// ---------------- X@W1 GEMM, indirect A rows, fused node_e1 epilogue ----------------
__global__ void __launch_bounds__(256)
tf32_gemm_w1(const unsigned long long* __restrict__ rowp, const float* __restrict__ W1,
             const float* __restrict__ as1, const float* __restrict__ ad1,
             float* __restrict__ h1, float* __restrict__ es, float* __restrict__ ed)
{
    constexpr int BM = 128, BN = 128, BK = 16;
    constexpr int WARPS_M = 2, WARPS_N = 4;
    constexpr int ASTR = BM + 8, BSTR = BN + 8;
    constexpr int WM = BM / WARPS_M, WN = BN / WARPS_N;   // 64, 32
    constexpr int MT = WM / 16, NT = WN / 8;              // 4, 4
    constexpr int M = NNODES, N = H1DIM, K = FEAT;

    __shared__ uint32_t sA[2*BK*ASTR];
    __shared__ uint32_t sB[2*BK*BSTR];
    __shared__ float s_as[HID], s_ad[HID];

    int tid = threadIdx.x, lane = tid & 31, warp = tid >> 5;
    int wm = warp % WARPS_M, wn = warp / WARPS_M;
    int row0 = blockIdx.y * BM, col0 = blockIdx.x * BN;
    int h = blockIdx.x;                    // BN == HID -> column tile == head
    int lr = lane >> 2, lc = lane & 3;

    if (tid < HID) { s_as[tid] = as1[h*HID + tid]; s_ad[tid] = ad1[h*HID + tid]; }

    float acc[MT][NT][4];
    #pragma unroll
    for (int i = 0; i < MT; i++)
        #pragma unroll
        for (int j = 0; j < NT; j++)
            #pragma unroll
            for (int e = 0; e < 4; e++) acc[i][j][e] = 0.f;

    int ntiles = (K + BK - 1) / BK;
    float areg[1][8];
    float bregN[8];

    ld8<BM, 1, true>(nullptr, rowp, M, K, row0, 0, K, tid, areg);
    ldB_n<BN>(W1, N, 0, K, col0, tid, bregN);
    sts8<BM, ASTR, 1>(sA, tid, areg);
    stsB_n<BN, BSTR>(sB, tid, bregN);
    __syncthreads();

    int buf = 0;
    for (int t = 0; t < ntiles; t++) {
        bool more = (t + 1 < ntiles);
        if (more) {
            int k0 = (t+1)*BK;
            ld8<BM, 1, true>(nullptr, rowp, M, K, row0, k0, K, tid, areg);
            ldB_n<BN>(W1, N, k0, K, col0, tid, bregN);
        }
        const uint32_t* pA = sA + buf*BK*ASTR;
        const uint32_t* pB = sB + buf*BK*BSTR;
        #pragma unroll
        for (int ks = 0; ks < 2; ks++) {
            int kk = ks*8;
            uint32_t af[MT][4];
            #pragma unroll
            for (int i = 0; i < MT; i++) {
                int m0 = wm*WM + i*16;
                af[i][0] = pA[(kk+lc  )*ASTR + m0 + lr];
                af[i][1] = pA[(kk+lc  )*ASTR + m0 + lr + 8];
                af[i][2] = pA[(kk+lc+4)*ASTR + m0 + lr];
                af[i][3] = pA[(kk+lc+4)*ASTR + m0 + lr + 8];
            }
            uint32_t bf2[NT][2];
            #pragma unroll
            for (int j = 0; j < NT; j++) {
                int n0 = wn*WN + j*8;
                bf2[j][0] = pB[(kk+lc  )*BSTR + n0 + lr];
                bf2[j][1] = pB[(kk+lc+4)*BSTR + n0 + lr];
            }
            #pragma unroll
            for (int i = 0; i < MT; i++)
                #pragma unroll
                for (int j = 0; j < NT; j++)
                    mma_tf32(acc[i][j], af[i], bf2[j]);
        }
        if (more) {
            sts8<BM, ASTR, 1>(sA + (buf^1)*BK*ASTR, tid, areg);
            stsB_n<BN, BSTR>(sB + (buf^1)*BK*BSTR, tid, bregN);
        }
        __syncthreads();
        buf ^= 1;
    }

    // write h1
    #pragma unroll
    for (int i = 0; i < MT; i++) {
        int r0 = row0 + wm*WM + i*16 + lr;
        #pragma unroll
        for (int j = 0; j < NT; j++) {
            int c0 = col0 + wn*WN + j*8 + 2*lc;
            #pragma unroll
            for (int e = 0; e < 4; e++) {
                int r = r0 + (e >> 1)*8;
                int c = c0 + (e & 1);
                if (r < M) h1[(size_t)r*N + c] = acc[i][j][e];
            }
        }
    }

    // fused node_e1: per (row, head) dot with a_src/a_dst over this 128-col tile
    #pragma unroll
    for (int i = 0; i < MT; i++) {
        #pragma unroll
        for (int er = 0; er < 2; er++) {
            float se = 0.f, de = 0.f;
            #pragma unroll
            for (int j = 0; j < NT; j++) {
                #pragma unroll
                for (int ec = 0; ec < 2; ec++) {
                    int cl = wn*WN + j*8 + 2*lc + ec;
                    float vv = acc[i][j][er*2 + ec];
                    se += vv * s_as[cl];
                    de += vv * s_ad[cl];
                }
            }
            se += __shfl_xor_sync(~0u, se, 1); se += __shfl_xor_sync(~0u, se, 2);
            de += __shfl_xor_sync(~0u, de, 1); de += __shfl_xor_sync(~0u, de, 2);
            int r = row0 + wm*WM + i*16 + lr + er*8;
            if (lc == 0 && r < M) {
                atomicAdd(&es[r*HEADS + h], se);
                atomicAdd(&ed[r*HEADS + h], de);
            }
        }
    }
}

static void launch_small(const float* A, const float* B, const float* bias, const float* resid,
                         float* C, int M, int N, int K, float scale, bool transB)
{
    dim3 grid((N + 63)/64, (M + 63)/64);
    if (transB) tf32_gemm<64,64,2,4,true ,false><<<grid,256>>>(A,B,bias,resid,C,M,N,K,scale,0);
    else        tf32_gemm<64,64,2,4,false,false><<<grid,256>>>(A,B,bias,resid,C,M,N,K,scale,0);
}

static void launch_big(const float* A, const float* B, const float* bias, const float* resid,
                       float* C, int M, int N, int K, float scale, bool transB)
{
    dim3 grid((N + 127)/128, (M + 127)/128);
    if (transB) tf32_gemm<128,128,2,4,true ,false><<<grid,256>>>(A,B,bias,resid,C,M,N,K,scale,0);
    else        tf32_gemm<128,128,2,4,false,false><<<grid,256>>>(A,B,bias,resid,C,M,N,K,scale,0);
}

static void launch_splitk(const float* A, const float* B, float* C, int M, int N, int K, int splits)
{
    int chunk = ((K/splits + 15)/16)*16;
    dim3 grid((N + 63)/64, (M + 63)/64, splits);
    tf32_gemm<64,64,2,4,false,true><<<grid,256>>>(A,B,nullptr,nullptr,C,M,N,K,1.f,chunk);
}

// ---------------- softmax over 4096-wide rows ----------------
__global__ void softmax_rows(float* __restrict__ S)
{
    __shared__ float buf[NPAIRS_MAP];
    __shared__ float red[256];
    int row = blockIdx.x, tid = threadIdx.x;
    float* r = S + (size_t)row * NPAIRS_MAP;
    float mx = -INFINITY;
    for (int i = tid; i < NPAIRS_MAP; i += 256) { float v = r[i]; buf[i] = v; mx = fmaxf(mx, v); }
    red[tid] = mx; __syncthreads();
    for (int o = 128; o; o >>= 1) { if (tid < o) red[tid] = fmaxf(red[tid], red[tid+o]); __syncthreads(); }
    mx = red[0]; __syncthreads();
    float sum = 0.f;
    for (int i = tid; i < NPAIRS_MAP; i += 256) { float e = expf(buf[i] - mx); buf[i] = e; sum += e; }
    red[tid] = sum; __syncthreads();
    for (int o = 128; o; o >>= 1) { if (tid < o) red[tid] += red[tid+o]; __syncthreads(); }
    float inv = 1.f / red[0];
    for (int i = tid; i < NPAIRS_MAP; i += 256) r[i] = buf[i] * inv;
}

// ---------------- row-pointer table (replaces x copy + scatter) ----------------
__global__ void fill_rowptr(const float* __restrict__ x, unsigned long long* __restrict__ rp)
{
    int i = blockIdx.x*blockDim.x + threadIdx.x;
    if (i < NNODES) rp[i] = (unsigned long long)(x + (size_t)i*FEAT);
}

__global__ void scatter_winner(const int* __restrict__ com_idx, int* __restrict__ winner, int n)
{ int i = blockIdx.x*blockDim.x + threadIdx.x; if (i < n) atomicMax(&winner[com_idx[i]], i); }

__global__ void apply_rowptr(const int* __restrict__ com_idx, const int* __restrict__ winner,
                             const float* __restrict__ fused, unsigned long long* __restrict__ rp, int n)
{
    int p = blockIdx.x*blockDim.x + threadIdx.x;
    if (p >= n) return;
    int node = com_idx[p];
    if (winner[node] == p) rp[node] = (unsigned long long)(fused + (size_t)p*FEAT);
}

// ---------------- CSR build by dst ----------------
__global__ void hist_dst(const int* __restrict__ dst, int* __restrict__ deg, int E)
{ int e = blockIdx.x*blockDim.x + threadIdx.x; if (e < E) atomicAdd(&deg[dst[e]], 1); }

__global__ void scan_deg(const int* __restrict__ deg, int* __restrict__ off,
                         int* __restrict__ cur, int n)
{
    __shared__ int warp_sums[32];
    __shared__ int s_carry;
    int tid = threadIdx.x;
    int lane = tid & 31, w = tid >> 5;
    if (tid == 0) s_carry = 0;
    __syncthreads();
    for (int base = 0; base < n; base += 1024) {
        int i = base + tid;
        int v = (i < n) ? deg[i] : 0;
        int x = v;
        #pragma unroll
        for (int o = 1; o < 32; o <<= 1) { int y = __shfl_up_sync(~0u, x, o); if (lane >= o) x += y; }
        if (lane == 31) warp_sums[w] = x;
        __syncthreads();
        if (w == 0) {
            int t = warp_sums[lane];
            #pragma unroll
            for (int o = 1; o < 32; o <<= 1) { int y = __shfl_up_sync(~0u, t, o); if (lane >= o) t += y; }
            warp_sums[lane] = t;
        }
        __syncthreads();
        int warp_off = (w == 0) ? 0 : warp_sums[w-1];
        int incl = x + warp_off;
        int carry = s_carry;
        if (i < n) { off[i] = carry + incl - v; cur[i] = carry + incl - v; }
        __syncthreads();
        if (tid == 1023) s_carry = carry + incl;
        __syncthreads();
    }
    if (threadIdx.x == 0) off[n] = s_carry;
}

__global__ void scatter_csr(const int* __restrict__ src, const int* __restrict__ dst,
                            int* __restrict__ cur, int* __restrict__ csr, int E)
{
    int e = blockIdx.x*blockDim.x + threadIdx.x;
    if (e >= E) return;
    int pos = atomicAdd(&cur[dst[e]], 1);
    csr[pos] = src[e];
}

// ---------------- mega-fused GAT1 aggregate + ELU + W2 GEMV + node_e2 ----------------
__global__ void __launch_bounds__(256)
gat1_fused(const int* __restrict__ off, const int* __restrict__ csr,
           const float* __restrict__ es, const float* __restrict__ ed,
           const float* __restrict__ h1, const float* __restrict__ b1,
           const float* __restrict__ W2, const float* __restrict__ as2,
           const float* __restrict__ ad2,
           float* __restrict__ h2, float* __restrict__ es2, float* __restrict__ ed2)
{
    __shared__ float wT[OUTC][H1DIM];
    __shared__ float sb1[H1DIM];
    int tid = threadIdx.x;
    for (int i = tid; i < OUTC*H1DIM; i += 256) {
        int k = i / OUTC, c = i % OUTC;
        wT[c][k] = W2[i];
    }
    for (int i = tid; i < H1DIM; i += 256) sb1[i] = b1[i];
    __syncthreads();

    int lane = tid & 31;
    int d = blockIdx.x*8 + (tid >> 5);
    if (d >= NNODES) return;

    int s0 = off[d], s1 = off[d+1];
    float edv[HEADS], eself[HEADS], m[HEADS];
    #pragma unroll
    for (int h = 0; h < HEADS; h++) {
        edv[h] = ed[d*HEADS + h];
        eself[h] = leaky(es[d*HEADS + h] + edv[h]);
        m[h] = eself[h];
    }
    for (int i = s0 + lane; i < s1; i += 32) {
        int s = csr[i];
        #pragma unroll
        for (int h = 0; h < HEADS; h++)
            m[h] = fmaxf(m[h], leaky(es[s*HEADS + h] + edv[h]));
    }
    #pragma unroll
    for (int h = 0; h < HEADS; h++)
        #pragma unroll
        for (int o = 16; o; o >>= 1) m[h] = fmaxf(m[h], __shfl_xor_sync(~0u, m[h], o));

    float denp[HEADS];
    #pragma unroll
    for (int h = 0; h < HEADS; h++) denp[h] = 0.f;
    float4 acc[3];
    {
        const float4* hp = (const float4*)(h1 + (size_t)d*H1DIM);
        float wself[HEADS];
        #pragma unroll
        for (int h = 0; h < HEADS; h++) wself[h] = expf(eself[h] - m[h]);
        #pragma unroll
        for (int u = 0; u < 3; u++) {
            float4 hv = hp[lane + 32*u];
            float w = wself[u];
            acc[u].x = hv.x*w; acc[u].y = hv.y*w; acc[u].z = hv.z*w; acc[u].w = hv.w*w;
        }
        if (lane == 0)
            #pragma unroll
            for (int h = 0; h < HEADS; h++) denp[h] += wself[h];
    }
    for (int base = s0; base < s1; base += 32) {
        int i = base + lane;
        int sidx = 0;
        float w[HEADS];
        #pragma unroll
        for (int h = 0; h < HEADS; h++) w[h] = 0.f;
        if (i < s1) {
            sidx = csr[i];
            #pragma unroll
            for (int h = 0; h < HEADS; h++) {
                w[h] = expf(leaky(es[sidx*HEADS + h] + edv[h]) - m[h]);
                denp[h] += w[h];
            }
        }
        int cnt = min(32, s1 - base);
        #pragma unroll 4
        for (int j = 0; j < cnt; j++) {
            int s  = __shfl_sync(~0u, sidx, j);
            float w0 = __shfl_sync(~0u, w[0], j);
            float w1 = __shfl_sync(~0u, w[1], j);
            float w2 = __shfl_sync(~0u, w[2], j);
            const float4* sp = (const float4*)(h1 + (size_t)s*H1DIM);
            float4 v0 = sp[lane], v1 = sp[lane+32], v2 = sp[lane+64];
            acc[0].x += w0*v0.x; acc[0].y += w0*v0.y; acc[0].z += w0*v0.z; acc[0].w += w0*v0.w;
            acc[1].x += w1*v1.x; acc[1].y += w1*v1.y; acc[1].z += w1*v1.z; acc[1].w += w1*v1.w;
            acc[2].x += w2*v2.x; acc[2].y += w2*v2.y; acc[2].z += w2*v2.z; acc[2].w += w2*v2.w;
        }
    }
    #pragma unroll
    for (int h = 0; h < HEADS; h++)
        #pragma unroll
        for (int o = 16; o; o >>= 1) denp[h] += __shfl_xor_sync(~0u, denp[h], o);
    float inv[HEADS];
    #pragma unroll
    for (int h = 0; h < HEADS; h++) inv[h] = 1.f / (denp[h] + 1e-16f);

    const float4* b4 = (const float4*)sb1;
    float4 v[3];
    #pragma unroll
    for (int u = 0; u < 3; u++) {
        float4 bb = b4[lane + 32*u];
        float iv = inv[u];
        float xx;
        xx = acc[u].x*iv + bb.x; v[u].x = xx > 0.f ? xx : expm1f(xx);
        xx = acc[u].y*iv + bb.y; v[u].y = xx > 0.f ? xx : expm1f(xx);
        xx = acc[u].z*iv + bb.z; v[u].z = xx > 0.f ? xx : expm1f(xx);
        xx = acc[u].w*iv + bb.w; v[u].w = xx > 0.f ? xx : expm1f(xx);
    }
    float hh[OUTC];
    #pragma unroll
    for (int j = 0; j < OUTC; j++) {
        const float4* w4 = (const float4*)wT[j];
        float s = 0.f;
        #pragma unroll
        for (int u = 0; u < 3; u++) {
            float4 wv = w4[lane + 32*u];
            s += v[u].x*wv.x + v[u].y*wv.y + v[u].z*wv.z + v[u].w*wv.w;
        }
        #pragma unroll
        for (int o = 16; o; o >>= 1) s += __shfl_xor_sync(~0u, s, o);
        hh[j] = s;
    }
    if (lane == 0) {
        float s2 = 0.f, d2 = 0.f;
        #pragma unroll
        for (int j = 0; j < OUTC; j++) {
            h2[(size_t)d*OUTC + j] = hh[j];
            s2 += hh[j] * as2[j];
            d2 += hh[j] * ad2[j];
        }
        es2[d] = s2; ed2[d] = d2;
    }
}

// ---------------- fused GAT2 aggregate + bias ----------------
__global__ void __launch_bounds__(256)
gat2_fused(const int* __restrict__ off, const int* __restrict__ csr,
           const float* __restrict__ es, const float* __restrict__ ed,
           const float* __restrict__ h2, const float* __restrict__ b2,
           float* __restrict__ o2)
{
    int lane = threadIdx.x & 31;
    int d = blockIdx.x*8 + (threadIdx.x >> 5);
    if (d >= NNODES) return;
    int s0 = off[d], s1 = off[d+1];
    float edv = ed[d];
    float eself = leaky(es[d] + edv);
    float m = eself;
    for (int i = s0 + lane; i < s1; i += 32)
        m = fmaxf(m, leaky(es[csr[i]] + edv));
    #pragma unroll
    for (int o = 16; o; o >>= 1) m = fmaxf(m, __shfl_xor_sync(~0u, m, o));

    float den = 0.f;
    float acc[OUTC];
    #pragma unroll
    for (int c = 0; c < OUTC; c++) acc[c] = 0.f;
    for (int i = s0 + lane; i < s1; i += 32) {
        int s = csr[i];
        float w = expf(leaky(es[s] + edv) - m);
        den += w;
        const float* hp = h2 + (size_t)s*OUTC;
        #pragma unroll
        for (int c = 0; c < OUTC; c++) acc[c] += w * hp[c];
    }
    if (lane == 0) {
        float w = expf(eself - m);
        den += w;
        const float* hp = h2 + (size_t)d*OUTC;
        #pragma unroll
        for (int c = 0; c < OUTC; c++) acc[c] += w * hp[c];
    }
    #pragma unroll
    for (int o = 16; o; o >>= 1) {
        den += __shfl_xor_sync(~0u, den, o);
        #pragma unroll
        for (int c = 0; c < OUTC; c++) acc[c] += __shfl_xor_sync(~0u, acc[c], o);
    }
    if (lane == 0) {
        float inv = 1.f / (den + 1e-16f);
        #pragma unroll
        for (int c = 0; c < OUTC; c++) o2[(size_t)d*OUTC + c] = acc[c]*inv + b2[c];
    }
}

// ---------------- final pair scores ----------------
__global__ void pair_scores(const int* __restrict__ pair, const float* __restrict__ emb,
                            float* __restrict__ out, int n)
{
    int i = blockIdx.x*blockDim.x + threadIdx.x;
    if (i >= n) return;
    int a = pair[2*i], b = pair[2*i+1];
    const float2* ea = (const float2*)(emb + (size_t)a*OUTC);
    const float2* eb = (const float2*)(emb + (size_t)b*OUTC);
    float s = 0.f;
    #pragma unroll
    for (int c = 0; c < 5; c++) {
        float2 x = ea[c], y = eb[c];
        s += x.x*y.x + x.y*y.y;
    }
    out[i] = s;
}

// ---------------- host ----------------
extern "C" void kernel_launch(void* const* d_in, const int* in_sizes, int n_in,
                              void* d_out, int out_size)
{
    const float* fsub   = (const float*)d_in[0];
    const float* fcom   = (const float*)d_in[1];
    const float* x      = (const float*)d_in[2];
    const int*   comidx = (const int*)  d_in[3];
    const int*   edge   = (const int*)  d_in[4];
    const int*   pair   = (const int*)  d_in[5];
    const float* Wq = (const float*)d_in[6];  const float* bq = (const float*)d_in[7];
    const float* Wk = (const float*)d_in[8];  const float* bk = (const float*)d_in[9];
    const float* Wv = (const float*)d_in[10]; const float* bv = (const float*)d_in[11];
    const float* Wf = (const float*)d_in[12]; const float* bf = (const float*)d_in[13];
    const float* W1 = (const float*)d_in[14];
    const float* as1 = (const float*)d_in[15]; const float* ad1 = (const float*)d_in[16];
    const float* b1 = (const float*)d_in[17];
    const float* W2 = (const float*)d_in[18];
    const float* as2 = (const float*)d_in[19]; const float* ad2 = (const float*)d_in[20];
    const float* b2 = (const float*)d_in[21];
    float* out = (float*)d_out;

    const int E = in_sizes[4] / 2;
    const int* src = edge;
    const int* dst = edge + E;
    const int npairs = in_sizes[5] / 2;

    float *q, *k, *v, *S, *attv, *fused, *h1, *es1, *ed1;
    float *h2, *es2, *ed2, *o2;
    int *winner, *deg, *off, *cur, *csr;
    unsigned long long* rowptr;
    cudaGetSymbolAddress((void**)&q, g_q);       cudaGetSymbolAddress((void**)&k, g_k);
    cudaGetSymbolAddress((void**)&v, g_v);       cudaGetSymbolAddress((void**)&S, g_S);
    cudaGetSymbolAddress((void**)&attv, g_attv); cudaGetSymbolAddress((void**)&fused, g_fused);
    cudaGetSymbolAddress((void**)&rowptr, g_rowptr);
    cudaGetSymbolAddress((void**)&winner, g_winner);
    cudaGetSymbolAddress((void**)&h1, g_h1);
    cudaGetSymbolAddress((void**)&es1, g_es1);   cudaGetSymbolAddress((void**)&ed1, g_ed1);
    cudaGetSymbolAddress((void**)&h2, g_h2);
    cudaGetSymbolAddress((void**)&es2, g_es2);   cudaGetSymbolAddress((void**)&ed2, g_ed2);
    cudaGetSymbolAddress((void**)&o2, g_o2);
    cudaGetSymbolAddress((void**)&deg, g_deg);   cudaGetSymbolAddress((void**)&off, g_off);
    cudaGetSymbolAddress((void**)&cur, g_cur);   cudaGetSymbolAddress((void**)&csr, g_csr);

    const float inv_sqrt_feat = 0.057735026918962584f;   // 1/sqrt(300)

    // ---- CSR build + rowptr init ----
    cudaMemsetAsync(deg, 0, NNODES*sizeof(int), 0);
    hist_dst<<<(E + 255)/256, 256>>>(dst, deg, E);
    scan_deg<<<1, 1024>>>(deg, off, cur, NNODES);
    scatter_csr<<<(E + 255)/256, 256>>>(src, dst, cur, csr, E);
    fill_rowptr<<<(NNODES + 255)/256, 256>>>(x, rowptr);
    cudaMemsetAsync(winner, 0xFF, NNODES*sizeof(int), 0);
    scatter_winner<<<(NPAIRS_MAP + 255)/256, 256>>>(comidx, winner, NPAIRS_MAP);

    // ---- cross-attention ----
    {
        dim3 grid((FEAT + 63)/64, (NPAIRS_MAP + 63)/64, 3);
        tf32_gemm_qkv<<<grid, 256>>>(fsub, fcom, Wq, bq, Wk, bk, Wv, bv, q, k, v);
    }
    launch_big(q, k, nullptr, nullptr, S, NPAIRS_MAP, NPAIRS_MAP, FEAT, inv_sqrt_feat, true);
    softmax_rows<<<NPAIRS_MAP, 256>>>(S);
    cudaMemcpyAsync(attv, fsub, (size_t)NPAIRS_MAP*FEAT*sizeof(float), cudaMemcpyDeviceToDevice, 0);
    launch_splitk(S, v, attv, NPAIRS_MAP, FEAT, NPAIRS_MAP, 8);
    launch_small(attv, Wf, bf, nullptr, fused, NPAIRS_MAP, FEAT, FEAT, 1.f, false);

    // ---- substitute fused rows via row pointers ----
    apply_rowptr<<<(NPAIRS_MAP + 255)/256, 256>>>(comidx, winner, fused, rowptr, NPAIRS_MAP);

    // ---- GAT layer 1: indirect GEMM with fused node scores ----
    cudaMemsetAsync(es1, 0, NNODES*HEADS*sizeof(float), 0);
    cudaMemsetAsync(ed1, 0, NNODES*HEADS*sizeof(float), 0);
    {
        dim3 grid(HEADS, (NNODES + 127)/128);
        tf32_gemm_w1<<<grid, 256>>>(rowptr, W1, as1, ad1, h1, es1, ed1);
    }
    gat1_fused<<<(NNODES + 7)/8, 256>>>(off, csr, es1, ed1, h1, b1, W2, as2, ad2,
                                        h2, es2, ed2);

    // ---- GAT layer 2 ----
    gat2_fused<<<(NNODES + 7)/8, 256>>>(off, csr, es2, ed2, h2, b2, o2);

    // ---- pair scores ----
    pair_scores<<<(npairs + 255)/256, 256>>>(pair, o2, out, npairs);
}

// round 9
// speedup vs baseline: 2.8310x; 1.0089x over previous
#include <cuda_runtime.h>
#include <cuda_fp16.h>
#include <math.h>
#include <stdint.h>

// ---------------- problem constants ----------------
#define NPAIRS_MAP 4096
#define NNODES     50000
#define MAXEDGES   524288
#define FEAT       300
#define HID        128
#define HEADS      3
#define OUTC       10
#define H1DIM      (HEADS*HID)   // 384

// ---------------- scratch ----------------
__device__ float g_q[NPAIRS_MAP*FEAT];
__device__ float g_k[NPAIRS_MAP*FEAT];
__device__ float g_v[NPAIRS_MAP*FEAT];
__device__ float g_S[(size_t)NPAIRS_MAP*NPAIRS_MAP];
__device__ float g_attv[NPAIRS_MAP*FEAT];
__device__ float g_fused[NPAIRS_MAP*FEAT];
__device__ unsigned long long g_rowptr[NNODES];
__device__ int   g_winner[NNODES];
__device__ float g_h1[(size_t)NNODES*H1DIM];
__device__ __half g_h1h[(size_t)NNODES*H1DIM];
__device__ float g_es1[NNODES*HEADS];
__device__ float g_ed1[NNODES*HEADS];
__device__ float g_h2[NNODES*OUTC];
__device__ float g_es2[NNODES];
__device__ float g_ed2[NNODES];
__device__ float g_o2[NNODES*OUTC];
__device__ int   g_deg[NNODES];
__device__ int   g_off[NNODES+1];
__device__ int   g_cur[NNODES];
__device__ int   g_csr[MAXEDGES];

// ---------------- helpers ----------------
__device__ __forceinline__ uint32_t f2tf32(float f) {
    uint32_t u; asm("cvt.rna.tf32.f32 %0, %1;" : "=r"(u) : "f"(f)); return u;
}

__device__ __forceinline__ void mma_tf32(float* c, const uint32_t* a, const uint32_t* b) {
    asm volatile("mma.sync.aligned.m16n8k8.row.col.f32.tf32.tf32.f32 "
        "{%0,%1,%2,%3}, {%4,%5,%6,%7}, {%8,%9}, {%0,%1,%2,%3};"
        : "+f"(c[0]), "+f"(c[1]), "+f"(c[2]), "+f"(c[3])
        : "r"(a[0]), "r"(a[1]), "r"(a[2]), "r"(a[3]), "r"(b[0]), "r"(b[1]));
}

__device__ __forceinline__ float leaky(float v) { return v > 0.f ? v : 0.2f*v; }

// ---------------- generic loaders ----------------
template<int ROWS, int IT, bool IND>
__device__ __forceinline__ void ld8(const float* __restrict__ A,
                                    const unsigned long long* __restrict__ rowp,
                                    int nrows, int ld,
                                    int row0, int k0, int kmax, int tid, float (&reg)[IT][8])
{
    #pragma unroll
    for (int i = 0; i < IT; i++) {
        int idx = tid + i*256;
        #pragma unroll
        for (int j = 0; j < 8; j++) reg[i][j] = 0.f;
        if (idx < ROWS*2) {
            int r = idx >> 1, seg = idx & 1;
            int gr = row0 + r, gk = k0 + seg*8;
            if (gr < nrows && gk < kmax) {
                const float* base = IND ? (const float*)rowp[gr] : A + (size_t)gr*ld;
                const float* p = base + gk;
                if (gk + 8 <= kmax) {
                    float4 v0 = *(const float4*)p;
                    float4 v1 = *(const float4*)(p+4);
                    reg[i][0]=v0.x; reg[i][1]=v0.y; reg[i][2]=v0.z; reg[i][3]=v0.w;
                    reg[i][4]=v1.x; reg[i][5]=v1.y; reg[i][6]=v1.z; reg[i][7]=v1.w;
                } else {
                    #pragma unroll
                    for (int j = 0; j < 8; j++) if (gk + j < kmax) reg[i][j] = p[j];
                }
            }
        }
    }
}

template<int ROWS, int STR, int IT>
__device__ __forceinline__ void sts8(uint32_t* __restrict__ s, int tid, const float (&reg)[IT][8])
{
    #pragma unroll
    for (int i = 0; i < IT; i++) {
        int idx = tid + i*256;
        if (idx < ROWS*2) {
            int r = idx >> 1, seg = idx & 1;
            #pragma unroll
            for (int j = 0; j < 8; j++)
                s[(seg*8 + j)*STR + r] = f2tf32(reg[i][j]);
        }
    }
}

template<int BN>
__device__ __forceinline__ void ldB_n(const float* __restrict__ B, int N, int k0, int kmax,
                                      int col0, int tid, float (&reg)[8])
{
    #pragma unroll
    for (int j = 0; j < 8; j++) reg[j] = 0.f;
    int kk = tid >> 4, f0 = tid & 15;
    int gk = k0 + kk;
    if (gk < kmax) {
        #pragma unroll
        for (int it = 0; it < BN/64; it++) {
            int gc = col0 + (f0 + it*16)*4;
            if (gc < N) {
                const float* bp = B + (size_t)gk*N + gc;
                if (gc + 4 <= N) {
                    float4 v = *(const float4*)bp;
                    reg[it*4+0]=v.x; reg[it*4+1]=v.y; reg[it*4+2]=v.z; reg[it*4+3]=v.w;
                } else {
                    #pragma unroll
                    for (int j = 0; j < 4; j++) if (gc + j < N) reg[it*4+j] = bp[j];
                }
            }
        }
    }
}

template<int BN, int STR>
__device__ __forceinline__ void stsB_n(uint32_t* __restrict__ s, int tid, const float (&reg)[8])
{
    int kk = tid >> 4, f0 = tid & 15;
    #pragma unroll
    for (int it = 0; it < BN/64; it++) {
        uint4 v;
        v.x = f2tf32(reg[it*4+0]); v.y = f2tf32(reg[it*4+1]);
        v.z = f2tf32(reg[it*4+2]); v.w = f2tf32(reg[it*4+3]);
        *(uint4*)&s[kk*STR + (f0 + it*16)*4] = v;
    }
}

// ---------------- TF32 GEMM body ----------------
template<int BM, int BN, int WARPS_M, int WARPS_N, bool TRANSB, bool SPLITK>
__device__ __forceinline__ void gemm_body(
          const float* __restrict__ A, const float* __restrict__ B,
          const float* __restrict__ bias, const float* __restrict__ resid,
          float* __restrict__ C, int M, int N, int K, float scale, int kchunk)
{
    constexpr int BK = 16;
    constexpr int ASTR = BM + 8, BSTR = BN + 8;
    constexpr int WM = BM / WARPS_M, WN = BN / WARPS_N;
    constexpr int MT = WM / 16, NT = WN / 8;
    constexpr int A_IT = (BM*2 + 255)/256;
    constexpr int B_IT = (BN*2 + 255)/256;

    __shared__ uint32_t sA[2*BK*ASTR];
    __shared__ uint32_t sB[2*BK*BSTR];

    int tid = threadIdx.x, lane = tid & 31, warp = tid >> 5;
    int wm = warp % WARPS_M, wn = warp / WARPS_M;
    int row0 = blockIdx.y * BM, col0 = blockIdx.x * BN;
    int lr = lane >> 2, lc = lane & 3;

    int kb = SPLITK ? blockIdx.z * kchunk : 0;
    int ke = SPLITK ? min(K, kb + kchunk) : K;
    int ntiles = (ke - kb + BK - 1) / BK;
    if (ntiles <= 0) return;

    float acc[MT][NT][4];
    #pragma unroll
    for (int i = 0; i < MT; i++)
        #pragma unroll
        for (int j = 0; j < NT; j++)
            #pragma unroll
            for (int e = 0; e < 4; e++) acc[i][j][e] = 0.f;

    float areg[A_IT][8];
    float bregT[B_IT][8];
    float bregN[8];

    ld8<BM, A_IT, false>(A, nullptr, M, K, row0, kb, ke, tid, areg);
    if (TRANSB) ld8<BN, B_IT, false>(B, nullptr, N, K, col0, kb, ke, tid, bregT);
    else        ldB_n<BN>(B, N, kb, ke, col0, tid, bregN);
    sts8<BM, ASTR, A_IT>(sA, tid, areg);
    if (TRANSB) sts8<BN, BSTR, B_IT>(sB, tid, bregT);
    else        stsB_n<BN, BSTR>(sB, tid, bregN);
    __syncthreads();

    int buf = 0;
    for (int t = 0; t < ntiles; t++) {
        bool more = (t + 1 < ntiles);
        if (more) {
            int k0 = kb + (t+1)*BK;
            ld8<BM, A_IT, false>(A, nullptr, M, K, row0, k0, ke, tid, areg);
            if (TRANSB) ld8<BN, B_IT, false>(B, nullptr, N, K, col0, k0, ke, tid, bregT);
            else        ldB_n<BN>(B, N, k0, ke, col0, tid, bregN);
        }
        const uint32_t* pA = sA + buf*BK*ASTR;
        const uint32_t* pB = sB + buf*BK*BSTR;
        #pragma unroll
        for (int ks = 0; ks < 2; ks++) {
            int kk = ks*8;
            uint32_t af[MT][4];
            #pragma unroll
            for (int i = 0; i < MT; i++) {
                int m0 = wm*WM + i*16;
                af[i][0] = pA[(kk+lc  )*ASTR + m0 + lr];
                af[i][1] = pA[(kk+lc  )*ASTR + m0 + lr + 8];
                af[i][2] = pA[(kk+lc+4)*ASTR + m0 + lr];
                af[i][3] = pA[(kk+lc+4)*ASTR + m0 + lr + 8];
            }
            uint32_t bf2[NT][2];
            #pragma unroll
            for (int j = 0; j < NT; j++) {
                int n0 = wn*WN + j*8;
                bf2[j][0] = pB[(kk+lc  )*BSTR + n0 + lr];
                bf2[j][1] = pB[(kk+lc+4)*BSTR + n0 + lr];
            }
            #pragma unroll
            for (int i = 0; i < MT; i++)
                #pragma unroll
                for (int j = 0; j < NT; j++)
                    mma_tf32(acc[i][j], af[i], bf2[j]);
        }
        if (more) {
            sts8<BM, ASTR, A_IT>(sA + (buf^1)*BK*ASTR, tid, areg);
            if (TRANSB) sts8<BN, BSTR, B_IT>(sB + (buf^1)*BK*BSTR, tid, bregT);
            else        stsB_n<BN, BSTR>(sB + (buf^1)*BK*BSTR, tid, bregN);
        }
        __syncthreads();
        buf ^= 1;
    }

    #pragma unroll
    for (int i = 0; i < MT; i++) {
        int r0 = row0 + wm*WM + i*16 + lr;
        #pragma unroll
        for (int j = 0; j < NT; j++) {
            int c0 = col0 + wn*WN + j*8 + 2*lc;
            #pragma unroll
            for (int e = 0; e < 4; e++) {
                int r = r0 + (e >> 1)*8;
                int c = c0 + (e & 1);
                if (r < M && c < N) {
                    float v = acc[i][j][e] * scale;
                    if (SPLITK) {
                        atomicAdd(&C[(size_t)r*N + c], v);
                    } else {
                        if (bias)  v += bias[c];
                        if (resid) v += resid[(size_t)r*N + c];
                        C[(size_t)r*N + c] = v;
                    }
                }
            }
        }
    }
}

template<int BM, int BN, int WARPS_M, int WARPS_N, bool TRANSB, bool SPLITK>
__global__ void __launch_bounds__(256)
tf32_gemm(const float* __restrict__ A, const float* __restrict__ B,
          const float* __restrict__ bias, const float* __restrict__ resid,
          float* __restrict__ C, int M, int N, int K, float scale, int kchunk)
{
    gemm_body<BM,BN,WARPS_M,WARPS_N,TRANSB,SPLITK>(A,B,bias,resid,C,M,N,K,scale,kchunk);
}

// batched QKV
__global__ void __launch_bounds__(256)
tf32_gemm_qkv(const float* __restrict__ fsub, const float* __restrict__ fcom,
              const float* __restrict__ Wq, const float* __restrict__ bq,
              const float* __restrict__ Wk, const float* __restrict__ bk,
              const float* __restrict__ Wv, const float* __restrict__ bv,
              float* __restrict__ q, float* __restrict__ k, float* __restrict__ v)
{
    const float* A; const float* B; const float* bias; float* C;
    if (blockIdx.z == 0)      { A = fsub; B = Wq; bias = bq; C = q; }
    else if (blockIdx.z == 1) { A = fcom; B = Wk; bias = bk; C = k; }
    else                      { A = fcom; B = Wv; bias = bv; C = v; }
    gemm_body<64,64,2,4,false,false>(A, B, bias, nullptr, C,
                                     NPAIRS_MAP, FEAT, FEAT, 1.f, 0);
}

// ---------------- X@W1 GEMM, indirect A rows, fused node_e1 + fp16 mirror ----------------
__global__ void __launch_bounds__(256)
tf32_gemm_w1(const unsigned long long* __restrict__ rowp, const float* __restrict__ W1,
             const float* __restrict__ as1, const float* __restrict__ ad1,
             float* __restrict__ h1, __half* __restrict__ h1h,
             float* __restrict__ es, float* __restrict__ ed)
{
    constexpr int BM = 128, BN = 128, BK = 16;
    constexpr int WARPS_M = 2, WARPS_N = 4;
    constexpr int ASTR = BM + 8, BSTR = BN + 8;
    constexpr int WM = BM / WARPS_M, WN = BN / WARPS_N;
    constexpr int MT = WM / 16, NT = WN / 8;
    constexpr int M = NNODES, N = H1DIM, K = FEAT;

    __shared__ uint32_t sA[2*BK*ASTR];
    __shared__ uint32_t sB[2*BK*BSTR];
    __shared__ float s_as[HID], s_ad[HID];

    int tid = threadIdx.x, lane = tid & 31, warp = tid >> 5;
    int wm = warp % WARPS_M, wn = warp / WARPS_M;
    int row0 = blockIdx.y * BM, col0 = blockIdx.x * BN;
    int h = blockIdx.x;
    int lr = lane >> 2, lc = lane & 3;

    if (tid < HID) { s_as[tid] = as1[h*HID + tid]; s_ad[tid] = ad1[h*HID + tid]; }

    float acc[MT][NT][4];
    #pragma unroll
    for (int i = 0; i < MT; i++)
        #pragma unroll
        for (int j = 0; j < NT; j++)
            #pragma unroll
            for (int e = 0; e < 4; e++) acc[i][j][e] = 0.f;

    int ntiles = (K + BK - 1) / BK;
    float areg[1][8];
    float bregN[8];

    ld8<BM, 1, true>(nullptr, rowp, M, K, row0, 0, K, tid, areg);
    ldB_n<BN>(W1, N, 0, K, col0, tid, bregN);
    sts8<BM, ASTR, 1>(sA, tid, areg);
    stsB_n<BN, BSTR>(sB, tid, bregN);
    __syncthreads();

    int buf = 0;
    for (int t = 0; t < ntiles; t++) {
        bool more = (t + 1 < ntiles);
        if (more) {
            int k0 = (t+1)*BK;
            ld8<BM, 1, true>(nullptr, rowp, M, K, row0, k0, K, tid, areg);
            ldB_n<BN>(W1, N, k0, K, col0, tid, bregN);
        }
        const uint32_t* pA = sA + buf*BK*ASTR;
        const uint32_t* pB = sB + buf*BK*BSTR;
        #pragma unroll
        for (int ks = 0; ks < 2; ks++) {
            int kk = ks*8;
            uint32_t af[MT][4];
            #pragma unroll
            for (int i = 0; i < MT; i++) {
                int m0 = wm*WM + i*16;
                af[i][0] = pA[(kk+lc  )*ASTR + m0 + lr];
                af[i][1] = pA[(kk+lc  )*ASTR + m0 + lr + 8];
                af[i][2] = pA[(kk+lc+4)*ASTR + m0 + lr];
                af[i][3] = pA[(kk+lc+4)*ASTR + m0 + lr + 8];
            }
            uint32_t bf2[NT][2];
            #pragma unroll
            for (int j = 0; j < NT; j++) {
                int n0 = wn*WN + j*8;
                bf2[j][0] = pB[(kk+lc  )*BSTR + n0 + lr];
                bf2[j][1] = pB[(kk+lc+4)*BSTR + n0 + lr];
            }
            #pragma unroll
            for (int i = 0; i < MT; i++)
                #pragma unroll
                for (int j = 0; j < NT; j++)
                    mma_tf32(acc[i][j], af[i], bf2[j]);
        }
        if (more) {
            sts8<BM, ASTR, 1>(sA + (buf^1)*BK*ASTR, tid, areg);
            stsB_n<BN, BSTR>(sB + (buf^1)*BK*BSTR, tid, bregN);
        }
        __syncthreads();
        buf ^= 1;
    }

    // write h1 (fp32) + h1h (fp16 pairs; e&1 are adjacent columns)
    #pragma unroll
    for (int i = 0; i < MT; i++) {
        int r0 = row0 + wm*WM + i*16 + lr;
        #pragma unroll
        for (int j = 0; j < NT; j++) {
            int c0 = col0 + wn*WN + j*8 + 2*lc;
            #pragma unroll
            for (int er = 0; er < 2; er++) {
                int r = r0 + er*8;
                if (r < M) {
                    float v0 = acc[i][j][er*2 + 0];
                    float v1 = acc[i][j][er*2 + 1];
                    h1[(size_t)r*N + c0]     = v0;
                    h1[(size_t)r*N + c0 + 1] = v1;
                    *(__half2*)&h1h[(size_t)r*N + c0] = __floats2half2_rn(v0, v1);
                }
            }
        }
    }

    // fused node_e1
    #pragma unroll
    for (int i = 0; i < MT; i++) {
        #pragma unroll
        for (int er = 0; er < 2; er++) {
            float se = 0.f, de = 0.f;
            #pragma unroll
            for (int j = 0; j < NT; j++) {
                #pragma unroll
                for (int ec = 0; ec < 2; ec++) {
                    int cl = wn*WN + j*8 + 2*lc + ec;
                    float vv = acc[i][j][er*2 + ec];
                    se += vv * s_as[cl];
                    de += vv * s_ad[cl];
                }
            }
            se += __shfl_xor_sync(~0u, se, 1); se += __shfl_xor_sync(~0u, se, 2);
            de += __shfl_xor_sync(~0u, de, 1); de += __shfl_xor_sync(~0u, de, 2);
            int r = row0 + wm*WM + i*16 + lr + er*8;
            if (lc == 0 && r < M) {
                atomicAdd(&es[r*HEADS + h], se);
                atomicAdd(&ed[r*HEADS + h], de);
            }
        }
    }
}

static void launch_small(const float* A, const float* B, const float* bias, const float* resid,
                         float* C, int M, int N, int K, float scale, bool transB)
{
    dim3 grid((N + 63)/64, (M + 63)/64);
    if (transB) tf32_gemm<64,64,2,4,true ,false><<<grid,256>>>(A,B,bias,resid,C,M,N,K,scale,0);
    else        tf32_gemm<64,64,2,4,false,false><<<grid,256>>>(A,B,bias,resid,C,M,N,K,scale,0);
}

static void launch_big(const float* A, const float* B, const float* bias, const float* resid,
                       float* C, int M, int N, int K, float scale, bool transB)
{
    dim3 grid((N + 127)/128, (M + 127)/128);
    if (transB) tf32_gemm<128,128,2,4,true ,false><<<grid,256>>>(A,B,bias,resid,C,M,N,K,scale,0);
    else        tf32_gemm<128,128,2,4,false,false><<<grid,256>>>(A,B,bias,resid,C,M,N,K,scale,0);
}

static void launch_splitk(const float* A, const float* B, float* C, int M, int N, int K, int splits)
{
    int chunk = ((K/splits + 15)/16)*16;
    dim3 grid((N + 63)/64, (M + 63)/64, splits);
    tf32_gemm<64,64,2,4,false,true><<<grid,256>>>(A,B,nullptr,nullptr,C,M,N,K,1.f,chunk);
}

// ---------------- softmax over 4096-wide rows ----------------
__global__ void softmax_rows(float* __restrict__ S)
{
    __shared__ float buf[NPAIRS_MAP];
    __shared__ float red[256];
    int row = blockIdx.x, tid = threadIdx.x;
    float* r = S + (size_t)row * NPAIRS_MAP;
    float mx = -INFINITY;
    for (int i = tid; i < NPAIRS_MAP; i += 256) { float v = r[i]; buf[i] = v; mx = fmaxf(mx, v); }
    red[tid] = mx; __syncthreads();
    for (int o = 128; o; o >>= 1) { if (tid < o) red[tid] = fmaxf(red[tid], red[tid+o]); __syncthreads(); }
    mx = red[0]; __syncthreads();
    float sum = 0.f;
    for (int i = tid; i < NPAIRS_MAP; i += 256) { float e = __expf(buf[i] - mx); buf[i] = e; sum += e; }
    red[tid] = sum; __syncthreads();
    for (int o = 128; o; o >>= 1) { if (tid < o) red[tid] += red[tid+o]; __syncthreads(); }
    float inv = 1.f / red[0];
    for (int i = tid; i < NPAIRS_MAP; i += 256) r[i] = buf[i] * inv;
}

// ---------------- row-pointer table ----------------
__global__ void fill_rowptr(const float* __restrict__ x, unsigned long long* __restrict__ rp)
{
    int i = blockIdx.x*blockDim.x + threadIdx.x;
    if (i < NNODES) rp[i] = (unsigned long long)(x + (size_t)i*FEAT);
}

__global__ void scatter_winner(const int* __restrict__ com_idx, int* __restrict__ winner, int n)
{ int i = blockIdx.x*blockDim.x + threadIdx.x; if (i < n) atomicMax(&winner[com_idx[i]], i); }

__global__ void apply_rowptr(const int* __restrict__ com_idx, const int* __restrict__ winner,
                             const float* __restrict__ fused, unsigned long long* __restrict__ rp, int n)
{
    int p = blockIdx.x*blockDim.x + threadIdx.x;
    if (p >= n) return;
    int node = com_idx[p];
    if (winner[node] == p) rp[node] = (unsigned long long)(fused + (size_t)p*FEAT);
}

// ---------------- CSR build by dst ----------------
__global__ void hist_dst(const int* __restrict__ dst, int* __restrict__ deg, int E)
{ int e = blockIdx.x*blockDim.x + threadIdx.x; if (e < E) atomicAdd(&deg[dst[e]], 1); }

// thread-coarsened single-block scan (4 elements per thread per iteration)
__global__ void scan_deg(const int* __restrict__ deg, int* __restrict__ off,
                         int* __restrict__ cur, int n)
{
    __shared__ int warp_sums[32];
    __shared__ int s_carry;
    int tid = threadIdx.x;
    int lane = tid & 31, w = tid >> 5;
    if (tid == 0) s_carry = 0;
    __syncthreads();
    for (int base = 0; base < n; base += 4096) {
        int i0 = base + tid*4;
        int v0 = (i0   < n) ? deg[i0]   : 0;
        int v1 = (i0+1 < n) ? deg[i0+1] : 0;
        int v2 = (i0+2 < n) ? deg[i0+2] : 0;
        int v3 = (i0+3 < n) ? deg[i0+3] : 0;
        int p1 = v0, p2 = v0+v1, p3 = v0+v1+v2;
        int tsum = p3 + v3;
        int x = tsum;
        #pragma unroll
        for (int o = 1; o < 32; o <<= 1) { int y = __shfl_up_sync(~0u, x, o); if (lane >= o) x += y; }
        if (lane == 31) warp_sums[w] = x;
        __syncthreads();
        if (w == 0) {
            int t = warp_sums[lane];
            #pragma unroll
            for (int o = 1; o < 32; o <<= 1) { int y = __shfl_up_sync(~0u, t, o); if (lane >= o) t += y; }
            warp_sums[lane] = t;
        }
        __syncthreads();
        int warp_off = (w == 0) ? 0 : warp_sums[w-1];
        int excl = x - tsum + warp_off;
        int carry = s_carry;
        if (i0   < n) { int o0 = carry + excl;      off[i0]   = o0; cur[i0]   = o0; }
        if (i0+1 < n) { int o1 = carry + excl + p1; off[i0+1] = o1; cur[i0+1] = o1; }
        if (i0+2 < n) { int o2 = carry + excl + p2; off[i0+2] = o2; cur[i0+2] = o2; }
        if (i0+3 < n) { int o3 = carry + excl + p3; off[i0+3] = o3; cur[i0+3] = o3; }
        __syncthreads();
        if (tid == 0) s_carry = carry + warp_sums[31];
        __syncthreads();
    }
    if (threadIdx.x == 0) off[n] = s_carry;
}

__global__ void scatter_csr(const int* __restrict__ src, const int* __restrict__ dst,
                            int* __restrict__ cur, int* __restrict__ csr, int E)
{
    int e = blockIdx.x*blockDim.x + threadIdx.x;
    if (e >= E) return;
    int pos = atomicAdd(&cur[dst[e]], 1);
    csr[pos] = src[e];
}

// ---------------- mega-fused GAT1 aggregate + ELU + W2 GEMV + node_e2 ----------------
__global__ void __launch_bounds__(256)
gat1_fused(const int* __restrict__ off, const int* __restrict__ csr,
           const float* __restrict__ es, const float* __restrict__ ed,
           const float* __restrict__ h1, const __half* __restrict__ h1h,
           const float* __restrict__ b1,
           const float* __restrict__ W2, const float* __restrict__ as2,
           const float* __restrict__ ad2,
           float* __restrict__ h2, float* __restrict__ es2, float* __restrict__ ed2)
{
    __shared__ float wT[OUTC][H1DIM];
    __shared__ float sb1[H1DIM];
    int tid = threadIdx.x;
    for (int i = tid; i < OUTC*H1DIM; i += 256) {
        int k = i / OUTC, c = i % OUTC;
        wT[c][k] = W2[i];
    }
    for (int i = tid; i < H1DIM; i += 256) sb1[i] = b1[i];
    __syncthreads();

    int lane = tid & 31;
    int d = blockIdx.x*8 + (tid >> 5);
    if (d >= NNODES) return;

    int s0 = off[d], s1 = off[d+1];
    float edv[HEADS], eself[HEADS], m[HEADS];
    #pragma unroll
    for (int h = 0; h < HEADS; h++) {
        edv[h] = ed[d*HEADS + h];
        eself[h] = leaky(es[d*HEADS + h] + edv[h]);
        m[h] = eself[h];
    }
    for (int i = s0 + lane; i < s1; i += 32) {
        int s = csr[i];
        #pragma unroll
        for (int h = 0; h < HEADS; h++)
            m[h] = fmaxf(m[h], leaky(es[s*HEADS + h] + edv[h]));
    }
    #pragma unroll
    for (int h = 0; h < HEADS; h++)
        #pragma unroll
        for (int o = 16; o; o >>= 1) m[h] = fmaxf(m[h], __shfl_xor_sync(~0u, m[h], o));

    float denp[HEADS];
    #pragma unroll
    for (int h = 0; h < HEADS; h++) denp[h] = 0.f;
    float4 acc[3];
    {   // self-loop: fp32 row
        const float4* hp = (const float4*)(h1 + (size_t)d*H1DIM);
        float wself[HEADS];
        #pragma unroll
        for (int h = 0; h < HEADS; h++) wself[h] = __expf(eself[h] - m[h]);
        #pragma unroll
        for (int u = 0; u < 3; u++) {
            float4 hv = hp[lane + 32*u];
            float w = wself[u];
            acc[u].x = hv.x*w; acc[u].y = hv.y*w; acc[u].z = hv.z*w; acc[u].w = hv.w*w;
        }
        if (lane == 0)
            #pragma unroll
            for (int h = 0; h < HEADS; h++) denp[h] += wself[h];
    }
    for (int base = s0; base < s1; base += 32) {
        int i = base + lane;
        int sidx = 0;
        float w[HEADS];
        #pragma unroll
        for (int h = 0; h < HEADS; h++) w[h] = 0.f;
        if (i < s1) {
            sidx = csr[i];
            #pragma unroll
            for (int h = 0; h < HEADS; h++) {
                w[h] = __expf(leaky(es[sidx*HEADS + h] + edv[h]) - m[h]);
                denp[h] += w[h];
            }
        }
        int cnt = min(32, s1 - base);
        #pragma unroll 4
        for (int j = 0; j < cnt; j++) {
            int s  = __shfl_sync(~0u, sidx, j);
            float w0 = __shfl_sync(~0u, w[0], j);
            float w1 = __shfl_sync(~0u, w[1], j);
            float w2 = __shfl_sync(~0u, w[2], j);
            const uint2* sp = (const uint2*)(h1h + (size_t)s*H1DIM);   // 4 halves per uint2
            uint2 r0 = sp[lane], r1 = sp[lane+32], r2 = sp[lane+64];
            float2 a0 = __half22float2(*(__half2*)&r0.x), b0 = __half22float2(*(__half2*)&r0.y);
            float2 a1 = __half22float2(*(__half2*)&r1.x), b1 = __half22float2(*(__half2*)&r1.y);
            float2 a2 = __half22float2(*(__half2*)&r2.x), b2 = __half22float2(*(__half2*)&r2.y);
            acc[0].x += w0*a0.x; acc[0].y += w0*a0.y; acc[0].z += w0*b0.x; acc[0].w += w0*b0.y;
            acc[1].x += w1*a1.x; acc[1].y += w1*a1.y; acc[1].z += w1*b1.x; acc[1].w += w1*b1.y;
            acc[2].x += w2*a2.x; acc[2].y += w2*a2.y; acc[2].z += w2*b2.x; acc[2].w += w2*b2.y;
        }
    }
    #pragma unroll
    for (int h = 0; h < HEADS; h++)
        #pragma unroll
        for (int o = 16; o; o >>= 1) denp[h] += __shfl_xor_sync(~0u, denp[h], o);
    float inv[HEADS];
    #pragma unroll
    for (int h = 0; h < HEADS; h++) inv[h] = 1.f / (denp[h] + 1e-16f);

    const float4* b4 = (const float4*)sb1;
    float4 v[3];
    #pragma unroll
    for (int u = 0; u < 3; u++) {
        float4 bb = b4[lane + 32*u];
        float iv = inv[u];
        float xx;
        xx = acc[u].x*iv + bb.x; v[u].x = xx > 0.f ? xx : expm1f(xx);
        xx = acc[u].y*iv + bb.y; v[u].y = xx > 0.f ? xx : expm1f(xx);
        xx = acc[u].z*iv + bb.z; v[u].z = xx > 0.f ? xx : expm1f(xx);
        xx = acc[u].w*iv + bb.w; v[u].w = xx > 0.f ? xx : expm1f(xx);
    }
    float hh[OUTC];
    #pragma unroll
    for (int j = 0; j < OUTC; j++) {
        const float4* w4 = (const float4*)wT[j];
        float s = 0.f;
        #pragma unroll
        for (int u = 0; u < 3; u++) {
            float4 wv = w4[lane + 32*u];
            s += v[u].x*wv.x + v[u].y*wv.y + v[u].z*wv.z + v[u].w*wv.w;
        }
        #pragma unroll
        for (int o = 16; o; o >>= 1) s += __shfl_xor_sync(~0u, s, o);
        hh[j] = s;
    }
    if (lane == 0) {
        float s2 = 0.f, d2 = 0.f;
        #pragma unroll
        for (int j = 0; j < OUTC; j++) {
            h2[(size_t)d*OUTC + j] = hh[j];
            s2 += hh[j] * as2[j];
            d2 += hh[j] * ad2[j];
        }
        es2[d] = s2; ed2[d] = d2;
    }
}

// ---------------- fused GAT2 aggregate + bias ----------------
__global__ void __launch_bounds__(256)
gat2_fused(const int* __restrict__ off, const int* __restrict__ csr,
           const float* __restrict__ es, const float* __restrict__ ed,
           const float* __restrict__ h2, const float* __restrict__ b2,
           float* __restrict__ o2)
{
    int lane = threadIdx.x & 31;
    int d = blockIdx.x*8 + (threadIdx.x >> 5);
    if (d >= NNODES) return;
    int s0 = off[d], s1 = off[d+1];
    float edv = ed[d];
    float eself = leaky(es[d] + edv);
    float m = eself;
    for (int i = s0 + lane; i < s1; i += 32)
        m = fmaxf(m, leaky(es[csr[i]] + edv));
    #pragma unroll
    for (int o = 16; o; o >>= 1) m = fmaxf(m, __shfl_xor_sync(~0u, m, o));

    float den = 0.f;
    float acc[OUTC];
    #pragma unroll
    for (int c = 0; c < OUTC; c++) acc[c] = 0.f;
    for (int i = s0 + lane; i < s1; i += 32) {
        int s = csr[i];
        float w = __expf(leaky(es[s] + edv) - m);
        den += w;
        const float* hp = h2 + (size_t)s*OUTC;
        #pragma unroll
        for (int c = 0; c < OUTC; c++) acc[c] += w * hp[c];
    }
    if (lane == 0) {
        float w = __expf(eself - m);
        den += w;
        const float* hp = h2 + (size_t)d*OUTC;
        #pragma unroll
        for (int c = 0; c < OUTC; c++) acc[c] += w * hp[c];
    }
    #pragma unroll
    for (int o = 16; o; o >>= 1) {
        den += __shfl_xor_sync(~0u, den, o);
        #pragma unroll
        for (int c = 0; c < OUTC; c++) acc[c] += __shfl_xor_sync(~0u, acc[c], o);
    }
    if (lane == 0) {
        float inv = 1.f / (den + 1e-16f);
        #pragma unroll
        for (int c = 0; c < OUTC; c++) o2[(size_t)d*OUTC + c] = acc[c]*inv + b2[c];
    }
}

// ---------------- final pair scores ----------------
__global__ void pair_scores(const int* __restrict__ pair, const float* __restrict__ emb,
                            float* __restrict__ out, int n)
{
    int i = blockIdx.x*blockDim.x + threadIdx.x;
    if (i >= n) return;
    int a = pair[2*i], b = pair[2*i+1];
    const float2* ea = (const float2*)(emb + (size_t)a*OUTC);
    const float2* eb = (const float2*)(emb + (size_t)b*OUTC);
    float s = 0.f;
    #pragma unroll
    for (int c = 0; c < 5; c++) {
        float2 x = ea[c], y = eb[c];
        s += x.x*y.x + x.y*y.y;
    }
    out[i] = s;
}

// ---------------- host ----------------
extern "C" void kernel_launch(void* const* d_in, const int* in_sizes, int n_in,
                              void* d_out, int out_size)
{
    const float* fsub   = (const float*)d_in[0];
    const float* fcom   = (const float*)d_in[1];
    const float* x      = (const float*)d_in[2];
    const int*   comidx = (const int*)  d_in[3];
    const int*   edge   = (const int*)  d_in[4];
    const int*   pair   = (const int*)  d_in[5];
    const float* Wq = (const float*)d_in[6];  const float* bq = (const float*)d_in[7];
    const float* Wk = (const float*)d_in[8];  const float* bk = (const float*)d_in[9];
    const float* Wv = (const float*)d_in[10]; const float* bv = (const float*)d_in[11];
    const float* Wf = (const float*)d_in[12]; const float* bf = (const float*)d_in[13];
    const float* W1 = (const float*)d_in[14];
    const float* as1 = (const float*)d_in[15]; const float* ad1 = (const float*)d_in[16];
    const float* b1 = (const float*)d_in[17];
    const float* W2 = (const float*)d_in[18];
    const float* as2 = (const float*)d_in[19]; const float* ad2 = (const float*)d_in[20];
    const float* b2 = (const float*)d_in[21];
    float* out = (float*)d_out;

    const int E = in_sizes[4] / 2;
    const int* src = edge;
    const int* dst = edge + E;
    const int npairs = in_sizes[5] / 2;

    float *q, *k, *v, *S, *attv, *fused, *h1, *es1, *ed1;
    float *h2, *es2, *ed2, *o2;
    __half* h1h;
    int *winner, *deg, *off, *cur, *csr;
    unsigned long long* rowptr;
    cudaGetSymbolAddress((void**)&q, g_q);       cudaGetSymbolAddress((void**)&k, g_k);
    cudaGetSymbolAddress((void**)&v, g_v);       cudaGetSymbolAddress((void**)&S, g_S);
    cudaGetSymbolAddress((void**)&attv, g_attv); cudaGetSymbolAddress((void**)&fused, g_fused);
    cudaGetSymbolAddress((void**)&rowptr, g_rowptr);
    cudaGetSymbolAddress((void**)&winner, g_winner);
    cudaGetSymbolAddress((void**)&h1, g_h1);     cudaGetSymbolAddress((void**)&h1h, g_h1h);
    cudaGetSymbolAddress((void**)&es1, g_es1);   cudaGetSymbolAddress((void**)&ed1, g_ed1);
    cudaGetSymbolAddress((void**)&h2, g_h2);
    cudaGetSymbolAddress((void**)&es2, g_es2);   cudaGetSymbolAddress((void**)&ed2, g_ed2);
    cudaGetSymbolAddress((void**)&o2, g_o2);
    cudaGetSymbolAddress((void**)&deg, g_deg);   cudaGetSymbolAddress((void**)&off, g_off);
    cudaGetSymbolAddress((void**)&cur, g_cur);   cudaGetSymbolAddress((void**)&csr, g_csr);

    const float inv_sqrt_feat = 0.057735026918962584f;   // 1/sqrt(300)

    // ---- CSR build + rowptr init ----
    cudaMemsetAsync(deg, 0, NNODES*sizeof(int), 0);
    hist_dst<<<(E + 255)/256, 256>>>(dst, deg, E);
    scan_deg<<<1, 1024>>>(deg, off, cur, NNODES);
    scatter_csr<<<(E + 255)/256, 256>>>(src, dst, cur, csr, E);
    fill_rowptr<<<(NNODES + 255)/256, 256>>>(x, rowptr);
    cudaMemsetAsync(winner, 0xFF, NNODES*sizeof(int), 0);
    scatter_winner<<<(NPAIRS_MAP + 255)/256, 256>>>(comidx, winner, NPAIRS_MAP);

    // ---- cross-attention ----
    {
        dim3 grid((FEAT + 63)/64, (NPAIRS_MAP + 63)/64, 3);
        tf32_gemm_qkv<<<grid, 256>>>(fsub, fcom, Wq, bq, Wk, bk, Wv, bv, q, k, v);
    }
    launch_big(q, k, nullptr, nullptr, S, NPAIRS_MAP, NPAIRS_MAP, FEAT, inv_sqrt_feat, true);
    softmax_rows<<<NPAIRS_MAP, 256>>>(S);
    cudaMemcpyAsync(attv, fsub, (size_t)NPAIRS_MAP*FEAT*sizeof(float), cudaMemcpyDeviceToDevice, 0);
    launch_splitk(S, v, attv, NPAIRS_MAP, FEAT, NPAIRS_MAP, 8);
    launch_small(attv, Wf, bf, nullptr, fused, NPAIRS_MAP, FEAT, FEAT, 1.f, false);

    // ---- substitute fused rows via row pointers ----
    apply_rowptr<<<(NPAIRS_MAP + 255)/256, 256>>>(comidx, winner, fused, rowptr, NPAIRS_MAP);

    // ---- GAT layer 1 ----
    cudaMemsetAsync(es1, 0, NNODES*HEADS*sizeof(float), 0);
    cudaMemsetAsync(ed1, 0, NNODES*HEADS*sizeof(float), 0);
    {
        dim3 grid(HEADS, (NNODES + 127)/128);
        tf32_gemm_w1<<<grid, 256>>>(rowptr, W1, as1, ad1, h1, h1h, es1, ed1);
    }
    gat1_fused<<<(NNODES + 7)/8, 256>>>(off, csr, es1, ed1, h1, h1h, b1, W2, as2, ad2,
                                        h2, es2, ed2);

    // ---- GAT layer 2 ----
    gat2_fused<<<(NNODES + 7)/8, 256>>>(off, csr, es2, ed2, h2, b2, o2);

    // ---- pair scores ----
    pair_scores<<<(npairs + 255)/256, 256>>>(pair, o2, out, npairs);
}

// round 11
// speedup vs baseline: 3.0298x; 1.0702x over previous
#include <cuda_runtime.h>
#include <cuda_fp16.h>
#include <math.h>
#include <stdint.h>

// ---------------- problem constants ----------------
#define NPAIRS_MAP 4096
#define NNODES     50000
#define MAXEDGES   524288
#define FEAT       300
#define HID        128
#define HEADS      3
#define OUTC       10
#define H1DIM      (HEADS*HID)   // 384

// ---------------- scratch ----------------
__device__ float g_q[NPAIRS_MAP*FEAT];
__device__ float g_k[NPAIRS_MAP*FEAT];
__device__ float g_v[NPAIRS_MAP*FEAT];
__device__ float g_S[(size_t)NPAIRS_MAP*NPAIRS_MAP];
__device__ float g_rowsum[NPAIRS_MAP];
__device__ float g_attv[NPAIRS_MAP*FEAT];
__device__ float g_fused[NPAIRS_MAP*FEAT];
__device__ unsigned long long g_rowptr[NNODES];
__device__ int   g_winner[NNODES];
__device__ float g_h1[(size_t)NNODES*H1DIM];
__device__ __half g_h1h[(size_t)NNODES*H1DIM];
__device__ float g_es1[NNODES*HEADS];
__device__ float g_ed1[NNODES*HEADS];
__device__ float g_h2[NNODES*OUTC];
__device__ float g_es2[NNODES];
__device__ float g_ed2[NNODES];
__device__ float g_o2[NNODES*OUTC];
__device__ int   g_deg[NNODES];
__device__ int   g_off[NNODES+1];
__device__ int   g_cur[NNODES];
__device__ int   g_csr[MAXEDGES];

// ---------------- helpers ----------------
__device__ __forceinline__ uint32_t f2tf32(float f) {
    uint32_t u; asm("cvt.rna.tf32.f32 %0, %1;" : "=r"(u) : "f"(f)); return u;
}

__device__ __forceinline__ void mma_tf32(float* c, const uint32_t* a, const uint32_t* b) {
    asm volatile("mma.sync.aligned.m16n8k8.row.col.f32.tf32.tf32.f32 "
        "{%0,%1,%2,%3}, {%4,%5,%6,%7}, {%8,%9}, {%0,%1,%2,%3};"
        : "+f"(c[0]), "+f"(c[1]), "+f"(c[2]), "+f"(c[3])
        : "r"(a[0]), "r"(a[1]), "r"(a[2]), "r"(a[3]), "r"(b[0]), "r"(b[1]));
}

__device__ __forceinline__ float leaky(float v) { return v > 0.f ? v : 0.2f*v; }

// ---------------- generic loaders ----------------
// SC: scale each A row by rsc[row] during load
template<int ROWS, int IT, bool IND, bool SC>
__device__ __forceinline__ void ld8(const float* __restrict__ A,
                                    const unsigned long long* __restrict__ rowp,
                                    const float* __restrict__ rsc,
                                    int nrows, int ld,
                                    int row0, int k0, int kmax, int tid, float (&reg)[IT][8])
{
    #pragma unroll
    for (int i = 0; i < IT; i++) {
        int idx = tid + i*256;
        #pragma unroll
        for (int j = 0; j < 8; j++) reg[i][j] = 0.f;
        if (idx < ROWS*2) {
            int r = idx >> 1, seg = idx & 1;
            int gr = row0 + r, gk = k0 + seg*8;
            if (gr < nrows && gk < kmax) {
                const float* base = IND ? (const float*)rowp[gr] : A + (size_t)gr*ld;
                const float* p = base + gk;
                float sc = SC ? rsc[gr] : 1.f;
                if (gk + 8 <= kmax) {
                    float4 v0 = *(const float4*)p;
                    float4 v1 = *(const float4*)(p+4);
                    reg[i][0]=v0.x*sc; reg[i][1]=v0.y*sc; reg[i][2]=v0.z*sc; reg[i][3]=v0.w*sc;
                    reg[i][4]=v1.x*sc; reg[i][5]=v1.y*sc; reg[i][6]=v1.z*sc; reg[i][7]=v1.w*sc;
                } else {
                    #pragma unroll
                    for (int j = 0; j < 8; j++) if (gk + j < kmax) reg[i][j] = p[j]*sc;
                }
            }
        }
    }
}

template<int ROWS, int STR, int IT>
__device__ __forceinline__ void sts8(uint32_t* __restrict__ s, int tid, const float (&reg)[IT][8])
{
    #pragma unroll
    for (int i = 0; i < IT; i++) {
        int idx = tid + i*256;
        if (idx < ROWS*2) {
            int r = idx >> 1, seg = idx & 1;
            #pragma unroll
            for (int j = 0; j < 8; j++)
                s[(seg*8 + j)*STR + r] = f2tf32(reg[i][j]);
        }
    }
}

template<int BN>
__device__ __forceinline__ void ldB_n(const float* __restrict__ B, int N, int k0, int kmax,
                                      int col0, int tid, float (&reg)[8])
{
    #pragma unroll
    for (int j = 0; j < 8; j++) reg[j] = 0.f;
    int kk = tid >> 4, f0 = tid & 15;
    int gk = k0 + kk;
    if (gk < kmax) {
        #pragma unroll
        for (int it = 0; it < BN/64; it++) {
            int gc = col0 + (f0 + it*16)*4;
            if (gc < N) {
                const float* bp = B + (size_t)gk*N + gc;
                if (gc + 4 <= N) {
                    float4 v = *(const float4*)bp;
                    reg[it*4+0]=v.x; reg[it*4+1]=v.y; reg[it*4+2]=v.z; reg[it*4+3]=v.w;
                } else {
                    #pragma unroll
                    for (int j = 0; j < 4; j++) if (gc + j < N) reg[it*4+j] = bp[j];
                }
            }
        }
    }
}

template<int BN, int STR>
__device__ __forceinline__ void stsB_n(uint32_t* __restrict__ s, int tid, const float (&reg)[8])
{
    int kk = tid >> 4, f0 = tid & 15;
    #pragma unroll
    for (int it = 0; it < BN/64; it++) {
        uint4 v;
        v.x = f2tf32(reg[it*4+0]); v.y = f2tf32(reg[it*4+1]);
        v.z = f2tf32(reg[it*4+2]); v.w = f2tf32(reg[it*4+3]);
        *(uint4*)&s[kk*STR + (f0 + it*16)*4] = v;
    }
}

// ---------------- TF32 GEMM body ----------------
// EXPOUT: C = exp(acc*scale), accumulate per-row sums into rowsum (atomics)
// SCALEA: A row r scaled by rowscale[r] on load
template<int BM, int BN, int WARPS_M, int WARPS_N, bool TRANSB, bool SPLITK, bool EXPOUT, bool SCALEA>
__device__ __forceinline__ void gemm_body(
          const float* __restrict__ A, const float* __restrict__ B,
          const float* __restrict__ bias, const float* __restrict__ resid,
          float* __restrict__ C, int M, int N, int K, float scale, int kchunk,
          const float* __restrict__ rowscale, float* __restrict__ rowsum)
{
    constexpr int BK = 16;
    constexpr int ASTR = BM + 8, BSTR = BN + 8;
    constexpr int WM = BM / WARPS_M, WN = BN / WARPS_N;
    constexpr int MT = WM / 16, NT = WN / 8;
    constexpr int A_IT = (BM*2 + 255)/256;
    constexpr int B_IT = (BN*2 + 255)/256;

    __shared__ uint32_t sA[2*BK*ASTR];
    __shared__ uint32_t sB[2*BK*BSTR];

    int tid = threadIdx.x, lane = tid & 31, warp = tid >> 5;
    int wm = warp % WARPS_M, wn = warp / WARPS_M;
    int row0 = blockIdx.y * BM, col0 = blockIdx.x * BN;
    int lr = lane >> 2, lc = lane & 3;

    int kb = SPLITK ? blockIdx.z * kchunk : 0;
    int ke = SPLITK ? min(K, kb + kchunk) : K;
    int ntiles = (ke - kb + BK - 1) / BK;
    if (ntiles <= 0) return;

    float acc[MT][NT][4];
    #pragma unroll
    for (int i = 0; i < MT; i++)
        #pragma unroll
        for (int j = 0; j < NT; j++)
            #pragma unroll
            for (int e = 0; e < 4; e++) acc[i][j][e] = 0.f;

    float areg[A_IT][8];
    float bregT[B_IT][8];
    float bregN[8];

    ld8<BM, A_IT, false, SCALEA>(A, nullptr, rowscale, M, K, row0, kb, ke, tid, areg);
    if (TRANSB) ld8<BN, B_IT, false, false>(B, nullptr, nullptr, N, K, col0, kb, ke, tid, bregT);
    else        ldB_n<BN>(B, N, kb, ke, col0, tid, bregN);
    sts8<BM, ASTR, A_IT>(sA, tid, areg);
    if (TRANSB) sts8<BN, BSTR, B_IT>(sB, tid, bregT);
    else        stsB_n<BN, BSTR>(sB, tid, bregN);
    __syncthreads();

    int buf = 0;
    for (int t = 0; t < ntiles; t++) {
        bool more = (t + 1 < ntiles);
        if (more) {
            int k0 = kb + (t+1)*BK;
            ld8<BM, A_IT, false, SCALEA>(A, nullptr, rowscale, M, K, row0, k0, ke, tid, areg);
            if (TRANSB) ld8<BN, B_IT, false, false>(B, nullptr, nullptr, N, K, col0, k0, ke, tid, bregT);
            else        ldB_n<BN>(B, N, k0, ke, col0, tid, bregN);
        }
        const uint32_t* pA = sA + buf*BK*ASTR;
        const uint32_t* pB = sB + buf*BK*BSTR;
        #pragma unroll
        for (int ks = 0; ks < 2; ks++) {
            int kk = ks*8;
            uint32_t af[MT][4];
            #pragma unroll
            for (int i = 0; i < MT; i++) {
                int m0 = wm*WM + i*16;
                af[i][0] = pA[(kk+lc  )*ASTR + m0 + lr];
                af[i][1] = pA[(kk+lc  )*ASTR + m0 + lr + 8];
                af[i][2] = pA[(kk+lc+4)*ASTR + m0 + lr];
                af[i][3] = pA[(kk+lc+4)*ASTR + m0 + lr + 8];
            }
            uint32_t bf2[NT][2];
            #pragma unroll
            for (int j = 0; j < NT; j++) {
                int n0 = wn*WN + j*8;
                bf2[j][0] = pB[(kk+lc  )*BSTR + n0 + lr];
                bf2[j][1] = pB[(kk+lc+4)*BSTR + n0 + lr];
            }
            #pragma unroll
            for (int i = 0; i < MT; i++)
                #pragma unroll
                for (int j = 0; j < NT; j++)
                    mma_tf32(acc[i][j], af[i], bf2[j]);
        }
        if (more) {
            sts8<BM, ASTR, A_IT>(sA + (buf^1)*BK*ASTR, tid, areg);
            if (TRANSB) sts8<BN, BSTR, B_IT>(sB + (buf^1)*BK*BSTR, tid, bregT);
            else        stsB_n<BN, BSTR>(sB + (buf^1)*BK*BSTR, tid, bregN);
        }
        __syncthreads();
        buf ^= 1;
    }

    #pragma unroll
    for (int i = 0; i < MT; i++) {
        int r0 = row0 + wm*WM + i*16 + lr;
        #pragma unroll
        for (int er = 0; er < 2; er++) {
            int r = r0 + er*8;
            float rsum = 0.f;
            #pragma unroll
            for (int j = 0; j < NT; j++) {
                int c0 = col0 + wn*WN + j*8 + 2*lc;
                #pragma unroll
                for (int ec = 0; ec < 2; ec++) {
                    int c = c0 + ec;
                    if (r < M && c < N) {
                        float v = acc[i][j][er*2 + ec] * scale;
                        if (EXPOUT) {
                            v = __expf(v);
                            rsum += v;
                            C[(size_t)r*N + c] = v;
                        } else if (SPLITK) {
                            atomicAdd(&C[(size_t)r*N + c], v);
                        } else {
                            if (bias)  v += bias[c];
                            if (resid) v += resid[(size_t)r*N + c];
                            C[(size_t)r*N + c] = v;
                        }
                    }
                }
            }
            if (EXPOUT) {
                rsum += __shfl_xor_sync(~0u, rsum, 1);
                rsum += __shfl_xor_sync(~0u, rsum, 2);
                if (lc == 0 && r < M) atomicAdd(&rowsum[r], rsum);
            }
        }
    }
}

template<int BM, int BN, int WARPS_M, int WARPS_N, bool TRANSB, bool SPLITK, bool EXPOUT, bool SCALEA>
__global__ void __launch_bounds__(256)
tf32_gemm(const float* __restrict__ A, const float* __restrict__ B,
          const float* __restrict__ bias, const float* __restrict__ resid,
          float* __restrict__ C, int M, int N, int K, float scale, int kchunk,
          const float* __restrict__ rowscale, float* __restrict__ rowsum)
{
    gemm_body<BM,BN,WARPS_M,WARPS_N,TRANSB,SPLITK,EXPOUT,SCALEA>(
        A,B,bias,resid,C,M,N,K,scale,kchunk,rowscale,rowsum);
}

// batched QKV (128x128 tile)
__global__ void __launch_bounds__(256)
tf32_gemm_qkv(const float* __restrict__ fsub, const float* __restrict__ fcom,
              const float* __restrict__ Wq, const float* __restrict__ bq,
              const float* __restrict__ Wk, const float* __restrict__ bk,
              const float* __restrict__ Wv, const float* __restrict__ bv,
              float* __restrict__ q, float* __restrict__ k, float* __restrict__ v)
{
    const float* A; const float* B; const float* bias; float* C;
    if (blockIdx.z == 0)      { A = fsub; B = Wq; bias = bq; C = q; }
    else if (blockIdx.z == 1) { A = fcom; B = Wk; bias = bk; C = k; }
    else                      { A = fcom; B = Wv; bias = bv; C = v; }
    gemm_body<128,128,2,4,false,false,false,false>(A, B, bias, nullptr, C,
                                     NPAIRS_MAP, FEAT, FEAT, 1.f, 0, nullptr, nullptr);
}

// ---------------- X@W1 GEMM, indirect A rows, fused node_e1 + fp16 mirror ----------------
__global__ void __launch_bounds__(256)
tf32_gemm_w1(const unsigned long long* __restrict__ rowp, const float* __restrict__ W1,
             const float* __restrict__ as1, const float* __restrict__ ad1,
             float* __restrict__ h1, __half* __restrict__ h1h,
             float* __restrict__ es, float* __restrict__ ed)
{
    constexpr int BM = 128, BN = 128, BK = 16;
    constexpr int WARPS_M = 2, WARPS_N = 4;
    constexpr int ASTR = BM + 8, BSTR = BN + 8;
    constexpr int WM = BM / WARPS_M, WN = BN / WARPS_N;
    constexpr int MT = WM / 16, NT = WN / 8;
    constexpr int M = NNODES, N = H1DIM, K = FEAT;

    __shared__ uint32_t sA[2*BK*ASTR];
    __shared__ uint32_t sB[2*BK*BSTR];
    __shared__ float s_as[HID], s_ad[HID];

    int tid = threadIdx.x, lane = tid & 31, warp = tid >> 5;
    int wm = warp % WARPS_M, wn = warp / WARPS_M;
    int row0 = blockIdx.y * BM, col0 = blockIdx.x * BN;
    int h = blockIdx.x;
    int lr = lane >> 2, lc = lane & 3;

    if (tid < HID) { s_as[tid] = as1[h*HID + tid]; s_ad[tid] = ad1[h*HID + tid]; }

    float acc[MT][NT][4];
    #pragma unroll
    for (int i = 0; i < MT; i++)
        #pragma unroll
        for (int j = 0; j < NT; j++)
            #pragma unroll
            for (int e = 0; e < 4; e++) acc[i][j][e] = 0.f;

    int ntiles = (K + BK - 1) / BK;
    float areg[1][8];
    float bregN[8];

    ld8<BM, 1, true, false>(nullptr, rowp, nullptr, M, K, row0, 0, K, tid, areg);
    ldB_n<BN>(W1, N, 0, K, col0, tid, bregN);
    sts8<BM, ASTR, 1>(sA, tid, areg);
    stsB_n<BN, BSTR>(sB, tid, bregN);
    __syncthreads();

    int buf = 0;
    for (int t = 0; t < ntiles; t++) {
        bool more = (t + 1 < ntiles);
        if (more) {
            int k0 = (t+1)*BK;
            ld8<BM, 1, true, false>(nullptr, rowp, nullptr, M, K, row0, k0, K, tid, areg);
            ldB_n<BN>(W1, N, k0, K, col0, tid, bregN);
        }
        const uint32_t* pA = sA + buf*BK*ASTR;
        const uint32_t* pB = sB + buf*BK*BSTR;
        #pragma unroll
        for (int ks = 0; ks < 2; ks++) {
            int kk = ks*8;
            uint32_t af[MT][4];
            #pragma unroll
            for (int i = 0; i < MT; i++) {
                int m0 = wm*WM + i*16;
                af[i][0] = pA[(kk+lc  )*ASTR + m0 + lr];
                af[i][1] = pA[(kk+lc  )*ASTR + m0 + lr + 8];
                af[i][2] = pA[(kk+lc+4)*ASTR + m0 + lr];
                af[i][3] = pA[(kk+lc+4)*ASTR + m0 + lr + 8];
            }
            uint32_t bf2[NT][2];
            #pragma unroll
            for (int j = 0; j < NT; j++) {
                int n0 = wn*WN + j*8;
                bf2[j][0] = pB[(kk+lc  )*BSTR + n0 + lr];
                bf2[j][1] = pB[(kk+lc+4)*BSTR + n0 + lr];
            }
            #pragma unroll
            for (int i = 0; i < MT; i++)
                #pragma unroll
                for (int j = 0; j < NT; j++)
                    mma_tf32(acc[i][j], af[i], bf2[j]);
        }
        if (more) {
            sts8<BM, ASTR, 1>(sA + (buf^1)*BK*ASTR, tid, areg);
            stsB_n<BN, BSTR>(sB + (buf^1)*BK*BSTR, tid, bregN);
        }
        __syncthreads();
        buf ^= 1;
    }

    #pragma unroll
    for (int i = 0; i < MT; i++) {
        int r0 = row0 + wm*WM + i*16 + lr;
        #pragma unroll
        for (int j = 0; j < NT; j++) {
            int c0 = col0 + wn*WN + j*8 + 2*lc;
            #pragma unroll
            for (int er = 0; er < 2; er++) {
                int r = r0 + er*8;
                if (r < M) {
                    float v0 = acc[i][j][er*2 + 0];
                    float v1 = acc[i][j][er*2 + 1];
                    h1[(size_t)r*N + c0]     = v0;
                    h1[(size_t)r*N + c0 + 1] = v1;
                    *(__half2*)&h1h[(size_t)r*N + c0] = __floats2half2_rn(v0, v1);
                }
            }
        }
    }

    #pragma unroll
    for (int i = 0; i < MT; i++) {
        #pragma unroll
        for (int er = 0; er < 2; er++) {
            float se = 0.f, de = 0.f;
            #pragma unroll
            for (int j = 0; j < NT; j++) {
                #pragma unroll
                for (int ec = 0; ec < 2; ec++) {
                    int cl = wn*WN + j*8 + 2*lc + ec;
                    float vv = acc[i][j][er*2 + ec];
                    se += vv * s_as[cl];
                    de += vv * s_ad[cl];
                }
            }
            se += __shfl_xor_sync(~0u, se, 1); se += __shfl_xor_sync(~0u, se, 2);
            de += __shfl_xor_sync(~0u, de, 1); de += __shfl_xor_sync(~0u, de, 2);
            int r = row0 + wm*WM + i*16 + lr + er*8;
            if (lc == 0 && r < M) {
                atomicAdd(&es[r*HEADS + h], se);
                atomicAdd(&ed[r*HEADS + h], de);
            }
        }
    }
}

// ---------------- tiny kernels ----------------
__global__ void inv_rowsum(float* __restrict__ rs)
{
    int i = blockIdx.x*blockDim.x + threadIdx.x;
    if (i < NPAIRS_MAP) rs[i] = 1.f / rs[i];
}

__global__ void fill_rowptr(const float* __restrict__ x, unsigned long long* __restrict__ rp)
{
    int i = blockIdx.x*blockDim.x + threadIdx.x;
    if (i < NNODES) rp[i] = (unsigned long long)(x + (size_t)i*FEAT);
}

__global__ void scatter_winner(const int* __restrict__ com_idx, int* __restrict__ winner, int n)
{ int i = blockIdx.x*blockDim.x + threadIdx.x; if (i < n) atomicMax(&winner[com_idx[i]], i); }

__global__ void apply_rowptr(const int* __restrict__ com_idx, const int* __restrict__ winner,
                             const float* __restrict__ fused, unsigned long long* __restrict__ rp, int n)
{
    int p = blockIdx.x*blockDim.x + threadIdx.x;
    if (p >= n) return;
    int node = com_idx[p];
    if (winner[node] == p) rp[node] = (unsigned long long)(fused + (size_t)p*FEAT);
}

// ---------------- CSR build by dst ----------------
__global__ void hist_dst(const int* __restrict__ dst, int* __restrict__ deg, int E)
{ int e = blockIdx.x*blockDim.x + threadIdx.x; if (e < E) atomicAdd(&deg[dst[e]], 1); }

__global__ void scan_deg(const int* __restrict__ deg, int* __restrict__ off,
                         int* __restrict__ cur, int n)
{
    __shared__ int warp_sums[32];
    __shared__ int s_carry;
    int tid = threadIdx.x;
    int lane = tid & 31, w = tid >> 5;
    if (tid == 0) s_carry = 0;
    __syncthreads();
    for (int base = 0; base < n; base += 4096) {
        int i0 = base + tid*4;
        int v0 = (i0   < n) ? deg[i0]   : 0;
        int v1 = (i0+1 < n) ? deg[i0+1] : 0;
        int v2 = (i0+2 < n) ? deg[i0+2] : 0;
        int v3 = (i0+3 < n) ? deg[i0+3] : 0;
        int p1 = v0, p2 = v0+v1, p3 = v0+v1+v2;
        int tsum = p3 + v3;
        int x = tsum;
        #pragma unroll
        for (int o = 1; o < 32; o <<= 1) { int y = __shfl_up_sync(~0u, x, o); if (lane >= o) x += y; }
        if (lane == 31) warp_sums[w] = x;
        __syncthreads();
        if (w == 0) {
            int t = warp_sums[lane];
            #pragma unroll
            for (int o = 1; o < 32; o <<= 1) { int y = __shfl_up_sync(~0u, t, o); if (lane >= o) t += y; }
            warp_sums[lane] = t;
        }
        __syncthreads();
        int warp_off = (w == 0) ? 0 : warp_sums[w-1];
        int excl = x - tsum + warp_off;
        int carry = s_carry;
        if (i0   < n) { int o0 = carry + excl;      off[i0]   = o0; cur[i0]   = o0; }
        if (i0+1 < n) { int o1 = carry + excl + p1; off[i0+1] = o1; cur[i0+1] = o1; }
        if (i0+2 < n) { int o2 = carry + excl + p2; off[i0+2] = o2; cur[i0+2] = o2; }
        if (i0+3 < n) { int o3 = carry + excl + p3; off[i0+3] = o3; cur[i0+3] = o3; }
        __syncthreads();
        if (tid == 0) s_carry = carry + warp_sums[31];
        __syncthreads();
    }
    if (threadIdx.x == 0) off[n] = s_carry;
}

__global__ void scatter_csr(const int* __restrict__ src, const int* __restrict__ dst,
                            int* __restrict__ cur, int* __restrict__ csr, int E)
{
    int e = blockIdx.x*blockDim.x + threadIdx.x;
    if (e >= E) return;
    int pos = atomicAdd(&cur[dst[e]], 1);
    csr[pos] = src[e];
}

// ---------------- mega-fused GAT1 aggregate + ELU + W2 GEMV + node_e2 ----------------
__global__ void __launch_bounds__(256)
gat1_fused(const int* __restrict__ off, const int* __restrict__ csr,
           const float* __restrict__ es, const float* __restrict__ ed,
           const float* __restrict__ h1, const __half* __restrict__ h1h,
           const float* __restrict__ b1,
           const float* __restrict__ W2, const float* __restrict__ as2,
           const float* __restrict__ ad2,
           float* __restrict__ h2, float* __restrict__ es2, float* __restrict__ ed2)
{
    __shared__ float wT[OUTC][H1DIM];
    __shared__ float sb1[H1DIM];
    int tid = threadIdx.x;
    for (int i = tid; i < OUTC*H1DIM; i += 256) {
        int k = i / OUTC, c = i % OUTC;
        wT[c][k] = W2[i];
    }
    for (int i = tid; i < H1DIM; i += 256) sb1[i] = b1[i];
    __syncthreads();

    int lane = tid & 31;
    int d = blockIdx.x*8 + (tid >> 5);
    if (d >= NNODES) return;

    int s0 = off[d], s1 = off[d+1];
    float edv[HEADS], eself[HEADS], m[HEADS];
    #pragma unroll
    for (int h = 0; h < HEADS; h++) {
        edv[h] = ed[d*HEADS + h];
        eself[h] = leaky(es[d*HEADS + h] + edv[h]);
        m[h] = eself[h];
    }
    for (int i = s0 + lane; i < s1; i += 32) {
        int s = csr[i];
        #pragma unroll
        for (int h = 0; h < HEADS; h++)
            m[h] = fmaxf(m[h], leaky(es[s*HEADS + h] + edv[h]));
    }
    #pragma unroll
    for (int h = 0; h < HEADS; h++)
        #pragma unroll
        for (int o = 16; o; o >>= 1) m[h] = fmaxf(m[h], __shfl_xor_sync(~0u, m[h], o));

    float denp[HEADS];
    #pragma unroll
    for (int h = 0; h < HEADS; h++) denp[h] = 0.f;
    float4 acc[3];
    {
        const float4* hp = (const float4*)(h1 + (size_t)d*H1DIM);
        float wself[HEADS];
        #pragma unroll
        for (int h = 0; h < HEADS; h++) wself[h] = __expf(eself[h] - m[h]);
        #pragma unroll
        for (int u = 0; u < 3; u++) {
            float4 hv = hp[lane + 32*u];
            float w = wself[u];
            acc[u].x = hv.x*w; acc[u].y = hv.y*w; acc[u].z = hv.z*w; acc[u].w = hv.w*w;
        }
        if (lane == 0)
            #pragma unroll
            for (int h = 0; h < HEADS; h++) denp[h] += wself[h];
    }
    for (int base = s0; base < s1; base += 32) {
        int i = base + lane;
        int sidx = 0;
        float w[HEADS];
        #pragma unroll
        for (int h = 0; h < HEADS; h++) w[h] = 0.f;
        if (i < s1) {
            sidx = csr[i];
            #pragma unroll
            for (int h = 0; h < HEADS; h++) {
                w[h] = __expf(leaky(es[sidx*HEADS + h] + edv[h]) - m[h]);
                denp[h] += w[h];
            }
        }
        int cnt = min(32, s1 - base);
        #pragma unroll 4
        for (int j = 0; j < cnt; j++) {
            int s  = __shfl_sync(~0u, sidx, j);
            float w0 = __shfl_sync(~0u, w[0], j);
            float w1 = __shfl_sync(~0u, w[1], j);
            float w2 = __shfl_sync(~0u, w[2], j);
            const uint2* sp = (const uint2*)(h1h + (size_t)s*H1DIM);
            uint2 r0 = sp[lane], r1 = sp[lane+32], r2 = sp[lane+64];
            float2 a0 = __half22float2(*(__half2*)&r0.x), b0 = __half22float2(*(__half2*)&r0.y);
            float2 a1 = __half22float2(*(__half2*)&r1.x), b1 = __half22float2(*(__half2*)&r1.y);
            float2 a2 = __half22float2(*(__half2*)&r2.x), b2 = __half22float2(*(__half2*)&r2.y);
            acc[0].x += w0*a0.x; acc[0].y += w0*a0.y; acc[0].z += w0*b0.x; acc[0].w += w0*b0.y;
            acc[1].x += w1*a1.x; acc[1].y += w1*a1.y; acc[1].z += w1*b1.x; acc[1].w += w1*b1.y;
            acc[2].x += w2*a2.x; acc[2].y += w2*a2.y; acc[2].z += w2*b2.x; acc[2].w += w2*b2.y;
        }
    }
    #pragma unroll
    for (int h = 0; h < HEADS; h++)
        #pragma unroll
        for (int o = 16; o; o >>= 1) denp[h] += __shfl_xor_sync(~0u, denp[h], o);
    float inv[HEADS];
    #pragma unroll
    for (int h = 0; h < HEADS; h++) inv[h] = 1.f / (denp[h] + 1e-16f);

    const float4* b4 = (const float4*)sb1;
    float4 v[3];
    #pragma unroll
    for (int u = 0; u < 3; u++) {
        float4 bb = b4[lane + 32*u];
        float iv = inv[u];
        float xx;
        xx = acc[u].x*iv + bb.x; v[u].x = xx > 0.f ? xx : expm1f(xx);
        xx = acc[u].y*iv + bb.y; v[u].y = xx > 0.f ? xx : expm1f(xx);
        xx = acc[u].z*iv + bb.z; v[u].z = xx > 0.f ? xx : expm1f(xx);
        xx = acc[u].w*iv + bb.w; v[u].w = xx > 0.f ? xx : expm1f(xx);
    }
    float hh[OUTC];
    #pragma unroll
    for (int j = 0; j < OUTC; j++) {
        const float4* w4 = (const float4*)wT[j];
        float s = 0.f;
        #pragma unroll
        for (int u = 0; u < 3; u++) {
            float4 wv = w4[lane + 32*u];
            s += v[u].x*wv.x + v[u].y*wv.y + v[u].z*wv.z + v[u].w*wv.w;
        }
        #pragma unroll
        for (int o = 16; o; o >>= 1) s += __shfl_xor_sync(~0u, s, o);
        hh[j] = s;
    }
    if (lane == 0) {
        float s2 = 0.f, d2 = 0.f;
        #pragma unroll
        for (int j = 0; j < OUTC; j++) {
            h2[(size_t)d*OUTC + j] = hh[j];
            s2 += hh[j] * as2[j];
            d2 += hh[j] * ad2[j];
        }
        es2[d] = s2; ed2[d] = d2;
    }
}

// ---------------- fused GAT2 aggregate + bias ----------------
__global__ void __launch_bounds__(256)
gat2_fused(const int* __restrict__ off, const int* __restrict__ csr,
           const float* __restrict__ es, const float* __restrict__ ed,
           const float* __restrict__ h2, const float* __restrict__ b2,
           float* __restrict__ o2)
{
    int lane = threadIdx.x & 31;
    int d = blockIdx.x*8 + (threadIdx.x >> 5);
    if (d >= NNODES) return;
    int s0 = off[d], s1 = off[d+1];
    float edv = ed[d];
    float eself = leaky(es[d] + edv);
    float m = eself;
    for (int i = s0 + lane; i < s1; i += 32)
        m = fmaxf(m, leaky(es[csr[i]] + edv));
    #pragma unroll
    for (int o = 16; o; o >>= 1) m = fmaxf(m, __shfl_xor_sync(~0u, m, o));

    float den = 0.f;
    float acc[OUTC];
    #pragma unroll
    for (int c = 0; c < OUTC; c++) acc[c] = 0.f;
    for (int i = s0 + lane; i < s1; i += 32) {
        int s = csr[i];
        float w = __expf(leaky(es[s] + edv) - m);
        den += w;
        const float* hp = h2 + (size_t)s*OUTC;
        #pragma unroll
        for (int c = 0; c < OUTC; c++) acc[c] += w * hp[c];
    }
    if (lane == 0) {
        float w = __expf(eself - m);
        den += w;
        const float* hp = h2 + (size_t)d*OUTC;
        #pragma unroll
        for (int c = 0; c < OUTC; c++) acc[c] += w * hp[c];
    }
    #pragma unroll
    for (int o = 16; o; o >>= 1) {
        den += __shfl_xor_sync(~0u, den, o);
        #pragma unroll
        for (int c = 0; c < OUTC; c++) acc[c] += __shfl_xor_sync(~0u, acc[c], o);
    }
    if (lane == 0) {
        float inv = 1.f / (den + 1e-16f);
        #pragma unroll
        for (int c = 0; c < OUTC; c++) o2[(size_t)d*OUTC + c] = acc[c]*inv + b2[c];
    }
}

// ---------------- final pair scores ----------------
__global__ void pair_scores(const int* __restrict__ pair, const float* __restrict__ emb,
                            float* __restrict__ out, int n)
{
    int i = blockIdx.x*blockDim.x + threadIdx.x;
    if (i >= n) return;
    int a = pair[2*i], b = pair[2*i+1];
    const float2* ea = (const float2*)(emb + (size_t)a*OUTC);
    const float2* eb = (const float2*)(emb + (size_t)b*OUTC);
    float s = 0.f;
    #pragma unroll
    for (int c = 0; c < 5; c++) {
        float2 x = ea[c], y = eb[c];
        s += x.x*y.x + x.y*y.y;
    }
    out[i] = s;
}

// ---------------- host ----------------
extern "C" void kernel_launch(void* const* d_in, const int* in_sizes, int n_in,
                              void* d_out, int out_size)
{
    const float* fsub   = (const float*)d_in[0];
    const float* fcom   = (const float*)d_in[1];
    const float* x      = (const float*)d_in[2];
    const int*   comidx = (const int*)  d_in[3];
    const int*   edge   = (const int*)  d_in[4];
    const int*   pair   = (const int*)  d_in[5];
    const float* Wq = (const float*)d_in[6];  const float* bq = (const float*)d_in[7];
    const float* Wk = (const float*)d_in[8];  const float* bk = (const float*)d_in[9];
    const float* Wv = (const float*)d_in[10]; const float* bv = (const float*)d_in[11];
    const float* Wf = (const float*)d_in[12]; const float* bf = (const float*)d_in[13];
    const float* W1 = (const float*)d_in[14];
    const float* as1 = (const float*)d_in[15]; const float* ad1 = (const float*)d_in[16];
    const float* b1 = (const float*)d_in[17];
    const float* W2 = (const float*)d_in[18];
    const float* as2 = (const float*)d_in[19]; const float* ad2 = (const float*)d_in[20];
    const float* b2 = (const float*)d_in[21];
    float* out = (float*)d_out;

    const int E = in_sizes[4] / 2;
    const int* src = edge;
    const int* dst = edge + E;
    const int npairs = in_sizes[5] / 2;

    float *q, *k, *v, *S, *rowsum, *attv, *fused, *h1, *es1, *ed1;
    float *h2, *es2, *ed2, *o2;
    __half* h1h;
    int *winner, *deg, *off, *cur, *csr;
    unsigned long long* rowptr;
    cudaGetSymbolAddress((void**)&q, g_q);       cudaGetSymbolAddress((void**)&k, g_k);
    cudaGetSymbolAddress((void**)&v, g_v);       cudaGetSymbolAddress((void**)&S, g_S);
    cudaGetSymbolAddress((void**)&rowsum, g_rowsum);
    cudaGetSymbolAddress((void**)&attv, g_attv); cudaGetSymbolAddress((void**)&fused, g_fused);
    cudaGetSymbolAddress((void**)&rowptr, g_rowptr);
    cudaGetSymbolAddress((void**)&winner, g_winner);
    cudaGetSymbolAddress((void**)&h1, g_h1);     cudaGetSymbolAddress((void**)&h1h, g_h1h);
    cudaGetSymbolAddress((void**)&es1, g_es1);   cudaGetSymbolAddress((void**)&ed1, g_ed1);
    cudaGetSymbolAddress((void**)&h2, g_h2);
    cudaGetSymbolAddress((void**)&es2, g_es2);   cudaGetSymbolAddress((void**)&ed2, g_ed2);
    cudaGetSymbolAddress((void**)&o2, g_o2);
    cudaGetSymbolAddress((void**)&deg, g_deg);   cudaGetSymbolAddress((void**)&off, g_off);
    cudaGetSymbolAddress((void**)&cur, g_cur);   cudaGetSymbolAddress((void**)&csr, g_csr);

    const float inv_sqrt_feat = 0.057735026918962584f;   // 1/sqrt(300)

    // ---- CSR build + rowptr init ----
    cudaMemsetAsync(deg, 0, NNODES*sizeof(int), 0);
    hist_dst<<<(E + 255)/256, 256>>>(dst, deg, E);
    scan_deg<<<1, 1024>>>(deg, off, cur, NNODES);
    scatter_csr<<<(E + 255)/256, 256>>>(src, dst, cur, csr, E);
    fill_rowptr<<<(NNODES + 255)/256, 256>>>(x, rowptr);
    cudaMemsetAsync(winner, 0xFF, NNODES*sizeof(int), 0);
    scatter_winner<<<(NPAIRS_MAP + 255)/256, 256>>>(comidx, winner, NPAIRS_MAP);

    // ---- cross-attention ----
    {
        dim3 grid((FEAT + 127)/128, (NPAIRS_MAP + 127)/128, 3);
        tf32_gemm_qkv<<<grid, 256>>>(fsub, fcom, Wq, bq, Wk, bk, Wv, bv, q, k, v);
    }
    // S_exp = exp(q@k^T/sqrt(FEAT)), rowsum accumulated (max-free: scores are O(1))
    cudaMemsetAsync(rowsum, 0, NPAIRS_MAP*sizeof(float), 0);
    {
        dim3 grid(NPAIRS_MAP/128, NPAIRS_MAP/128);
        tf32_gemm<128,128,2,4,true,false,true,false><<<grid,256>>>(
            q, k, nullptr, nullptr, S, NPAIRS_MAP, NPAIRS_MAP, FEAT, inv_sqrt_feat, 0,
            nullptr, rowsum);
    }
    inv_rowsum<<<(NPAIRS_MAP + 255)/256, 256>>>(rowsum);
    // attv = fsub + softmax(S)@v  (normalize-on-load, split-K atomic accumulate)
    cudaMemcpyAsync(attv, fsub, (size_t)NPAIRS_MAP*FEAT*sizeof(float), cudaMemcpyDeviceToDevice, 0);
    {
        int splits = 8;
        int chunk = ((NPAIRS_MAP/splits + 15)/16)*16;
        dim3 grid((FEAT + 127)/128, NPAIRS_MAP/128, splits);
        tf32_gemm<128,128,2,4,false,true,false,true><<<grid,256>>>(
            S, v, nullptr, nullptr, attv, NPAIRS_MAP, FEAT, NPAIRS_MAP, 1.f, chunk,
            rowsum, nullptr);
    }
    {
        dim3 grid((FEAT + 127)/128, (NPAIRS_MAP + 127)/128);
        tf32_gemm<128,128,2,4,false,false,false,false><<<grid,256>>>(
            attv, Wf, bf, nullptr, fused, NPAIRS_MAP, FEAT, FEAT, 1.f, 0, nullptr, nullptr);
    }

    // ---- substitute fused rows via row pointers ----
    apply_rowptr<<<(NPAIRS_MAP + 255)/256, 256>>>(comidx, winner, fused, rowptr, NPAIRS_MAP);

    // ---- GAT layer 1 ----
    cudaMemsetAsync(es1, 0, NNODES*HEADS*sizeof(float), 0);
    cudaMemsetAsync(ed1, 0, NNODES*HEADS*sizeof(float), 0);
    {
        dim3 grid(HEADS, (NNODES + 127)/128);
        tf32_gemm_w1<<<grid, 256>>>(rowptr, W1, as1, ad1, h1, h1h, es1, ed1);
    }
    gat1_fused<<<(NNODES + 7)/8, 256>>>(off, csr, es1, ed1, h1, h1h, b1, W2, as2, ad2,
                                        h2, es2, ed2);

    // ---- GAT layer 2 ----
    gat2_fused<<<(NNODES + 7)/8, 256>>>(off, csr, es2, ed2, h2, b2, o2);

    // ---- pair scores ----
    pair_scores<<<(npairs + 255)/256, 256>>>(pair, o2, out, npairs);
}

// round 12
// speedup vs baseline: 3.6304x; 1.1982x over previous
#include <cuda_runtime.h>
#include <cuda_fp16.h>
#include <math.h>
#include <stdint.h>

// ---------------- problem constants ----------------
#define NPAIRS_MAP 4096
#define NNODES     50000
#define MAXEDGES   524288
#define FEAT       300
#define HID        128
#define HEADS      3
#define OUTC       10
#define H1DIM      (HEADS*HID)   // 384

// ---------------- scratch ----------------
__device__ float  g_q[NPAIRS_MAP*FEAT];
__device__ float  g_k[NPAIRS_MAP*FEAT];
__device__ float  g_v[NPAIRS_MAP*FEAT];
__device__ __half g_S[(size_t)NPAIRS_MAP*NPAIRS_MAP];
__device__ float  g_rowsum[NPAIRS_MAP];
__device__ float  g_attv[NPAIRS_MAP*FEAT];
__device__ float  g_fused[NPAIRS_MAP*FEAT];
__device__ unsigned long long g_rowptr[NNODES];
__device__ int    g_winner[NNODES];
__device__ __half g_h1h[(size_t)NNODES*H1DIM];
__device__ float  g_es1[NNODES*HEADS];
__device__ float  g_ed1[NNODES*HEADS];
__device__ float  g_h2[NNODES*OUTC];
__device__ float  g_es2[NNODES];
__device__ float  g_ed2[NNODES];
__device__ float  g_o2[NNODES*OUTC];
__device__ int    g_deg[NNODES];
__device__ int    g_off[NNODES+1];
__device__ int    g_cur[NNODES];
__device__ int    g_csr[MAXEDGES];

// ---------------- helpers ----------------
__device__ __forceinline__ void mma_f16(float* c, const uint32_t* a, const uint32_t* b) {
    asm volatile("mma.sync.aligned.m16n8k16.row.col.f32.f16.f16.f32 "
        "{%0,%1,%2,%3}, {%4,%5,%6,%7}, {%8,%9}, {%0,%1,%2,%3};"
        : "+f"(c[0]), "+f"(c[1]), "+f"(c[2]), "+f"(c[3])
        : "r"(a[0]), "r"(a[1]), "r"(a[2]), "r"(a[3]), "r"(b[0]), "r"(b[1]));
}

__device__ __forceinline__ float leaky(float v) { return v > 0.f ? v : 0.2f*v; }

// ---------------- loaders: 32 k-values per tile, packed as 16 half2 slots ----------------
// slot layout: s[p][row], p = k/2 (0..15); each uint32 = half2 {k=2p, k=2p+1}
template<int ROWS, int IT, bool IND, bool SC, bool HALFA>
__device__ __forceinline__ void ld16(const void* __restrict__ Av,
                                     const unsigned long long* __restrict__ rowp,
                                     const float* __restrict__ rsc,
                                     int nrows, int ld, int row0, int k0, int kmax,
                                     int tid, uint32_t (&reg)[IT][8])
{
    #pragma unroll
    for (int i = 0; i < IT; i++) {
        int idx = tid + i*256;
        #pragma unroll
        for (int j = 0; j < 8; j++) reg[i][j] = 0u;
        if (idx < ROWS*2) {
            int r = idx >> 1, seg = idx & 1;
            int gr = row0 + r, gk = k0 + seg*16;
            if (gr < nrows && gk < kmax) {
                float sc = SC ? rsc[gr] : 1.f;
                if (!HALFA) {
                    const float* base = IND ? (const float*)rowp[gr]
                                            : (const float*)Av + (size_t)gr*ld;
                    const float* p = base + gk;
                    float f[16];
                    if (gk + 16 <= kmax) {
                        #pragma unroll
                        for (int qq = 0; qq < 4; qq++) {
                            float4 vv = *(const float4*)(p + qq*4);
                            f[qq*4+0]=vv.x; f[qq*4+1]=vv.y; f[qq*4+2]=vv.z; f[qq*4+3]=vv.w;
                        }
                    } else {
                        #pragma unroll
                        for (int j = 0; j < 16; j++) f[j] = (gk + j < kmax) ? p[j] : 0.f;
                    }
                    #pragma unroll
                    for (int j = 0; j < 8; j++) {
                        __half2 hv = __floats2half2_rn(f[2*j]*sc, f[2*j+1]*sc);
                        reg[i][j] = *(uint32_t*)&hv;
                    }
                } else {
                    const __half* p = (const __half*)Av + (size_t)gr*ld + gk;
                    if (gk + 16 <= kmax) {
                        uint4 v0 = *(const uint4*)p;
                        uint4 v1 = *(const uint4*)(p+8);
                        uint32_t raw[8] = {v0.x,v0.y,v0.z,v0.w,v1.x,v1.y,v1.z,v1.w};
                        if (!SC) {
                            #pragma unroll
                            for (int j = 0; j < 8; j++) reg[i][j] = raw[j];
                        } else {
                            #pragma unroll
                            for (int j = 0; j < 8; j++) {
                                float2 ff = __half22float2(*(__half2*)&raw[j]);
                                __half2 hv = __floats2half2_rn(ff.x*sc, ff.y*sc);
                                reg[i][j] = *(uint32_t*)&hv;
                            }
                        }
                    } else {
                        #pragma unroll
                        for (int j = 0; j < 8; j++) {
                            float f0 = (gk+2*j   < kmax) ? __half2float(p[2*j])  *sc : 0.f;
                            float f1 = (gk+2*j+1 < kmax) ? __half2float(p[2*j+1])*sc : 0.f;
                            __half2 hv = __floats2half2_rn(f0, f1);
                            reg[i][j] = *(uint32_t*)&hv;
                        }
                    }
                }
            }
        }
    }
}

template<int ROWS, int STR, int IT>
__device__ __forceinline__ void sts16(uint32_t* __restrict__ s, int tid,
                                      const uint32_t (&reg)[IT][8])
{
    #pragma unroll
    for (int i = 0; i < IT; i++) {
        int idx = tid + i*256;
        if (idx < ROWS*2) {
            int r = idx >> 1, seg = idx & 1;
            #pragma unroll
            for (int j = 0; j < 8; j++)
                s[(seg*8 + j)*STR + r] = reg[i][j];
        }
    }
}

// non-transposed B [K][N] row-major -> sB[p][n] = half2{B[2p][n], B[2p+1][n]}
template<int BN>
__device__ __forceinline__ void ldB16_n(const float* __restrict__ B, int N, int k0, int kmax,
                                        int col0, int tid, uint32_t (&reg)[8])
{
    #pragma unroll
    for (int j = 0; j < 8; j++) reg[j] = 0u;
    int p = tid >> 4, f0 = tid & 15;
    int gk0 = k0 + 2*p, gk1 = gk0 + 1;
    if (gk0 < kmax) {
        bool ok1 = gk1 < kmax;
        #pragma unroll
        for (int it = 0; it < BN/64; it++) {
            int gc = col0 + (f0 + it*16)*4;
            if (gc < N) {
                const float* b0 = B + (size_t)gk0*N + gc;
                const float* b1 = B + (size_t)gk1*N + gc;
                float4 r0, r1;
                if (gc + 4 <= N) r0 = *(const float4*)b0;
                else r0 = make_float4(b0[0], gc+1<N?b0[1]:0.f, gc+2<N?b0[2]:0.f, gc+3<N?b0[3]:0.f);
                if (ok1) {
                    if (gc + 4 <= N) r1 = *(const float4*)b1;
                    else r1 = make_float4(b1[0], gc+1<N?b1[1]:0.f, gc+2<N?b1[2]:0.f, gc+3<N?b1[3]:0.f);
                } else r1 = make_float4(0.f,0.f,0.f,0.f);
                __half2 h0 = __floats2half2_rn(r0.x, r1.x);
                __half2 h1 = __floats2half2_rn(r0.y, r1.y);
                __half2 h2 = __floats2half2_rn(r0.z, r1.z);
                __half2 h3 = __floats2half2_rn(r0.w, r1.w);
                reg[it*4+0] = *(uint32_t*)&h0; reg[it*4+1] = *(uint32_t*)&h1;
                reg[it*4+2] = *(uint32_t*)&h2; reg[it*4+3] = *(uint32_t*)&h3;
            }
        }
    }
}

template<int BN, int STR>
__device__ __forceinline__ void stsB16_n(uint32_t* __restrict__ s, int tid, const uint32_t (&reg)[8])
{
    int p = tid >> 4, f0 = tid & 15;
    #pragma unroll
    for (int it = 0; it < BN/64; it++)
        *(uint4*)&s[p*STR + (f0 + it*16)*4] =
            make_uint4(reg[it*4+0], reg[it*4+1], reg[it*4+2], reg[it*4+3]);
}

// ---------------- FP16 GEMM body (k-tile = 32) ----------------
template<int BM, int BN, int WARPS_M, int WARPS_N,
         bool TRANSB, bool SPLITK, bool EXPOUT, bool SCALEA, bool HALFA>
__device__ __forceinline__ void gemm16_body(
          const void* __restrict__ A, const float* __restrict__ Bf,
          const float* __restrict__ bias, const float* __restrict__ resid,
          float* __restrict__ C, __half* __restrict__ Ch,
          int M, int N, int K, float scale, int kchunk,
          const float* __restrict__ rowscale, float* __restrict__ rowsum,
          const unsigned long long* __restrict__ rowp)
{
    constexpr int ASTR = BM + 8, BSTR = BN + 8;
    constexpr int WM = BM / WARPS_M, WN = BN / WARPS_N;
    constexpr int MT = WM / 16, NT = WN / 8;
    constexpr int A_IT = (BM*2 + 255)/256;
    constexpr int B_IT = (BN*2 + 255)/256;

    __shared__ uint32_t sA[2*16*ASTR];
    __shared__ uint32_t sB[2*16*BSTR];

    int tid = threadIdx.x, lane = tid & 31, warp = tid >> 5;
    int wm = warp % WARPS_M, wn = warp / WARPS_M;
    int row0 = blockIdx.y * BM, col0 = blockIdx.x * BN;
    int lr = lane >> 2, lc = lane & 3;

    int kb = SPLITK ? blockIdx.z * kchunk : 0;
    int ke = SPLITK ? min(K, kb + kchunk) : K;
    int ntiles = (ke - kb + 31) / 32;
    if (ntiles <= 0) return;

    float acc[MT][NT][4];
    #pragma unroll
    for (int i = 0; i < MT; i++)
        #pragma unroll
        for (int j = 0; j < NT; j++)
            #pragma unroll
            for (int e = 0; e < 4; e++) acc[i][j][e] = 0.f;

    uint32_t areg[A_IT][8];
    uint32_t bregT[B_IT][8];
    uint32_t bregN[8];

    constexpr bool INDA = false;   // generic path; W1 kernel handles IND separately
    ld16<BM, A_IT, INDA, SCALEA, HALFA>(A, rowp, rowscale, M, K, row0, kb, ke, tid, areg);
    if (TRANSB) ld16<BN, B_IT, false, false, false>(Bf, nullptr, nullptr, N, K, col0, kb, ke, tid, bregT);
    else        ldB16_n<BN>(Bf, N, kb, ke, col0, tid, bregN);
    sts16<BM, ASTR, A_IT>(sA, tid, areg);
    if (TRANSB) sts16<BN, BSTR, B_IT>(sB, tid, bregT);
    else        stsB16_n<BN, BSTR>(sB, tid, bregN);
    __syncthreads();

    int buf = 0;
    for (int t = 0; t < ntiles; t++) {
        bool more = (t + 1 < ntiles);
        if (more) {
            int k0 = kb + (t+1)*32;
            ld16<BM, A_IT, INDA, SCALEA, HALFA>(A, rowp, rowscale, M, K, row0, k0, ke, tid, areg);
            if (TRANSB) ld16<BN, B_IT, false, false, false>(Bf, nullptr, nullptr, N, K, col0, k0, ke, tid, bregT);
            else        ldB16_n<BN>(Bf, N, k0, ke, col0, tid, bregN);
        }
        const uint32_t* pA = sA + buf*16*ASTR;
        const uint32_t* pB = sB + buf*16*BSTR;
        #pragma unroll
        for (int ks = 0; ks < 2; ks++) {
            int kk = ks*8;
            uint32_t af[MT][4];
            #pragma unroll
            for (int i = 0; i < MT; i++) {
                int m0 = wm*WM + i*16;
                af[i][0] = pA[(kk+lc  )*ASTR + m0 + lr];
                af[i][1] = pA[(kk+lc  )*ASTR + m0 + lr + 8];
                af[i][2] = pA[(kk+lc+4)*ASTR + m0 + lr];
                af[i][3] = pA[(kk+lc+4)*ASTR + m0 + lr + 8];
            }
            uint32_t bf2[NT][2];
            #pragma unroll
            for (int j = 0; j < NT; j++) {
                int n0 = wn*WN + j*8;
                bf2[j][0] = pB[(kk+lc  )*BSTR + n0 + lr];
                bf2[j][1] = pB[(kk+lc+4)*BSTR + n0 + lr];
            }
            #pragma unroll
            for (int i = 0; i < MT; i++)
                #pragma unroll
                for (int j = 0; j < NT; j++)
                    mma_f16(acc[i][j], af[i], bf2[j]);
        }
        if (more) {
            sts16<BM, ASTR, A_IT>(sA + (buf^1)*16*ASTR, tid, areg);
            if (TRANSB) sts16<BN, BSTR, B_IT>(sB + (buf^1)*16*BSTR, tid, bregT);
            else        stsB16_n<BN, BSTR>(sB + (buf^1)*16*BSTR, tid, bregN);
        }
        __syncthreads();
        buf ^= 1;
    }

    #pragma unroll
    for (int i = 0; i < MT; i++) {
        int r0 = row0 + wm*WM + i*16 + lr;
        #pragma unroll
        for (int er = 0; er < 2; er++) {
            int r = r0 + er*8;
            float rsum = 0.f;
            #pragma unroll
            for (int j = 0; j < NT; j++) {
                int c0 = col0 + wn*WN + j*8 + 2*lc;
                float v0 = acc[i][j][er*2+0] * scale;
                float v1 = acc[i][j][er*2+1] * scale;
                if (EXPOUT) {
                    if (r < M) {
                        v0 = __expf(v0); v1 = __expf(v1);
                        rsum += v0 + v1;
                        *(__half2*)&Ch[(size_t)r*N + c0] = __floats2half2_rn(v0, v1);
                    }
                } else if (SPLITK) {
                    if (r < M && c0   < N) atomicAdd(&C[(size_t)r*N + c0],   v0);
                    if (r < M && c0+1 < N) atomicAdd(&C[(size_t)r*N + c0+1], v1);
                } else {
                    if (r < M && c0 < N) {
                        float v = v0;
                        if (bias)  v += bias[c0];
                        if (resid) v += resid[(size_t)r*N + c0];
                        C[(size_t)r*N + c0] = v;
                    }
                    if (r < M && c0+1 < N) {
                        float v = v1;
                        if (bias)  v += bias[c0+1];
                        if (resid) v += resid[(size_t)r*N + c0+1];
                        C[(size_t)r*N + c0+1] = v;
                    }
                }
            }
            if (EXPOUT) {
                rsum += __shfl_xor_sync(~0u, rsum, 1);
                rsum += __shfl_xor_sync(~0u, rsum, 2);
                if (lc == 0 && r < M) atomicAdd(&rowsum[r], rsum);
            }
        }
    }
}

template<int BM, int BN, int WARPS_M, int WARPS_N,
         bool TRANSB, bool SPLITK, bool EXPOUT, bool SCALEA, bool HALFA>
__global__ void __launch_bounds__(256)
f16_gemm(const void* __restrict__ A, const float* __restrict__ Bf,
         const float* __restrict__ bias, const float* __restrict__ resid,
         float* __restrict__ C, __half* __restrict__ Ch,
         int M, int N, int K, float scale, int kchunk,
         const float* __restrict__ rowscale, float* __restrict__ rowsum)
{
    gemm16_body<BM,BN,WARPS_M,WARPS_N,TRANSB,SPLITK,EXPOUT,SCALEA,HALFA>(
        A,Bf,bias,resid,C,Ch,M,N,K,scale,kchunk,rowscale,rowsum,nullptr);
}

// batched QKV
__global__ void __launch_bounds__(256)
f16_gemm_qkv(const float* __restrict__ fsub, const float* __restrict__ fcom,
             const float* __restrict__ Wq, const float* __restrict__ bq,
             const float* __restrict__ Wk, const float* __restrict__ bk,
             const float* __restrict__ Wv, const float* __restrict__ bv,
             float* __restrict__ q, float* __restrict__ k, float* __restrict__ v)
{
    const float* A; const float* B; const float* bias; float* C;
    if (blockIdx.z == 0)      { A = fsub; B = Wq; bias = bq; C = q; }
    else if (blockIdx.z == 1) { A = fcom; B = Wk; bias = bk; C = k; }
    else                      { A = fcom; B = Wv; bias = bv; C = v; }
    gemm16_body<128,128,2,4,false,false,false,false,false>(
        A, B, bias, nullptr, C, nullptr, NPAIRS_MAP, FEAT, FEAT, 1.f, 0, nullptr, nullptr, nullptr);
}

// ---------------- X@W1 GEMM, indirect rows, fused node_e1 + fp16 h1 ----------------
__global__ void __launch_bounds__(256)
f16_gemm_w1(const unsigned long long* __restrict__ rowp, const float* __restrict__ W1,
            const float* __restrict__ as1, const float* __restrict__ ad1,
            __half* __restrict__ h1h, float* __restrict__ es, float* __restrict__ ed)
{
    constexpr int BM = 128, BN = 128;
    constexpr int WARPS_M = 2, WARPS_N = 4;
    constexpr int ASTR = BM + 8, BSTR = BN + 8;
    constexpr int WM = BM / WARPS_M, WN = BN / WARPS_N;
    constexpr int MT = WM / 16, NT = WN / 8;
    constexpr int M = NNODES, N = H1DIM, K = FEAT;

    __shared__ uint32_t sA[2*16*ASTR];
    __shared__ uint32_t sB[2*16*BSTR];
    __shared__ float s_as[HID], s_ad[HID];

    int tid = threadIdx.x, lane = tid & 31, warp = tid >> 5;
    int wm = warp % WARPS_M, wn = warp / WARPS_M;
    int row0 = blockIdx.y * BM, col0 = blockIdx.x * BN;
    int h = blockIdx.x;
    int lr = lane >> 2, lc = lane & 3;

    if (tid < HID) { s_as[tid] = as1[h*HID + tid]; s_ad[tid] = ad1[h*HID + tid]; }

    float acc[MT][NT][4];
    #pragma unroll
    for (int i = 0; i < MT; i++)
        #pragma unroll
        for (int j = 0; j < NT; j++)
            #pragma unroll
            for (int e = 0; e < 4; e++) acc[i][j][e] = 0.f;

    int ntiles = (K + 31) / 32;
    uint32_t areg[1][8];
    uint32_t bregN[8];

    ld16<BM, 1, true, false, false>(nullptr, rowp, nullptr, M, K, row0, 0, K, tid, areg);
    ldB16_n<BN>(W1, N, 0, K, col0, tid, bregN);
    sts16<BM, ASTR, 1>(sA, tid, areg);
    stsB16_n<BN, BSTR>(sB, tid, bregN);
    __syncthreads();

    int buf = 0;
    for (int t = 0; t < ntiles; t++) {
        bool more = (t + 1 < ntiles);
        if (more) {
            int k0 = (t+1)*32;
            ld16<BM, 1, true, false, false>(nullptr, rowp, nullptr, M, K, row0, k0, K, tid, areg);
            ldB16_n<BN>(W1, N, k0, K, col0, tid, bregN);
        }
        const uint32_t* pA = sA + buf*16*ASTR;
        const uint32_t* pB = sB + buf*16*BSTR;
        #pragma unroll
        for (int ks = 0; ks < 2; ks++) {
            int kk = ks*8;
            uint32_t af[MT][4];
            #pragma unroll
            for (int i = 0; i < MT; i++) {
                int m0 = wm*WM + i*16;
                af[i][0] = pA[(kk+lc  )*ASTR + m0 + lr];
                af[i][1] = pA[(kk+lc  )*ASTR + m0 + lr + 8];
                af[i][2] = pA[(kk+lc+4)*ASTR + m0 + lr];
                af[i][3] = pA[(kk+lc+4)*ASTR + m0 + lr + 8];
            }
            uint32_t bf2[NT][2];
            #pragma unroll
            for (int j = 0; j < NT; j++) {
                int n0 = wn*WN + j*8;
                bf2[j][0] = pB[(kk+lc  )*BSTR + n0 + lr];
                bf2[j][1] = pB[(kk+lc+4)*BSTR + n0 + lr];
            }
            #pragma unroll
            for (int i = 0; i < MT; i++)
                #pragma unroll
                for (int j = 0; j < NT; j++)
                    mma_f16(acc[i][j], af[i], bf2[j]);
        }
        if (more) {
            sts16<BM, ASTR, 1>(sA + (buf^1)*16*ASTR, tid, areg);
            stsB16_n<BN, BSTR>(sB + (buf^1)*16*BSTR, tid, bregN);
        }
        __syncthreads();
        buf ^= 1;
    }

    // write h1h (fp16)
    #pragma unroll
    for (int i = 0; i < MT; i++) {
        int r0 = row0 + wm*WM + i*16 + lr;
        #pragma unroll
        for (int j = 0; j < NT; j++) {
            int c0 = col0 + wn*WN + j*8 + 2*lc;
            #pragma unroll
            for (int er = 0; er < 2; er++) {
                int r = r0 + er*8;
                if (r < M)
                    *(__half2*)&h1h[(size_t)r*N + c0] =
                        __floats2half2_rn(acc[i][j][er*2+0], acc[i][j][er*2+1]);
            }
        }
    }

    // fused node_e1
    #pragma unroll
    for (int i = 0; i < MT; i++) {
        #pragma unroll
        for (int er = 0; er < 2; er++) {
            float se = 0.f, de = 0.f;
            #pragma unroll
            for (int j = 0; j < NT; j++) {
                #pragma unroll
                for (int ec = 0; ec < 2; ec++) {
                    int cl = wn*WN + j*8 + 2*lc + ec;
                    float vv = acc[i][j][er*2 + ec];
                    se += vv * s_as[cl];
                    de += vv * s_ad[cl];
                }
            }
            se += __shfl_xor_sync(~0u, se, 1); se += __shfl_xor_sync(~0u, se, 2);
            de += __shfl_xor_sync(~0u, de, 1); de += __shfl_xor_sync(~0u, de, 2);
            int r = row0 + wm*WM + i*16 + lr + er*8;
            if (lc == 0 && r < M) {
                atomicAdd(&es[r*HEADS + h], se);
                atomicAdd(&ed[r*HEADS + h], de);
            }
        }
    }
}

// ---------------- tiny kernels ----------------
__global__ void inv_rowsum(float* __restrict__ rs)
{
    int i = blockIdx.x*blockDim.x + threadIdx.x;
    if (i < NPAIRS_MAP) rs[i] = 1.f / rs[i];
}

__global__ void fill_rowptr(const float* __restrict__ x, unsigned long long* __restrict__ rp)
{
    int i = blockIdx.x*blockDim.x + threadIdx.x;
    if (i < NNODES) rp[i] = (unsigned long long)(x + (size_t)i*FEAT);
}

__global__ void scatter_winner(const int* __restrict__ com_idx, int* __restrict__ winner, int n)
{ int i = blockIdx.x*blockDim.x + threadIdx.x; if (i < n) atomicMax(&winner[com_idx[i]], i); }

__global__ void apply_rowptr(const int* __restrict__ com_idx, const int* __restrict__ winner,
                             const float* __restrict__ fused, unsigned long long* __restrict__ rp, int n)
{
    int p = blockIdx.x*blockDim.x + threadIdx.x;
    if (p >= n) return;
    int node = com_idx[p];
    if (winner[node] == p) rp[node] = (unsigned long long)(fused + (size_t)p*FEAT);
}

// ---------------- CSR build by dst ----------------
__global__ void hist_dst(const int* __restrict__ dst, int* __restrict__ deg, int E)
{ int e = blockIdx.x*blockDim.x + threadIdx.x; if (e < E) atomicAdd(&deg[dst[e]], 1); }

__global__ void scan_deg(const int* __restrict__ deg, int* __restrict__ off,
                         int* __restrict__ cur, int n)
{
    __shared__ int warp_sums[32];
    __shared__ int s_carry;
    int tid = threadIdx.x;
    int lane = tid & 31, w = tid >> 5;
    if (tid == 0) s_carry = 0;
    __syncthreads();
    for (int base = 0; base < n; base += 4096) {
        int i0 = base + tid*4;
        int v0 = (i0   < n) ? deg[i0]   : 0;
        int v1 = (i0+1 < n) ? deg[i0+1] : 0;
        int v2 = (i0+2 < n) ? deg[i0+2] : 0;
        int v3 = (i0+3 < n) ? deg[i0+3] : 0;
        int p1 = v0, p2 = v0+v1, p3 = v0+v1+v2;
        int tsum = p3 + v3;
        int x = tsum;
        #pragma unroll
        for (int o = 1; o < 32; o <<= 1) { int y = __shfl_up_sync(~0u, x, o); if (lane >= o) x += y; }
        if (lane == 31) warp_sums[w] = x;
        __syncthreads();
        if (w == 0) {
            int t = warp_sums[lane];
            #pragma unroll
            for (int o = 1; o < 32; o <<= 1) { int y = __shfl_up_sync(~0u, t, o); if (lane >= o) t += y; }
            warp_sums[lane] = t;
        }
        __syncthreads();
        int warp_off = (w == 0) ? 0 : warp_sums[w-1];
        int excl = x - tsum + warp_off;
        int carry = s_carry;
        if (i0   < n) { int o0 = carry + excl;      off[i0]   = o0; cur[i0]   = o0; }
        if (i0+1 < n) { int o1 = carry + excl + p1; off[i0+1] = o1; cur[i0+1] = o1; }
        if (i0+2 < n) { int o2 = carry + excl + p2; off[i0+2] = o2; cur[i0+2] = o2; }
        if (i0+3 < n) { int o3 = carry + excl + p3; off[i0+3] = o3; cur[i0+3] = o3; }
        __syncthreads();
        if (tid == 0) s_carry = carry + warp_sums[31];
        __syncthreads();
    }
    if (threadIdx.x == 0) off[n] = s_carry;
}

__global__ void scatter_csr(const int* __restrict__ src, const int* __restrict__ dst,
                            int* __restrict__ cur, int* __restrict__ csr, int E)
{
    int e = blockIdx.x*blockDim.x + threadIdx.x;
    if (e >= E) return;
    int pos = atomicAdd(&cur[dst[e]], 1);
    csr[pos] = src[e];
}

// ---------------- mega-fused GAT1 aggregate + ELU + W2 GEMV + node_e2 ----------------
__global__ void __launch_bounds__(256)
gat1_fused(const int* __restrict__ off, const int* __restrict__ csr,
           const float* __restrict__ es, const float* __restrict__ ed,
           const __half* __restrict__ h1h, const float* __restrict__ b1,
           const float* __restrict__ W2, const float* __restrict__ as2,
           const float* __restrict__ ad2,
           float* __restrict__ h2, float* __restrict__ es2, float* __restrict__ ed2)
{
    __shared__ float wT[OUTC][H1DIM];
    __shared__ float sb1[H1DIM];
    int tid = threadIdx.x;
    for (int i = tid; i < OUTC*H1DIM; i += 256) {
        int k = i / OUTC, c = i % OUTC;
        wT[c][k] = W2[i];
    }
    for (int i = tid; i < H1DIM; i += 256) sb1[i] = b1[i];
    __syncthreads();

    int lane = tid & 31;
    int d = blockIdx.x*8 + (tid >> 5);
    if (d >= NNODES) return;

    int s0 = off[d], s1 = off[d+1];
    float edv[HEADS], eself[HEADS], m[HEADS];
    #pragma unroll
    for (int h = 0; h < HEADS; h++) {
        edv[h] = ed[d*HEADS + h];
        eself[h] = leaky(es[d*HEADS + h] + edv[h]);
        m[h] = eself[h];
    }
    for (int i = s0 + lane; i < s1; i += 32) {
        int s = csr[i];
        #pragma unroll
        for (int h = 0; h < HEADS; h++)
            m[h] = fmaxf(m[h], leaky(es[s*HEADS + h] + edv[h]));
    }
    #pragma unroll
    for (int h = 0; h < HEADS; h++)
        #pragma unroll
        for (int o = 16; o; o >>= 1) m[h] = fmaxf(m[h], __shfl_xor_sync(~0u, m[h], o));

    float denp[HEADS];
    #pragma unroll
    for (int h = 0; h < HEADS; h++) denp[h] = 0.f;
    float4 acc[3];
    {   // self-loop (fp16 row)
        float wself[HEADS];
        #pragma unroll
        for (int h = 0; h < HEADS; h++) wself[h] = __expf(eself[h] - m[h]);
        const uint2* hp = (const uint2*)(h1h + (size_t)d*H1DIM);
        uint2 q0 = hp[lane], q1 = hp[lane+32], q2 = hp[lane+64];
        float2 a0 = __half22float2(*(__half2*)&q0.x), c0 = __half22float2(*(__half2*)&q0.y);
        float2 a1 = __half22float2(*(__half2*)&q1.x), c1 = __half22float2(*(__half2*)&q1.y);
        float2 a2 = __half22float2(*(__half2*)&q2.x), c2 = __half22float2(*(__half2*)&q2.y);
        acc[0].x = wself[0]*a0.x; acc[0].y = wself[0]*a0.y; acc[0].z = wself[0]*c0.x; acc[0].w = wself[0]*c0.y;
        acc[1].x = wself[1]*a1.x; acc[1].y = wself[1]*a1.y; acc[1].z = wself[1]*c1.x; acc[1].w = wself[1]*c1.y;
        acc[2].x = wself[2]*a2.x; acc[2].y = wself[2]*a2.y; acc[2].z = wself[2]*c2.x; acc[2].w = wself[2]*c2.y;
        if (lane == 0)
            #pragma unroll
            for (int h = 0; h < HEADS; h++) denp[h] += wself[h];
    }
    for (int base = s0; base < s1; base += 32) {
        int i = base + lane;
        int sidx = 0;
        float w[HEADS];
        #pragma unroll
        for (int h = 0; h < HEADS; h++) w[h] = 0.f;
        if (i < s1) {
            sidx = csr[i];
            #pragma unroll
            for (int h = 0; h < HEADS; h++) {
                w[h] = __expf(leaky(es[sidx*HEADS + h] + edv[h]) - m[h]);
                denp[h] += w[h];
            }
        }
        int cnt = min(32, s1 - base);
        #pragma unroll 4
        for (int j = 0; j < cnt; j++) {
            int s  = __shfl_sync(~0u, sidx, j);
            float w0 = __shfl_sync(~0u, w[0], j);
            float w1 = __shfl_sync(~0u, w[1], j);
            float w2 = __shfl_sync(~0u, w[2], j);
            const uint2* sp = (const uint2*)(h1h + (size_t)s*H1DIM);
            uint2 r0 = sp[lane], r1 = sp[lane+32], r2 = sp[lane+64];
            float2 a0 = __half22float2(*(__half2*)&r0.x), b0 = __half22float2(*(__half2*)&r0.y);
            float2 a1 = __half22float2(*(__half2*)&r1.x), b1 = __half22float2(*(__half2*)&r1.y);
            float2 a2 = __half22float2(*(__half2*)&r2.x), b2 = __half22float2(*(__half2*)&r2.y);
            acc[0].x += w0*a0.x; acc[0].y += w0*a0.y; acc[0].z += w0*b0.x; acc[0].w += w0*b0.y;
            acc[1].x += w1*a1.x; acc[1].y += w1*a1.y; acc[1].z += w1*b1.x; acc[1].w += w1*b1.y;
            acc[2].x += w2*a2.x; acc[2].y += w2*a2.y; acc[2].z += w2*b2.x; acc[2].w += w2*b2.y;
        }
    }
    #pragma unroll
    for (int h = 0; h < HEADS; h++)
        #pragma unroll
        for (int o = 16; o; o >>= 1) denp[h] += __shfl_xor_sync(~0u, denp[h], o);
    float inv[HEADS];
    #pragma unroll
    for (int h = 0; h < HEADS; h++) inv[h] = 1.f / (denp[h] + 1e-16f);

    const float4* b4 = (const float4*)sb1;
    float4 v[3];
    #pragma unroll
    for (int u = 0; u < 3; u++) {
        float4 bb = b4[lane + 32*u];
        float iv = inv[u];
        float xx;
        xx = acc[u].x*iv + bb.x; v[u].x = xx > 0.f ? xx : expm1f(xx);
        xx = acc[u].y*iv + bb.y; v[u].y = xx > 0.f ? xx : expm1f(xx);
        xx = acc[u].z*iv + bb.z; v[u].z = xx > 0.f ? xx : expm1f(xx);
        xx = acc[u].w*iv + bb.w; v[u].w = xx > 0.f ? xx : expm1f(xx);
    }
    float hh[OUTC];
    #pragma unroll
    for (int j = 0; j < OUTC; j++) {
        const float4* w4 = (const float4*)wT[j];
        float s = 0.f;
        #pragma unroll
        for (int u = 0; u < 3; u++) {
            float4 wv = w4[lane + 32*u];
            s += v[u].x*wv.x + v[u].y*wv.y + v[u].z*wv.z + v[u].w*wv.w;
        }
        #pragma unroll
        for (int o = 16; o; o >>= 1) s += __shfl_xor_sync(~0u, s, o);
        hh[j] = s;
    }
    if (lane == 0) {
        float s2 = 0.f, d2 = 0.f;
        #pragma unroll
        for (int j = 0; j < OUTC; j++) {
            h2[(size_t)d*OUTC + j] = hh[j];
            s2 += hh[j] * as2[j];
            d2 += hh[j] * ad2[j];
        }
        es2[d] = s2; ed2[d] = d2;
    }
}

// ---------------- fused GAT2 aggregate + bias ----------------
__global__ void __launch_bounds__(256)
gat2_fused(const int* __restrict__ off, const int* __restrict__ csr,
           const float* __restrict__ es, const float* __restrict__ ed,
           const float* __restrict__ h2, const float* __restrict__ b2,
           float* __restrict__ o2)
{
    int lane = threadIdx.x & 31;
    int d = blockIdx.x*8 + (threadIdx.x >> 5);
    if (d >= NNODES) return;
    int s0 = off[d], s1 = off[d+1];
    float edv = ed[d];
    float eself = leaky(es[d] + edv);
    float m = eself;
    for (int i = s0 + lane; i < s1; i += 32)
        m = fmaxf(m, leaky(es[csr[i]] + edv));
    #pragma unroll
    for (int o = 16; o; o >>= 1) m = fmaxf(m, __shfl_xor_sync(~0u, m, o));

    float den = 0.f;
    float acc[OUTC];
    #pragma unroll
    for (int c = 0; c < OUTC; c++) acc[c] = 0.f;
    for (int i = s0 + lane; i < s1; i += 32) {
        int s = csr[i];
        float w = __expf(leaky(es[s] + edv) - m);
        den += w;
        const float* hp = h2 + (size_t)s*OUTC;
        #pragma unroll
        for (int c = 0; c < OUTC; c++) acc[c] += w * hp[c];
    }
    if (lane == 0) {
        float w = __expf(eself - m);
        den += w;
        const float* hp = h2 + (size_t)d*OUTC;
        #pragma unroll
        for (int c = 0; c < OUTC; c++) acc[c] += w * hp[c];
    }
    #pragma unroll
    for (int o = 16; o; o >>= 1) {
        den += __shfl_xor_sync(~0u, den, o);
        #pragma unroll
        for (int c = 0; c < OUTC; c++) acc[c] += __shfl_xor_sync(~0u, acc[c], o);
    }
    if (lane == 0) {
        float inv = 1.f / (den + 1e-16f);
        #pragma unroll
        for (int c = 0; c < OUTC; c++) o2[(size_t)d*OUTC + c] = acc[c]*inv + b2[c];
    }
}

// ---------------- final pair scores ----------------
__global__ void pair_scores(const int* __restrict__ pair, const float* __restrict__ emb,
                            float* __restrict__ out, int n)
{
    int i = blockIdx.x*blockDim.x + threadIdx.x;
    if (i >= n) return;
    int a = pair[2*i], b = pair[2*i+1];
    const float2* ea = (const float2*)(emb + (size_t)a*OUTC);
    const float2* eb = (const float2*)(emb + (size_t)b*OUTC);
    float s = 0.f;
    #pragma unroll
    for (int c = 0; c < 5; c++) {
        float2 x = ea[c], y = eb[c];
        s += x.x*y.x + x.y*y.y;
    }
    out[i] = s;
}

// ---------------- host ----------------
extern "C" void kernel_launch(void* const* d_in, const int* in_sizes, int n_in,
                              void* d_out, int out_size)
{
    const float* fsub   = (const float*)d_in[0];
    const float* fcom   = (const float*)d_in[1];
    const float* x      = (const float*)d_in[2];
    const int*   comidx = (const int*)  d_in[3];
    const int*   edge   = (const int*)  d_in[4];
    const int*   pair   = (const int*)  d_in[5];
    const float* Wq = (const float*)d_in[6];  const float* bq = (const float*)d_in[7];
    const float* Wk = (const float*)d_in[8];  const float* bk = (const float*)d_in[9];
    const float* Wv = (const float*)d_in[10]; const float* bv = (const float*)d_in[11];
    const float* Wf = (const float*)d_in[12]; const float* bf = (const float*)d_in[13];
    const float* W1 = (const float*)d_in[14];
    const float* as1 = (const float*)d_in[15]; const float* ad1 = (const float*)d_in[16];
    const float* b1 = (const float*)d_in[17];
    const float* W2 = (const float*)d_in[18];
    const float* as2 = (const float*)d_in[19]; const float* ad2 = (const float*)d_in[20];
    const float* b2 = (const float*)d_in[21];
    float* out = (float*)d_out;

    const int E = in_sizes[4] / 2;
    const int* src = edge;
    const int* dst = edge + E;
    const int npairs = in_sizes[5] / 2;

    float *q, *k, *v, *rowsum, *attv, *fused, *es1, *ed1;
    float *h2, *es2, *ed2, *o2;
    __half *S_h, *h1h;
    int *winner, *deg, *off, *cur, *csr;
    unsigned long long* rowptr;
    cudaGetSymbolAddress((void**)&q, g_q);       cudaGetSymbolAddress((void**)&k, g_k);
    cudaGetSymbolAddress((void**)&v, g_v);       cudaGetSymbolAddress((void**)&S_h, g_S);
    cudaGetSymbolAddress((void**)&rowsum, g_rowsum);
    cudaGetSymbolAddress((void**)&attv, g_attv); cudaGetSymbolAddress((void**)&fused, g_fused);
    cudaGetSymbolAddress((void**)&rowptr, g_rowptr);
    cudaGetSymbolAddress((void**)&winner, g_winner);
    cudaGetSymbolAddress((void**)&h1h, g_h1h);
    cudaGetSymbolAddress((void**)&es1, g_es1);   cudaGetSymbolAddress((void**)&ed1, g_ed1);
    cudaGetSymbolAddress((void**)&h2, g_h2);
    cudaGetSymbolAddress((void**)&es2, g_es2);   cudaGetSymbolAddress((void**)&ed2, g_ed2);
    cudaGetSymbolAddress((void**)&o2, g_o2);
    cudaGetSymbolAddress((void**)&deg, g_deg);   cudaGetSymbolAddress((void**)&off, g_off);
    cudaGetSymbolAddress((void**)&cur, g_cur);   cudaGetSymbolAddress((void**)&csr, g_csr);

    const float inv_sqrt_feat = 0.057735026918962584f;   // 1/sqrt(300)

    // ---- CSR build + rowptr init ----
    cudaMemsetAsync(deg, 0, NNODES*sizeof(int), 0);
    hist_dst<<<(E + 255)/256, 256>>>(dst, deg, E);
    scan_deg<<<1, 1024>>>(deg, off, cur, NNODES);
    scatter_csr<<<(E + 255)/256, 256>>>(src, dst, cur, csr, E);
    fill_rowptr<<<(NNODES + 255)/256, 256>>>(x, rowptr);
    cudaMemsetAsync(winner, 0xFF, NNODES*sizeof(int), 0);
    scatter_winner<<<(NPAIRS_MAP + 255)/256, 256>>>(comidx, winner, NPAIRS_MAP);

    // ---- cross-attention ----
    {
        dim3 grid((FEAT + 127)/128, (NPAIRS_MAP + 127)/128, 3);
        f16_gemm_qkv<<<grid, 256>>>(fsub, fcom, Wq, bq, Wk, bk, Wv, bv, q, k, v);
    }
    // S_exp = exp(q@k^T/sqrt(FEAT)) -> fp16, rowsum accumulated
    cudaMemsetAsync(rowsum, 0, NPAIRS_MAP*sizeof(float), 0);
    {
        dim3 grid(NPAIRS_MAP/128, NPAIRS_MAP/128);
        f16_gemm<128,128,2,4,true,false,true,false,false><<<grid,256>>>(
            q, k, nullptr, nullptr, nullptr, S_h,
            NPAIRS_MAP, NPAIRS_MAP, FEAT, inv_sqrt_feat, 0, nullptr, rowsum);
    }
    inv_rowsum<<<(NPAIRS_MAP + 255)/256, 256>>>(rowsum);
    // attv = fsub + softmax(S)@v  (normalize-on-load from fp16 S, split-K atomics)
    cudaMemcpyAsync(attv, fsub, (size_t)NPAIRS_MAP*FEAT*sizeof(float), cudaMemcpyDeviceToDevice, 0);
    {
        int splits = 8;
        int chunk = ((NPAIRS_MAP/splits + 31)/32)*32;
        dim3 grid((FEAT + 127)/128, NPAIRS_MAP/128, splits);
        f16_gemm<128,128,2,4,false,true,false,true,true><<<grid,256>>>(
            S_h, v, nullptr, nullptr, attv, nullptr,
            NPAIRS_MAP, FEAT, NPAIRS_MAP, 1.f, chunk, rowsum, nullptr);
    }
    {
        dim3 grid((FEAT + 127)/128, (NPAIRS_MAP + 127)/128);
        f16_gemm<128,128,2,4,false,false,false,false,false><<<grid,256>>>(
            attv, Wf, bf, nullptr, fused, nullptr,
            NPAIRS_MAP, FEAT, FEAT, 1.f, 0, nullptr, nullptr);
    }

    // ---- substitute fused rows via row pointers ----
    apply_rowptr<<<(NPAIRS_MAP + 255)/256, 256>>>(comidx, winner, fused, rowptr, NPAIRS_MAP);

    // ---- GAT layer 1 ----
    cudaMemsetAsync(es1, 0, NNODES*HEADS*sizeof(float), 0);
    cudaMemsetAsync(ed1, 0, NNODES*HEADS*sizeof(float), 0);
    {
        dim3 grid(HEADS, (NNODES + 127)/128);
        f16_gemm_w1<<<grid, 256>>>(rowptr, W1, as1, ad1, h1h, es1, ed1);
    }
    gat1_fused<<<(NNODES + 7)/8, 256>>>(off, csr, es1, ed1, h1h, b1, W2, as2, ad2,
                                        h2, es2, ed2);

    // ---- GAT layer 2 ----
    gat2_fused<<<(NNODES + 7)/8, 256>>>(off, csr, es2, ed2, h2, b2, o2);

    // ---- pair scores ----
    pair_scores<<<(npairs + 255)/256, 256>>>(pair, o2, out, npairs);
}